// round 9
// baseline (speedup 1.0000x reference)
#include <cuda_runtime.h>
#include <cuda_bf16.h>
#include <cuda_fp16.h>
#include <math.h>
#include <stdint.h>

// ---------------- problem constants ----------------
#define BBATCH 4
#define LL 4096
#define DD 1024
#define MM (BBATCH * LL)          // 16384 rows
#define NCHUNK 64
#define TCHUNK (LL / NCHUNK)      // 64
#define TOTN (BBATCH * NCHUNK * DD)

// ---------------- fp32 scratch ----------------
__device__ float g_pv[(size_t)MM * DD];
__device__ float g_kc[(size_t)MM * DD];
__device__ float g_ks[(size_t)MM * DD];
__device__ float g_kv[(size_t)MM * DD];
__device__ float g_gh[(size_t)MM * DD];
__device__ float g_bh[(size_t)MM * (DD / 2)];
__device__ float g_vg[MM];
__device__ float g_gcs[MM];
__device__ float g_bw[MM * 2];
__device__ float g_tot[4 * TOTN];
__device__ float g_blend[(size_t)MM * DD];
__device__ float g_pc[(size_t)LL * DD];
__device__ float g_ps[(size_t)LL * DD];

// ---------------- split-precision operand scratch ----------------
__device__ __nv_bfloat16 g_x3 [(size_t)MM * 3 * DD];
__device__ __nv_bfloat16 g_Wk3[(size_t)DD * 3 * DD];
__device__ __half g_x2   [(size_t)MM * 2 * DD];
__device__ __half g_ln2  [(size_t)MM * 2 * DD];
__device__ __half g_Wpvkv2[(size_t)2 * DD * 2 * DD];
__device__ __half g_Wg12 [(size_t)DD * 4 * DD];
__device__ __half g_Wb12 [(size_t)(DD / 2) * 2 * DD];
__device__ __half g_Wo2  [(size_t)DD * 2 * DD];

// ================= PTX helpers (family-safe) =================
__device__ __forceinline__ uint32_t s2u(const void* p) {
    return (uint32_t)__cvta_generic_to_shared(p);
}
__device__ __forceinline__ void ldsm4(uint32_t& r0, uint32_t& r1, uint32_t& r2, uint32_t& r3, uint32_t a) {
    asm volatile("ldmatrix.sync.aligned.m8n8.x4.shared.b16 {%0,%1,%2,%3}, [%4];"
                 : "=r"(r0), "=r"(r1), "=r"(r2), "=r"(r3) : "r"(a));
}
template <bool F16>
__device__ __forceinline__ void mma16816(float* d, const uint32_t* a, uint32_t b0, uint32_t b1);
template <>
__device__ __forceinline__ void mma16816<false>(float* d, const uint32_t* a, uint32_t b0, uint32_t b1) {
    asm volatile("mma.sync.aligned.m16n8k16.row.col.f32.bf16.bf16.f32 "
                 "{%0,%1,%2,%3},{%4,%5,%6,%7},{%8,%9},{%0,%1,%2,%3};"
                 : "+f"(d[0]), "+f"(d[1]), "+f"(d[2]), "+f"(d[3])
                 : "r"(a[0]), "r"(a[1]), "r"(a[2]), "r"(a[3]), "r"(b0), "r"(b1));
}
template <>
__device__ __forceinline__ void mma16816<true>(float* d, const uint32_t* a, uint32_t b0, uint32_t b1) {
    asm volatile("mma.sync.aligned.m16n8k16.row.col.f32.f16.f16.f32 "
                 "{%0,%1,%2,%3},{%4,%5,%6,%7},{%8,%9},{%0,%1,%2,%3};"
                 : "+f"(d[0]), "+f"(d[1]), "+f"(d[2]), "+f"(d[3])
                 : "r"(a[0]), "r"(a[1]), "r"(a[2]), "r"(a[3]), "r"(b0), "r"(b1));
}
__device__ __forceinline__ void cpasync16(uint32_t s, const void* g) {
    asm volatile("cp.async.cg.shared.global [%0], [%1], 16;" :: "r"(s), "l"(g));
}
__device__ __forceinline__ void sts_zero16(uint32_t a) {
    asm volatile("st.shared.v4.b32 [%0], {%1,%1,%1,%1};" :: "r"(a), "r"(0) : "memory");
}
__device__ __forceinline__ void cp_commit() { asm volatile("cp.async.commit_group;"); }
template <int n> __device__ __forceinline__ void cp_wait() {
    asm volatile("cp.async.wait_group %0;" :: "n"(n));
}

// ================= GEMM core =================
// CTA tile 128x256, K-chunk 64 elems, 256 threads (8 warps 2x4), warp tile 64x64.
constexpr int EP_KEY  = 1;
constexpr int EP_GELU = 2;
constexpr int EP_OUT  = 3;
constexpr int EP_PVKV = 4;

#define STG 49152
#define GEMM_SMEM (1024 + 3 * STG)

struct MmaCtx {
    uint32_t aBase[4]; int aXor[4];
    uint32_t bBase[4]; int bXor[4];
    int chi;
};
__device__ __forceinline__ void mma_ctx_init(MmaCtx& cx, int lane, int wm, int wn) {
    const int mat = lane >> 3, mr = lane & 7;
    cx.chi = mat >> 1;
#pragma unroll
    for (int mi = 0; mi < 4; mi++) {
        int row = wm * 64 + mi * 16 + mr + (mat & 1) * 8;
        cx.aBase[mi] = row * 128; cx.aXor[mi] = row & 7;
    }
#pragma unroll
    for (int g = 0; g < 4; g++) {
        int row = wn * 64 + g * 16 + mr + (mat & 1) * 8;
        cx.bBase[g] = 16384 + row * 128; cx.bXor[g] = row & 7;
    }
}
template <bool F16>
__device__ __forceinline__ void mma_tile(const MmaCtx& cx, uint32_t ps, float acc[4][8][4]) {
#pragma unroll
    for (int kk = 0; kk < 4; kk++) {
        const int cb = kk * 2 + cx.chi;
        uint32_t a[4][4];
#pragma unroll
        for (int mi = 0; mi < 4; mi++)
            ldsm4(a[mi][0], a[mi][1], a[mi][2], a[mi][3],
                  ps + cx.aBase[mi] + ((cb ^ cx.aXor[mi]) << 4));
#pragma unroll
        for (int g = 0; g < 4; g++) {
            uint32_t b0, b1, b2, b3;
            ldsm4(b0, b1, b2, b3, ps + cx.bBase[g] + ((cb ^ cx.bXor[g]) << 4));
#pragma unroll
            for (int mi = 0; mi < 4; mi++) {
                mma16816<F16>(acc[mi][2 * g],     a[mi], b0, b2);
                mma16816<F16>(acc[mi][2 * g + 1], a[mi], b1, b3);
            }
        }
    }
}

// ================= generic GEMM =================
template <int MODE, bool F16>
__global__ void __launch_bounds__(256, 1)
gemm_mma(const uint16_t* __restrict__ A, const uint16_t* __restrict__ Bt,
         const float* __restrict__ bias, const float* __restrict__ bias2,
         float* __restrict__ C, float* __restrict__ C2,
         const float* __restrict__ addsrc, int N, int K)
{
    extern __shared__ __align__(16) char smem_[];
    const uint32_t sbase = (s2u(smem_) + 1023u) & ~1023u;
    const int tid = threadIdx.x, lane = tid & 31, warp = tid >> 5;
    const int wm = warp >> 2, wn = warp & 3;
    const int brow = blockIdx.y, bcol = blockIdx.x;

    // loader: A 1024 chunks (4/thread), B 2048 chunks (8/thread); step = 32 rows
    const int lr = tid >> 3, lc = tid & 7;
    const uint16_t* aP = A + ((size_t)(brow * 128 + lr)) * K + lc * 8;
    const uint16_t* bP = Bt + ((size_t)(bcol * 256 + lr)) * K + lc * 8;
    const uint32_t soA = lr * 128 + ((uint32_t)(lc ^ (lr & 7)) << 4);
    const uint32_t soB = 16384 + soA;
    const size_t stepA = (size_t)32 * K;

    MmaCtx cx; mma_ctx_init(cx, lane, wm, wn);

    float acc[4][8][4];
#pragma unroll
    for (int i = 0; i < 4; i++)
#pragma unroll
        for (int j = 0; j < 8; j++)
#pragma unroll
            for (int q = 0; q < 4; q++) acc[i][j][q] = 0.f;

    const int nk = K >> 6;
#define GEN_LOAD(KOFF, DST)                                                     \
    do {                                                                        \
        _Pragma("unroll")                                                       \
        for (int j = 0; j < 4; j++)                                             \
            cpasync16((DST) + soA + j * 4096, aP + (KOFF) + (size_t)j * stepA); \
        _Pragma("unroll")                                                       \
        for (int j = 0; j < 8; j++)                                             \
            cpasync16((DST) + soB + j * 4096, bP + (KOFF) + (size_t)j * stepA); \
        cp_commit();                                                            \
    } while (0)

    GEN_LOAD(0, sbase);
    GEN_LOAD(64, sbase + STG);

    for (int it = 0; it < nk; it++) {
        if (it < nk - 1) cp_wait<1>(); else cp_wait<0>();
        __syncthreads();
        if (it + 2 < nk) {
            const uint32_t dst = sbase + (uint32_t)((it + 2) % 3) * STG;
            GEN_LOAD((size_t)(it + 2) * 64, dst);
        }
        mma_tile<F16>(cx, sbase + (uint32_t)(it % 3) * STG, acc);
    }
#undef GEN_LOAD

    // -------- epilogue --------
    const int r0 = brow * 128 + wm * 64 + (lane >> 2);
    const int sect = (MODE == EP_PVKV) ? (bcol >> 2) : 0;
    const float* bp = (MODE == EP_PVKV && sect) ? bias2 : bias;
    float* Cp = (MODE == EP_PVKV && sect) ? C2 : C;
    const int ostride = (MODE == EP_PVKV) ? DD : N;
    const int c0 = ((MODE == EP_PVKV) ? ((bcol & 3) * 256) : (bcol * 256)) + wn * 64 + (lane & 3) * 2;
#pragma unroll
    for (int mi = 0; mi < 4; mi++) {
#pragma unroll
        for (int nj = 0; nj < 8; nj++) {
            const int col = c0 + nj * 8;
            const float bv0 = bp[col], bv1 = bp[col + 1];
#pragma unroll
            for (int h = 0; h < 2; h++) {
                const int row = r0 + mi * 16 + h * 8;
                const size_t base = (size_t)row * ostride + col;
                float v0 = acc[mi][nj][2 * h]     + bv0;
                float v1 = acc[mi][nj][2 * h + 1] + bv1;
                if (MODE == EP_GELU) {
                    v0 = 0.5f * v0 * (1.f + erff(v0 * 0.70710678118654752f));
                    v1 = 0.5f * v1 * (1.f + erff(v1 * 0.70710678118654752f));
                }
                if (MODE == EP_OUT) { v0 += addsrc[base]; v1 += addsrc[base + 1]; }
                if (MODE == EP_KEY) {
                    float s0, cc0, s1, cc1;
                    sincosf(tanhf(v0) * 3.14159265358979323846f, &s0, &cc0);
                    sincosf(tanhf(v1) * 3.14159265358979323846f, &s1, &cc1);
                    *reinterpret_cast<float2*>(C  + base) = make_float2(cc0, cc1);
                    *reinterpret_cast<float2*>(C2 + base) = make_float2(s0, s1);
                } else {
                    *reinterpret_cast<float2*>(Cp + base) = make_float2(v0, v1);
                }
            }
        }
    }
}

// ================= gate GEMM: A = [x2 | shift1(x2)] virtual concat =================
__global__ void __launch_bounds__(256, 1)
gemm_gate(const uint16_t* __restrict__ X2, const uint16_t* __restrict__ Bt,
          const float* __restrict__ bias, float* __restrict__ C)
{
    extern __shared__ __align__(16) char smem_[];
    const uint32_t sbase = (s2u(smem_) + 1023u) & ~1023u;
    const int tid = threadIdx.x, lane = tid & 31, warp = tid >> 5;
    const int wm = warp >> 2, wn = warp & 3;
    const int brow = blockIdx.y, bcol = blockIdx.x;
    const int K = 4 * DD;         // virtual 4096
    const int KH = 2 * DD;        // 2048
    const int nkh = 32;

    const int lr = tid >> 3, lc = tid & 7;
    const uint16_t* aP = X2 + ((size_t)(brow * 128 + lr)) * KH + lc * 8;
    const uint16_t* bP = Bt + ((size_t)(bcol * 256 + lr)) * K + lc * 8;
    const uint32_t soA = lr * 128 + ((uint32_t)(lc ^ (lr & 7)) << 4);
    const uint32_t soB = 16384 + soA;
    const size_t stepA = (size_t)32 * KH;
    const size_t stepB = (size_t)32 * K;
    bool valid[4];
#pragma unroll
    for (int j = 0; j < 4; j++)
        valid[j] = ((brow * 128 + lr + 32 * j) & (LL - 1)) != 0;

    MmaCtx cx; mma_ctx_init(cx, lane, wm, wn);

    float acc[4][8][4];
#pragma unroll
    for (int i = 0; i < 4; i++)
#pragma unroll
        for (int j = 0; j < 8; j++)
#pragma unroll
            for (int q = 0; q < 4; q++) acc[i][j][q] = 0.f;

    const int nk = K >> 6;   // 64
#define GATE_LOAD(ITP, DST)                                                               \
    do {                                                                                  \
        int itp_ = (ITP);                                                                 \
        if (itp_ < nkh) {                                                                 \
            _Pragma("unroll")                                                             \
            for (int j = 0; j < 4; j++)                                                   \
                cpasync16((DST) + soA + j * 4096, aP + itp_ * 64 + (size_t)j * stepA);    \
        } else {                                                                          \
            _Pragma("unroll")                                                             \
            for (int j = 0; j < 4; j++) {                                                 \
                if (valid[j])                                                             \
                    cpasync16((DST) + soA + j * 4096,                                     \
                              aP - KH + (itp_ - nkh) * 64 + (size_t)j * stepA);           \
                else sts_zero16((DST) + soA + j * 4096);                                  \
            }                                                                             \
        }                                                                                 \
        _Pragma("unroll")                                                                 \
        for (int j = 0; j < 8; j++)                                                       \
            cpasync16((DST) + soB + j * 4096, bP + itp_ * 64 + (size_t)j * stepB);        \
        cp_commit();                                                                      \
    } while (0)

    GATE_LOAD(0, sbase);
    GATE_LOAD(1, sbase + STG);

    for (int it = 0; it < nk; it++) {
        if (it < nk - 1) cp_wait<1>(); else cp_wait<0>();
        __syncthreads();
        if (it + 2 < nk) {
            const uint32_t dst = sbase + (uint32_t)((it + 2) % 3) * STG;
            GATE_LOAD(it + 2, dst);
        }
        mma_tile<true>(cx, sbase + (uint32_t)(it % 3) * STG, acc);
    }
#undef GATE_LOAD

    const int r0 = brow * 128 + wm * 64 + (lane >> 2);
    const int c0 = bcol * 256 + wn * 64 + (lane & 3) * 2;
#pragma unroll
    for (int mi = 0; mi < 4; mi++) {
#pragma unroll
        for (int nj = 0; nj < 8; nj++) {
            const int col = c0 + nj * 8;
            const float bv0 = bias[col], bv1 = bias[col + 1];
#pragma unroll
            for (int h = 0; h < 2; h++) {
                const int row = r0 + mi * 16 + h * 8;
                const size_t base = (size_t)row * DD + col;
                float v0 = acc[mi][nj][2 * h]     + bv0;
                float v1 = acc[mi][nj][2 * h + 1] + bv1;
                v0 = 0.5f * v0 * (1.f + erff(v0 * 0.70710678118654752f));
                v1 = 0.5f * v1 * (1.f + erff(v1 * 0.70710678118654752f));
                *reinterpret_cast<float2*>(C + base) = make_float2(v0, v1);
            }
        }
    }
}

// ---------------- conversion kernels ----------------
// x -> bf16 triples AND fp16 pairs in one pass
__global__ void k_cvtA(const float* __restrict__ in, __nv_bfloat16* __restrict__ out3,
                       __half* __restrict__ out2)
{
    int t = blockIdx.x * 256 + threadIdx.x;
    int m = t >> 8, k4 = t & 255;
    float4 v = reinterpret_cast<const float4*>(in)[(size_t)m * 256 + k4];
    float vv[4] = {v.x, v.y, v.z, v.w};
    __align__(8) __nv_bfloat16 o3[12];
    __align__(16) __half o2[8];
#pragma unroll
    for (int j = 0; j < 4; j++) {
        __nv_bfloat16 h = __float2bfloat16(vv[j]);
        __nv_bfloat16 l = __float2bfloat16(vv[j] - __bfloat162float(h));
        o3[3 * j] = h; o3[3 * j + 1] = l; o3[3 * j + 2] = h;
        __half h2 = __float2half(vv[j]);
        __half l2 = __float2half(vv[j] - __half2float(h2));
        o2[2 * j] = h2; o2[2 * j + 1] = l2;
    }
    uint2* dst = reinterpret_cast<uint2*>(out3 + (size_t)m * 3 * DD + 12 * k4);
    const uint2* src = reinterpret_cast<const uint2*>(o3);
    dst[0] = src[0]; dst[1] = src[1]; dst[2] = src[2];
    reinterpret_cast<uint4*>(out2 + (size_t)m * 2 * DD + 8 * k4)[0] =
        *reinterpret_cast<const uint4*>(o2);
}

__global__ void k_cvtB3(const float* __restrict__ W, __nv_bfloat16* __restrict__ out, int K, int N)
{
    __shared__ float ts[32][33];
    const int k0 = blockIdx.y * 32, n0 = blockIdx.x * 32;
    const int tx = threadIdx.x, ty = threadIdx.y;
#pragma unroll
    for (int i = 0; i < 4; i++)
        ts[ty + i * 8][tx] = W[(size_t)(k0 + ty + i * 8) * N + n0 + tx];
    __syncthreads();
#pragma unroll
    for (int i = 0; i < 4; i++) {
        int n = ty + i * 8;
        float w = ts[tx][n];
        __nv_bfloat16 h = __float2bfloat16(w);
        __nv_bfloat16 l = __float2bfloat16(w - __bfloat162float(h));
        size_t ob = (size_t)(n0 + n) * 3 * K + 3 * (size_t)(k0 + tx);
        out[ob] = h; out[ob + 1] = h; out[ob + 2] = l;
    }
}

__global__ void k_cvtB2(const float* __restrict__ W, __half* __restrict__ out, int K, int N)
{
    __shared__ float ts[32][33];
    const int k0 = blockIdx.y * 32, n0 = blockIdx.x * 32;
    const int tx = threadIdx.x, ty = threadIdx.y;
#pragma unroll
    for (int i = 0; i < 4; i++)
        ts[ty + i * 8][tx] = W[(size_t)(k0 + ty + i * 8) * N + n0 + tx];
    __syncthreads();
#pragma unroll
    for (int i = 0; i < 4; i++) {
        int n = ty + i * 8;
        __half h = __float2half(ts[tx][n]);
        size_t ob = (size_t)(n0 + n) * 2 * K + 2 * (size_t)(k0 + tx);
        out[ob] = h; out[ob + 1] = h;
    }
}

__global__ void k_sincos(const float* __restrict__ pp)
{
    size_t t = (size_t)blockIdx.x * 256 + threadIdx.x;
    float sn, cs;
    sincosf(pp[t], &sn, &cs);
    g_pc[t] = cs; g_ps[t] = sn;
}

// ---------------- value_gates ----------------
__global__ void k_vg(const float* __restrict__ Wg2, const float* __restrict__ bg2)
{
    const int warp = threadIdx.x >> 5, lane = threadIdx.x & 31;
    const int row = blockIdx.x * 8 + warp;
    const float4* g = reinterpret_cast<const float4*>(g_gh + (size_t)row * DD);
    const float4* w = reinterpret_cast<const float4*>(Wg2);
    float s = 0.f;
#pragma unroll
    for (int i = 0; i < 8; i++) {
        float4 a = g[lane + i * 32], b = w[lane + i * 32];
        s += a.x * b.x + a.y * b.y + a.z * b.z + a.w * b.w;
    }
#pragma unroll
    for (int o = 16; o > 0; o >>= 1) s += __shfl_xor_sync(0xFFFFFFFFu, s, o);
    if (lane == 0) g_vg[row] = 1.f / (1.f + expf(-(s + bg2[0])));
}

// ---------------- blend weights ----------------
__global__ void k_bw(const float* __restrict__ Wb2, const float* __restrict__ bb2)
{
    const int warp = threadIdx.x >> 5, lane = threadIdx.x & 31;
    const int row = blockIdx.x * 8 + warp;
    const float4* hv = reinterpret_cast<const float4*>(g_bh + (size_t)row * (DD / 2));
    const float4* wv = reinterpret_cast<const float4*>(Wb2);
    float s0 = 0.f, s1 = 0.f;
#pragma unroll
    for (int i = 0; i < 4; i++) {
        int idx = lane + i * 32;
        float4 a = hv[idx];
        float4 w0 = wv[2 * idx], w1 = wv[2 * idx + 1];
        s0 += a.x * w0.x + a.y * w0.z + a.z * w1.x + a.w * w1.z;
        s1 += a.x * w0.y + a.y * w0.w + a.z * w1.y + a.w * w1.w;
    }
#pragma unroll
    for (int o = 16; o > 0; o >>= 1) {
        s0 += __shfl_xor_sync(0xFFFFFFFFu, s0, o);
        s1 += __shfl_xor_sync(0xFFFFFFFFu, s1, o);
    }
    if (lane == 0) {
        float a0 = s0 + bb2[0], a1 = s1 + bb2[1];
        float m = fmaxf(a0, a1);
        float e0 = expf(a0 - m), e1 = expf(a1 - m);
        float inv = 1.f / (e0 + e1);
        g_bw[2 * row]     = e0 * inv;
        g_bw[2 * row + 1] = e1 * inv;
    }
}

// ---------------- per-batch gate scan ----------------
__global__ void k_gatescan()
{
    int b = blockIdx.x;
    __shared__ float sh[1024];
    float carry = 0.f;
    for (int t0 = 0; t0 < LL; t0 += 1024) {
        int l = t0 + threadIdx.x;
        sh[threadIdx.x] = g_vg[b * LL + l];
        __syncthreads();
        for (int off = 1; off < 1024; off <<= 1) {
            float tv = (threadIdx.x >= off) ? sh[threadIdx.x - off] : 0.f;
            __syncthreads();
            sh[threadIdx.x] += tv;
            __syncthreads();
        }
        float inc = sh[threadIdx.x] + carry;
        float tot = sh[1023];
        g_gcs[b * LL + l] = sqrtf(fmaxf(inc, 1.f));
        carry += tot;
        __syncthreads();
    }
}

// ---------------- scan pass T ----------------
__global__ void k_scanT()
{
    int d = blockIdx.x * 256 + threadIdx.x;
    int c = blockIdx.y, b = blockIdx.z;
    float spc = 0.f, sps = 0.f, skc = 0.f, sks = 0.f;
    int l0 = c * TCHUNK;
    for (int t = 0; t < TCHUNK; t++) {
        int l = l0 + t;
        int rowi = b * LL + l;
        size_t idx = (size_t)rowi * DD + d;
        size_t pidx = (size_t)l * DD + d;
        float pvv = g_pv[idx];
        spc = fmaf(g_pc[pidx], pvv, spc);
        sps = fmaf(g_ps[pidx], pvv, sps);
        float kvg = g_kv[idx] * g_vg[rowi];
        float kcp = (l == 0) ? 0.f : g_kc[idx - DD];
        float ksp = (l == 0) ? 0.f : g_ks[idx - DD];
        skc = fmaf(kcp, kvg, skc);
        sks = fmaf(ksp, kvg, sks);
    }
    size_t tix = (size_t)(b * NCHUNK + c) * DD + d;
    g_tot[tix]            = spc;
    g_tot[TOTN + tix]     = sps;
    g_tot[2 * TOTN + tix] = skc;
    g_tot[3 * TOTN + tix] = sks;
}

// ---------------- scan pass C ----------------
__global__ void k_scanC()
{
    int d = blockIdx.x * 256 + threadIdx.x;
    int c = blockIdx.y, b = blockIdx.z;
    float opc = 0.f, ops = 0.f, okc = 0.f, oks = 0.f;
    for (int cc = 0; cc < c; cc++) {
        size_t tix = (size_t)(b * NCHUNK + cc) * DD + d;
        opc += g_tot[tix];
        ops += g_tot[TOTN + tix];
        okc += g_tot[2 * TOTN + tix];
        oks += g_tot[3 * TOTN + tix];
    }
    const float invSqrtD = 0.03125f;
    int l0 = c * TCHUNK;
    float spc = 0.f, sps = 0.f, skc = 0.f, sks = 0.f;
    for (int t = 0; t < TCHUNK; t++) {
        int l = l0 + t;
        int rowi = b * LL + l;
        size_t idx = (size_t)rowi * DD + d;
        size_t pidx = (size_t)l * DD + d;
        float pvv = g_pv[idx];
        float cs = g_pc[pidx], sn = g_ps[pidx];
        spc = fmaf(cs, pvv, spc);
        sps = fmaf(sn, pvv, sps);
        float kvg = g_kv[idx] * g_vg[rowi];
        float kcc = g_kc[idx], kss = g_ks[idx];
        float kcp = (l == 0) ? 0.f : g_kc[idx - DD];
        float ksp = (l == 0) ? 0.f : g_ks[idx - DD];
        skc = fmaf(kcp, kvg, skc);
        sks = fmaf(ksp, kvg, sks);
        float pos_ret = (cs * (spc + opc) + sn * (sps + ops)) * invSqrtD;
        float kv_ret  = (kcc * (skc + okc) + kss * (sks + oks)) / g_gcs[rowi] * invSqrtD;
        g_blend[idx] = g_bw[2 * rowi] * pos_ret + g_bw[2 * rowi + 1] * kv_ret;
    }
}

// ---------------- LayerNorm fused with fp16 pair-split output ----------------
__global__ void k_ln(const float* __restrict__ lng, const float* __restrict__ lnb,
                     __half* __restrict__ out2)
{
    int row = blockIdx.x, tid = threadIdx.x;
    float v[4], s = 0.f, sq = 0.f;
#pragma unroll
    for (int i = 0; i < 4; i++) {
        v[i] = g_blend[(size_t)row * DD + tid + i * 256];
        s += v[i]; sq += v[i] * v[i];
    }
    __shared__ float shs[256], shq[256];
    shs[tid] = s; shq[tid] = sq; __syncthreads();
    for (int o = 128; o > 0; o >>= 1) {
        if (tid < o) { shs[tid] += shs[tid + o]; shq[tid] += shq[tid + o]; }
        __syncthreads();
    }
    __shared__ float smu, srstd;
    if (tid == 0) {
        float mu  = shs[0] * (1.f / DD);
        float var = shq[0] * (1.f / DD) - mu * mu;
        smu = mu;
        srstd = rsqrtf(var + 1e-5f);
    }
    __syncthreads();
#pragma unroll
    for (int i = 0; i < 4; i++) {
        int dd = tid + i * 256;
        float t = (v[i] - smu) * srstd * lng[dd] + lnb[dd];
        __half h = __float2half(t);
        __half l = __float2half(t - __half2float(h));
        __half2 hl = __halves2half2(h, l);
        *reinterpret_cast<__half2*>(out2 + (size_t)row * 2 * DD + 2 * dd) = hl;
    }
}

// ---------------- launch ----------------
extern "C" void kernel_launch(void* const* d_in, const int* in_sizes, int n_in,
                              void* d_out, int out_size)
{
    const float* x   = (const float*)d_in[0];
    const float* pp  = (const float*)d_in[1];
    const float* Wpv = (const float*)d_in[2];
    const float* bpv = (const float*)d_in[3];
    const float* Wk  = (const float*)d_in[4];
    const float* bk  = (const float*)d_in[5];
    const float* Wkv = (const float*)d_in[6];
    const float* bkv = (const float*)d_in[7];
    const float* Wg1 = (const float*)d_in[8];
    const float* bg1 = (const float*)d_in[9];
    const float* Wg2 = (const float*)d_in[10];
    const float* bg2 = (const float*)d_in[11];
    const float* Wb1 = (const float*)d_in[12];
    const float* bb1 = (const float*)d_in[13];
    const float* Wb2 = (const float*)d_in[14];
    const float* bb2 = (const float*)d_in[15];
    const float* lng = (const float*)d_in[16];
    const float* lnb = (const float*)d_in[17];
    const float* Wo  = (const float*)d_in[18];
    const float* bo  = (const float*)d_in[19];
    float* out = (float*)d_out;

    float *pv, *kc, *ks, *kv, *gh, *bh;
    cudaGetSymbolAddress((void**)&pv, g_pv);
    cudaGetSymbolAddress((void**)&kc, g_kc);
    cudaGetSymbolAddress((void**)&ks, g_ks);
    cudaGetSymbolAddress((void**)&kv, g_kv);
    cudaGetSymbolAddress((void**)&gh, g_gh);
    cudaGetSymbolAddress((void**)&bh, g_bh);

    __nv_bfloat16 *x3, *Wk3;
    __half *x2, *ln2, *Wpvkv2, *Wg12, *Wb12, *Wo2;
    cudaGetSymbolAddress((void**)&x3,     g_x3);
    cudaGetSymbolAddress((void**)&Wk3,    g_Wk3);
    cudaGetSymbolAddress((void**)&x2,     g_x2);
    cudaGetSymbolAddress((void**)&ln2,    g_ln2);
    cudaGetSymbolAddress((void**)&Wpvkv2, g_Wpvkv2);
    cudaGetSymbolAddress((void**)&Wg12,   g_Wg12);
    cudaGetSymbolAddress((void**)&Wb12,   g_Wb12);
    cudaGetSymbolAddress((void**)&Wo2,    g_Wo2);

    cudaFuncSetAttribute((const void*)gemm_mma<EP_KEY,  false>, cudaFuncAttributeMaxDynamicSharedMemorySize, GEMM_SMEM);
    cudaFuncSetAttribute((const void*)gemm_mma<EP_PVKV, true >, cudaFuncAttributeMaxDynamicSharedMemorySize, GEMM_SMEM);
    cudaFuncSetAttribute((const void*)gemm_mma<EP_GELU, true >, cudaFuncAttributeMaxDynamicSharedMemorySize, GEMM_SMEM);
    cudaFuncSetAttribute((const void*)gemm_mma<EP_OUT,  true >, cudaFuncAttributeMaxDynamicSharedMemorySize, GEMM_SMEM);
    cudaFuncSetAttribute((const void*)gemm_gate, cudaFuncAttributeMaxDynamicSharedMemorySize, GEMM_SMEM);

    // 0-1: activation + key weight conversions
    k_cvtA<<<(MM * DD / 4) / 256, 256>>>(x, x3, x2);
    k_cvtB3<<<dim3(DD / 32, DD / 32), dim3(32, 8)>>>(Wk, Wk3, DD, DD);
    // 2: key GEMM (bf16 3-product)
    gemm_mma<EP_KEY, false><<<dim3(4, MM / 128), 256, GEMM_SMEM>>>(
        (const uint16_t*)x3, (const uint16_t*)Wk3, bk, nullptr, kc, ks, nullptr, DD, 3 * DD);
    // 3-4: pv+kv weights (fp16 pairs, packed)
    k_cvtB2<<<dim3(DD / 32, DD / 32), dim3(32, 8)>>>(Wpv, Wpvkv2, DD, DD);
    k_cvtB2<<<dim3(DD / 32, DD / 32), dim3(32, 8)>>>(Wkv, Wpvkv2 + (size_t)DD * 2 * DD, DD, DD);
    // 5: merged pv+kv GEMM (fp16 2-product, N=2048)
    gemm_mma<EP_PVKV, true><<<dim3(8, MM / 128), 256, GEMM_SMEM>>>(
        (const uint16_t*)x2, (const uint16_t*)Wpvkv2, bpv, bkv, pv, kv, nullptr, 2 * DD, 2 * DD);
    // 6-7: gate path
    k_cvtB2<<<dim3(DD / 32, 2 * DD / 32), dim3(32, 8)>>>(Wg1, Wg12, 2 * DD, DD);
    gemm_gate<<<dim3(4, MM / 128), 256, GEMM_SMEM>>>((const uint16_t*)x2, (const uint16_t*)Wg12, bg1, gh);
    // 8-9: blend hidden
    k_cvtB2<<<dim3((DD / 2) / 32, DD / 32), dim3(32, 8)>>>(Wb1, Wb12, DD, DD / 2);
    gemm_mma<EP_GELU, true><<<dim3(2, MM / 128), 256, GEMM_SMEM>>>(
        (const uint16_t*)x2, (const uint16_t*)Wb12, bb1, nullptr, bh, nullptr, nullptr, DD / 2, 2 * DD);
    // 10: pos phase cos/sin
    k_sincos<<<(LL * DD) / 256, 256>>>(pp);
    // 11-13: gates / blend softmax / gate cumsum
    k_vg<<<MM / 8, 256>>>(Wg2, bg2);
    k_bw<<<MM / 8, 256>>>(Wb2, bb2);
    k_gatescan<<<BBATCH, 1024>>>();
    // 14-15: scans
    dim3 gscan(DD / 256, NCHUNK, BBATCH);
    k_scanT<<<gscan, 256>>>();
    k_scanC<<<gscan, 256>>>();
    // 16: LayerNorm (fused fp16 pair-split)
    k_ln<<<MM, 256>>>(lng, lnb, ln2);
    // 17-18: output path (+residual)
    k_cvtB2<<<dim3(DD / 32, DD / 32), dim3(32, 8)>>>(Wo, Wo2, DD, DD);
    gemm_mma<EP_OUT, true><<<dim3(4, MM / 128), 256, GEMM_SMEM>>>(
        (const uint16_t*)ln2, (const uint16_t*)Wo2, bo, nullptr, out, nullptr, x, DD, 2 * DD);
}

// round 10
// speedup vs baseline: 1.0383x; 1.0383x over previous
#include <cuda_runtime.h>
#include <cuda_bf16.h>
#include <cuda_fp16.h>
#include <math.h>
#include <stdint.h>

// ---------------- problem constants ----------------
#define BBATCH 4
#define LL 4096
#define DD 1024
#define MM (BBATCH * LL)          // 16384 rows
#define NCHUNK 64
#define TCHUNK (LL / NCHUNK)      // 64
#define TOTN (BBATCH * NCHUNK * DD)

// ---------------- fp32 scratch ----------------
__device__ float g_pv[(size_t)MM * DD];
__device__ float g_kc[(size_t)MM * DD];
__device__ float g_ks[(size_t)MM * DD];
__device__ float g_kv[(size_t)MM * DD];
__device__ float g_gh[(size_t)MM * DD];
__device__ float g_bh[(size_t)MM * (DD / 2)];
__device__ float g_vg[MM];
__device__ float g_gcs[MM];
__device__ float g_bw[MM * 2];
__device__ float g_tot[4 * TOTN];
__device__ float g_blend[(size_t)MM * DD];
__device__ float g_pc[(size_t)LL * DD];
__device__ float g_ps[(size_t)LL * DD];

// ---------------- split-precision operand scratch ----------------
__device__ __nv_bfloat16 g_x3 [(size_t)MM * 3 * DD];
__device__ __nv_bfloat16 g_Wk3[(size_t)DD * 3 * DD];
__device__ __half g_x2   [(size_t)MM * 2 * DD];
__device__ __half g_ln2  [(size_t)MM * 2 * DD];
__device__ __half g_Wpvkv2[(size_t)2 * DD * 2 * DD];
__device__ __half g_Wg12 [(size_t)DD * 4 * DD];
__device__ __half g_Wb12 [(size_t)(DD / 2) * 2 * DD];
__device__ __half g_Wo2  [(size_t)DD * 2 * DD];

// ================= PTX helpers (family-safe) =================
__device__ __forceinline__ uint32_t s2u(const void* p) {
    return (uint32_t)__cvta_generic_to_shared(p);
}
__device__ __forceinline__ void ldsm4(uint32_t& r0, uint32_t& r1, uint32_t& r2, uint32_t& r3, uint32_t a) {
    asm volatile("ldmatrix.sync.aligned.m8n8.x4.shared.b16 {%0,%1,%2,%3}, [%4];"
                 : "=r"(r0), "=r"(r1), "=r"(r2), "=r"(r3) : "r"(a));
}
template <bool F16>
__device__ __forceinline__ void mma16816(float* d, const uint32_t* a, uint32_t b0, uint32_t b1);
template <>
__device__ __forceinline__ void mma16816<false>(float* d, const uint32_t* a, uint32_t b0, uint32_t b1) {
    asm volatile("mma.sync.aligned.m16n8k16.row.col.f32.bf16.bf16.f32 "
                 "{%0,%1,%2,%3},{%4,%5,%6,%7},{%8,%9},{%0,%1,%2,%3};"
                 : "+f"(d[0]), "+f"(d[1]), "+f"(d[2]), "+f"(d[3])
                 : "r"(a[0]), "r"(a[1]), "r"(a[2]), "r"(a[3]), "r"(b0), "r"(b1));
}
template <>
__device__ __forceinline__ void mma16816<true>(float* d, const uint32_t* a, uint32_t b0, uint32_t b1) {
    asm volatile("mma.sync.aligned.m16n8k16.row.col.f32.f16.f16.f32 "
                 "{%0,%1,%2,%3},{%4,%5,%6,%7},{%8,%9},{%0,%1,%2,%3};"
                 : "+f"(d[0]), "+f"(d[1]), "+f"(d[2]), "+f"(d[3])
                 : "r"(a[0]), "r"(a[1]), "r"(a[2]), "r"(a[3]), "r"(b0), "r"(b1));
}
__device__ __forceinline__ void cpasync16(uint32_t s, const void* g) {
    asm volatile("cp.async.cg.shared.global [%0], [%1], 16;" :: "r"(s), "l"(g));
}
__device__ __forceinline__ void sts_zero16(uint32_t a) {
    asm volatile("st.shared.v4.b32 [%0], {%1,%1,%1,%1};" :: "r"(a), "r"(0) : "memory");
}
__device__ __forceinline__ void cp_commit() { asm volatile("cp.async.commit_group;"); }
template <int n> __device__ __forceinline__ void cp_wait() {
    asm volatile("cp.async.wait_group %0;" :: "n"(n));
}

// ================= GEMM core (R8 config: 512 thr, 16 warps 4x4, warp tile 32x64) =================
constexpr int EP_KEY  = 1;
constexpr int EP_GELU = 2;
constexpr int EP_OUT  = 3;
constexpr int EP_PVKV = 4;

#define STG 49152
#define GEMM_SMEM (1024 + 3 * STG)

struct MmaCtx {
    uint32_t aBase[2]; int aXor[2];
    uint32_t bBase[4]; int bXor[4];
    int chi;
};
__device__ __forceinline__ void mma_ctx_init(MmaCtx& cx, int lane, int wm, int wn) {
    const int mat = lane >> 3, mr = lane & 7;
    cx.chi = mat >> 1;
#pragma unroll
    for (int mi = 0; mi < 2; mi++) {
        int row = wm * 32 + mi * 16 + mr + (mat & 1) * 8;
        cx.aBase[mi] = row * 128; cx.aXor[mi] = row & 7;
    }
#pragma unroll
    for (int g = 0; g < 4; g++) {
        int row = wn * 64 + g * 16 + mr + (mat & 1) * 8;
        cx.bBase[g] = 16384 + row * 128; cx.bXor[g] = row & 7;
    }
}
template <bool F16>
__device__ __forceinline__ void mma_tile(const MmaCtx& cx, uint32_t ps, float acc[2][8][4]) {
#pragma unroll
    for (int kk = 0; kk < 4; kk++) {
        const int cb = kk * 2 + cx.chi;
        uint32_t a0[4], a1[4];
        ldsm4(a0[0], a0[1], a0[2], a0[3], ps + cx.aBase[0] + ((cb ^ cx.aXor[0]) << 4));
        ldsm4(a1[0], a1[1], a1[2], a1[3], ps + cx.aBase[1] + ((cb ^ cx.aXor[1]) << 4));
#pragma unroll
        for (int g = 0; g < 4; g++) {
            uint32_t b0, b1, b2, b3;
            ldsm4(b0, b1, b2, b3, ps + cx.bBase[g] + ((cb ^ cx.bXor[g]) << 4));
            mma16816<F16>(acc[0][2 * g],     a0, b0, b2);
            mma16816<F16>(acc[0][2 * g + 1], a0, b1, b3);
            mma16816<F16>(acc[1][2 * g],     a1, b0, b2);
            mma16816<F16>(acc[1][2 * g + 1], a1, b1, b3);
        }
    }
}

// ================= generic GEMM =================
template <int MODE, bool F16>
__global__ void __launch_bounds__(512, 1)
gemm_mma(const uint16_t* __restrict__ A, const uint16_t* __restrict__ Bt,
         const float* __restrict__ bias, const float* __restrict__ bias2,
         float* __restrict__ C, float* __restrict__ C2,
         const float* __restrict__ addsrc, int N, int K)
{
    extern __shared__ __align__(16) char smem_[];
    const uint32_t sbase = (s2u(smem_) + 1023u) & ~1023u;
    const int tid = threadIdx.x, lane = tid & 31, warp = tid >> 5;
    const int wm = warp >> 2, wn = warp & 3;
    const int brow = blockIdx.y, bcol = blockIdx.x;

    const uint16_t* Ag = A  + (size_t)brow * 128 * K;
    const uint16_t* Bg = Bt + (size_t)bcol * 256 * K;

    uint32_t so[6];
    const uint16_t* gp[6];
#pragma unroll
    for (int j = 0; j < 6; j++) {
        int id = tid + j * 512;
        int q; const uint16_t* base; uint32_t off;
        if (id < 1024) { q = id;        base = Ag; off = 0; }
        else           { q = id - 1024; base = Bg; off = 16384; }
        int r = q >> 3, c = q & 7;
        gp[j] = base + (size_t)r * K + c * 8;
        so[j] = off + r * 128 + ((uint32_t)(c ^ (r & 7)) << 4);
    }
    MmaCtx cx; mma_ctx_init(cx, lane, wm, wn);

    float acc[2][8][4];
#pragma unroll
    for (int i = 0; i < 2; i++)
#pragma unroll
        for (int j = 0; j < 8; j++)
#pragma unroll
            for (int q = 0; q < 4; q++) acc[i][j][q] = 0.f;

    const int nk = K >> 6;
#pragma unroll
    for (int j = 0; j < 6; j++) cpasync16(sbase + so[j], gp[j]);
    cp_commit();
#pragma unroll
    for (int j = 0; j < 6; j++) { gp[j] += 64; cpasync16(sbase + STG + so[j], gp[j]); }
    cp_commit();

    for (int it = 0; it < nk; it++) {
        if (it < nk - 1) cp_wait<1>(); else cp_wait<0>();
        __syncthreads();
        if (it + 2 < nk) {
            const uint32_t dst = sbase + (uint32_t)((it + 2) % 3) * STG;
#pragma unroll
            for (int j = 0; j < 6; j++) { gp[j] += 64; cpasync16(dst + so[j], gp[j]); }
            cp_commit();
        }
        mma_tile<F16>(cx, sbase + (uint32_t)(it % 3) * STG, acc);
    }

    // -------- epilogue --------
    const int r0 = brow * 128 + wm * 32 + (lane >> 2);
    const int sect = (MODE == EP_PVKV) ? (bcol >> 2) : 0;
    const float* bp = (MODE == EP_PVKV && sect) ? bias2 : bias;
    float* Cp = (MODE == EP_PVKV && sect) ? C2 : C;
    const int ostride = (MODE == EP_PVKV) ? DD : N;
    const int c0 = ((MODE == EP_PVKV) ? ((bcol & 3) * 256) : (bcol * 256)) + wn * 64 + (lane & 3) * 2;
#pragma unroll
    for (int mi = 0; mi < 2; mi++) {
#pragma unroll
        for (int nj = 0; nj < 8; nj++) {
            const int col = c0 + nj * 8;
            const float bv0 = bp[col], bv1 = bp[col + 1];
#pragma unroll
            for (int h = 0; h < 2; h++) {
                const int row = r0 + mi * 16 + h * 8;
                const size_t base = (size_t)row * ostride + col;
                float v0 = acc[mi][nj][2 * h]     + bv0;
                float v1 = acc[mi][nj][2 * h + 1] + bv1;
                if (MODE == EP_GELU) {
                    v0 = 0.5f * v0 * (1.f + erff(v0 * 0.70710678118654752f));
                    v1 = 0.5f * v1 * (1.f + erff(v1 * 0.70710678118654752f));
                }
                if (MODE == EP_OUT) { v0 += addsrc[base]; v1 += addsrc[base + 1]; }
                if (MODE == EP_KEY) {
                    float s0, cc0, s1, cc1;
                    sincosf(tanhf(v0) * 3.14159265358979323846f, &s0, &cc0);
                    sincosf(tanhf(v1) * 3.14159265358979323846f, &s1, &cc1);
                    *reinterpret_cast<float2*>(C  + base) = make_float2(cc0, cc1);
                    *reinterpret_cast<float2*>(C2 + base) = make_float2(s0, s1);
                } else {
                    *reinterpret_cast<float2*>(Cp + base) = make_float2(v0, v1);
                }
            }
        }
    }
}

// ================= gate GEMM: A = [x2 | shift1(x2)] virtual concat (fp16 pairs) =================
__global__ void __launch_bounds__(512, 1)
gemm_gate(const uint16_t* __restrict__ X2, const uint16_t* __restrict__ Bt,
          const float* __restrict__ bias, float* __restrict__ C)
{
    extern __shared__ __align__(16) char smem_[];
    const uint32_t sbase = (s2u(smem_) + 1023u) & ~1023u;
    const int tid = threadIdx.x, lane = tid & 31, warp = tid >> 5;
    const int wm = warp >> 2, wn = warp & 3;
    const int brow = blockIdx.y, bcol = blockIdx.x;
    const int K = 4 * DD;
    const int KH = 2 * DD;
    const int nkh = 32;

    uint32_t soA[2];
    const uint16_t *aCur[2], *aPrev[2];
    bool validA[2];
#pragma unroll
    for (int j = 0; j < 2; j++) {
        int q = tid + j * 512;
        int r = q >> 3, c = q & 7;
        int R = brow * 128 + r;
        aCur[j]  = X2 + (size_t)R * KH + c * 8;
        aPrev[j] = X2 + ((size_t)R - 1) * KH + c * 8;
        validA[j] = (R & (LL - 1)) != 0;
        soA[j] = r * 128 + ((uint32_t)(c ^ (r & 7)) << 4);
    }
    uint32_t soB[4];
    const uint16_t* bgp[4];
#pragma unroll
    for (int j = 0; j < 4; j++) {
        int q = tid + j * 512;
        int r = q >> 3, c = q & 7;
        bgp[j] = Bt + (size_t)(bcol * 256 + r) * K + c * 8;
        soB[j] = 16384 + r * 128 + ((uint32_t)(c ^ (r & 7)) << 4);
    }
    MmaCtx cx; mma_ctx_init(cx, lane, wm, wn);

    float acc[2][8][4];
#pragma unroll
    for (int i = 0; i < 2; i++)
#pragma unroll
        for (int j = 0; j < 8; j++)
#pragma unroll
            for (int q = 0; q < 4; q++) acc[i][j][q] = 0.f;

    const int nk = K >> 6;   // 64
#define GATE_LOAD(ITP, DST)                                                           \
    do {                                                                              \
        int itp_ = (ITP);                                                             \
        if (itp_ < nkh) {                                                             \
            cpasync16((DST) + soA[0], aCur[0] + itp_ * 64);                           \
            cpasync16((DST) + soA[1], aCur[1] + itp_ * 64);                           \
        } else {                                                                      \
            if (validA[0]) cpasync16((DST) + soA[0], aPrev[0] + (itp_ - nkh) * 64);   \
            else sts_zero16((DST) + soA[0]);                                          \
            if (validA[1]) cpasync16((DST) + soA[1], aPrev[1] + (itp_ - nkh) * 64);   \
            else sts_zero16((DST) + soA[1]);                                          \
        }                                                                             \
        cpasync16((DST) + soB[0], bgp[0] + itp_ * 64);                                \
        cpasync16((DST) + soB[1], bgp[1] + itp_ * 64);                                \
        cpasync16((DST) + soB[2], bgp[2] + itp_ * 64);                                \
        cpasync16((DST) + soB[3], bgp[3] + itp_ * 64);                                \
        cp_commit();                                                                  \
    } while (0)

    GATE_LOAD(0, sbase);
    GATE_LOAD(1, sbase + STG);

    for (int it = 0; it < nk; it++) {
        if (it < nk - 1) cp_wait<1>(); else cp_wait<0>();
        __syncthreads();
        if (it + 2 < nk) {
            const uint32_t dst = sbase + (uint32_t)((it + 2) % 3) * STG;
            GATE_LOAD(it + 2, dst);
        }
        mma_tile<true>(cx, sbase + (uint32_t)(it % 3) * STG, acc);
    }
#undef GATE_LOAD

    const int r0 = brow * 128 + wm * 32 + (lane >> 2);
    const int c0 = bcol * 256 + wn * 64 + (lane & 3) * 2;
#pragma unroll
    for (int mi = 0; mi < 2; mi++) {
#pragma unroll
        for (int nj = 0; nj < 8; nj++) {
            const int col = c0 + nj * 8;
            const float bv0 = bias[col], bv1 = bias[col + 1];
#pragma unroll
            for (int h = 0; h < 2; h++) {
                const int row = r0 + mi * 16 + h * 8;
                const size_t base = (size_t)row * DD + col;
                float v0 = acc[mi][nj][2 * h]     + bv0;
                float v1 = acc[mi][nj][2 * h + 1] + bv1;
                v0 = 0.5f * v0 * (1.f + erff(v0 * 0.70710678118654752f));
                v1 = 0.5f * v1 * (1.f + erff(v1 * 0.70710678118654752f));
                *reinterpret_cast<float2*>(C + base) = make_float2(v0, v1);
            }
        }
    }
}

// ---------------- conversion kernels ----------------
__global__ void k_cvtA(const float* __restrict__ in, __nv_bfloat16* __restrict__ out3,
                       __half* __restrict__ out2)
{
    int t = blockIdx.x * 256 + threadIdx.x;
    int m = t >> 8, k4 = t & 255;
    float4 v = reinterpret_cast<const float4*>(in)[(size_t)m * 256 + k4];
    float vv[4] = {v.x, v.y, v.z, v.w};
    __align__(8) __nv_bfloat16 o3[12];
    __align__(16) __half o2[8];
#pragma unroll
    for (int j = 0; j < 4; j++) {
        __nv_bfloat16 h = __float2bfloat16(vv[j]);
        __nv_bfloat16 l = __float2bfloat16(vv[j] - __bfloat162float(h));
        o3[3 * j] = h; o3[3 * j + 1] = l; o3[3 * j + 2] = h;
        __half h2 = __float2half(vv[j]);
        __half l2 = __float2half(vv[j] - __half2float(h2));
        o2[2 * j] = h2; o2[2 * j + 1] = l2;
    }
    uint2* dst = reinterpret_cast<uint2*>(out3 + (size_t)m * 3 * DD + 12 * k4);
    const uint2* src = reinterpret_cast<const uint2*>(o3);
    dst[0] = src[0]; dst[1] = src[1]; dst[2] = src[2];
    reinterpret_cast<uint4*>(out2 + (size_t)m * 2 * DD + 8 * k4)[0] =
        *reinterpret_cast<const uint4*>(o2);
}

__global__ void k_cvtB3(const float* __restrict__ W, __nv_bfloat16* __restrict__ out, int K, int N)
{
    __shared__ float ts[32][33];
    const int k0 = blockIdx.y * 32, n0 = blockIdx.x * 32;
    const int tx = threadIdx.x, ty = threadIdx.y;
#pragma unroll
    for (int i = 0; i < 4; i++)
        ts[ty + i * 8][tx] = W[(size_t)(k0 + ty + i * 8) * N + n0 + tx];
    __syncthreads();
#pragma unroll
    for (int i = 0; i < 4; i++) {
        int n = ty + i * 8;
        float w = ts[tx][n];
        __nv_bfloat16 h = __float2bfloat16(w);
        __nv_bfloat16 l = __float2bfloat16(w - __bfloat162float(h));
        size_t ob = (size_t)(n0 + n) * 3 * K + 3 * (size_t)(k0 + tx);
        out[ob] = h; out[ob + 1] = h; out[ob + 2] = l;
    }
}

__global__ void k_cvtB2(const float* __restrict__ W, __half* __restrict__ out, int K, int N)
{
    __shared__ float ts[32][33];
    const int k0 = blockIdx.y * 32, n0 = blockIdx.x * 32;
    const int tx = threadIdx.x, ty = threadIdx.y;
#pragma unroll
    for (int i = 0; i < 4; i++)
        ts[ty + i * 8][tx] = W[(size_t)(k0 + ty + i * 8) * N + n0 + tx];
    __syncthreads();
#pragma unroll
    for (int i = 0; i < 4; i++) {
        int n = ty + i * 8;
        __half h = __float2half(ts[tx][n]);
        size_t ob = (size_t)(n0 + n) * 2 * K + 2 * (size_t)(k0 + tx);
        out[ob] = h; out[ob + 1] = h;
    }
}

__global__ void k_sincos(const float* __restrict__ pp)
{
    size_t t = (size_t)blockIdx.x * 256 + threadIdx.x;
    float sn, cs;
    sincosf(pp[t], &sn, &cs);
    g_pc[t] = cs; g_ps[t] = sn;
}

// ---------------- value_gates ----------------
__global__ void k_vg(const float* __restrict__ Wg2, const float* __restrict__ bg2)
{
    const int warp = threadIdx.x >> 5, lane = threadIdx.x & 31;
    const int row = blockIdx.x * 8 + warp;
    const float4* g = reinterpret_cast<const float4*>(g_gh + (size_t)row * DD);
    const float4* w = reinterpret_cast<const float4*>(Wg2);
    float s = 0.f;
#pragma unroll
    for (int i = 0; i < 8; i++) {
        float4 a = g[lane + i * 32], b = w[lane + i * 32];
        s += a.x * b.x + a.y * b.y + a.z * b.z + a.w * b.w;
    }
#pragma unroll
    for (int o = 16; o > 0; o >>= 1) s += __shfl_xor_sync(0xFFFFFFFFu, s, o);
    if (lane == 0) g_vg[row] = 1.f / (1.f + expf(-(s + bg2[0])));
}

// ---------------- blend weights ----------------
__global__ void k_bw(const float* __restrict__ Wb2, const float* __restrict__ bb2)
{
    const int warp = threadIdx.x >> 5, lane = threadIdx.x & 31;
    const int row = blockIdx.x * 8 + warp;
    const float4* hv = reinterpret_cast<const float4*>(g_bh + (size_t)row * (DD / 2));
    const float4* wv = reinterpret_cast<const float4*>(Wb2);
    float s0 = 0.f, s1 = 0.f;
#pragma unroll
    for (int i = 0; i < 4; i++) {
        int idx = lane + i * 32;
        float4 a = hv[idx];
        float4 w0 = wv[2 * idx], w1 = wv[2 * idx + 1];
        s0 += a.x * w0.x + a.y * w0.z + a.z * w1.x + a.w * w1.z;
        s1 += a.x * w0.y + a.y * w0.w + a.z * w1.y + a.w * w1.w;
    }
#pragma unroll
    for (int o = 16; o > 0; o >>= 1) {
        s0 += __shfl_xor_sync(0xFFFFFFFFu, s0, o);
        s1 += __shfl_xor_sync(0xFFFFFFFFu, s1, o);
    }
    if (lane == 0) {
        float a0 = s0 + bb2[0], a1 = s1 + bb2[1];
        float m = fmaxf(a0, a1);
        float e0 = expf(a0 - m), e1 = expf(a1 - m);
        float inv = 1.f / (e0 + e1);
        g_bw[2 * row]     = e0 * inv;
        g_bw[2 * row + 1] = e1 * inv;
    }
}

// ---------------- per-batch gate scan ----------------
__global__ void k_gatescan()
{
    int b = blockIdx.x;
    __shared__ float sh[1024];
    float carry = 0.f;
    for (int t0 = 0; t0 < LL; t0 += 1024) {
        int l = t0 + threadIdx.x;
        sh[threadIdx.x] = g_vg[b * LL + l];
        __syncthreads();
        for (int off = 1; off < 1024; off <<= 1) {
            float tv = (threadIdx.x >= off) ? sh[threadIdx.x - off] : 0.f;
            __syncthreads();
            sh[threadIdx.x] += tv;
            __syncthreads();
        }
        float inc = sh[threadIdx.x] + carry;
        float tot = sh[1023];
        g_gcs[b * LL + l] = sqrtf(fmaxf(inc, 1.f));
        carry += tot;
        __syncthreads();
    }
}

// ---------------- scan pass T: batch-fused, register-carried shift ----------------
__global__ void __launch_bounds__(128)
k_scanT()
{
    const int d = blockIdx.x * 128 + threadIdx.x;
    const int c = blockIdx.y;
    const int l0 = c * TCHUNK;
    float spc[4], sps[4], skc[4], sks[4], kcp[4], ksp[4];
#pragma unroll
    for (int b = 0; b < 4; b++) {
        spc[b] = sps[b] = skc[b] = sks[b] = 0.f;
        if (l0 == 0) { kcp[b] = 0.f; ksp[b] = 0.f; }
        else {
            size_t pidx = (size_t)(b * LL + l0 - 1) * DD + d;
            kcp[b] = g_kc[pidx]; ksp[b] = g_ks[pidx];
        }
    }
    for (int t = 0; t < TCHUNK; t++) {
        const int l = l0 + t;
        const size_t pidx = (size_t)l * DD + d;
        const float cs = g_pc[pidx], sn = g_ps[pidx];
#pragma unroll
        for (int b = 0; b < 4; b++) {
            const int rowi = b * LL + l;
            const size_t idx = (size_t)rowi * DD + d;
            const float pvv = g_pv[idx];
            spc[b] = fmaf(cs, pvv, spc[b]);
            sps[b] = fmaf(sn, pvv, sps[b]);
            const float kvg = g_kv[idx] * g_vg[rowi];
            skc[b] = fmaf(kcp[b], kvg, skc[b]);
            sks[b] = fmaf(ksp[b], kvg, sks[b]);
            kcp[b] = g_kc[idx];
            ksp[b] = g_ks[idx];
        }
    }
#pragma unroll
    for (int b = 0; b < 4; b++) {
        size_t tix = (size_t)(b * NCHUNK + c) * DD + d;
        g_tot[tix]            = spc[b];
        g_tot[TOTN + tix]     = sps[b];
        g_tot[2 * TOTN + tix] = skc[b];
        g_tot[3 * TOTN + tix] = sks[b];
    }
}

// ---------------- scan pass C: batch-fused, offsets + local recompute + blend ----------------
__global__ void __launch_bounds__(128)
k_scanC()
{
    const int d = blockIdx.x * 128 + threadIdx.x;
    const int c = blockIdx.y;
    const int l0 = c * TCHUNK;
    float opc[4], ops[4], okc[4], oks[4];
    float spc[4], sps[4], skc[4], sks[4], kcp[4], ksp[4];
#pragma unroll
    for (int b = 0; b < 4; b++) {
        opc[b] = ops[b] = okc[b] = oks[b] = 0.f;
        spc[b] = sps[b] = skc[b] = sks[b] = 0.f;
        if (l0 == 0) { kcp[b] = 0.f; ksp[b] = 0.f; }
        else {
            size_t pidx = (size_t)(b * LL + l0 - 1) * DD + d;
            kcp[b] = g_kc[pidx]; ksp[b] = g_ks[pidx];
        }
    }
    for (int cc = 0; cc < c; cc++) {
#pragma unroll
        for (int b = 0; b < 4; b++) {
            size_t tix = (size_t)(b * NCHUNK + cc) * DD + d;
            opc[b] += g_tot[tix];
            ops[b] += g_tot[TOTN + tix];
            okc[b] += g_tot[2 * TOTN + tix];
            oks[b] += g_tot[3 * TOTN + tix];
        }
    }
    const float invSqrtD = 0.03125f;
    for (int t = 0; t < TCHUNK; t++) {
        const int l = l0 + t;
        const size_t pidx = (size_t)l * DD + d;
        const float cs = g_pc[pidx], sn = g_ps[pidx];
#pragma unroll
        for (int b = 0; b < 4; b++) {
            const int rowi = b * LL + l;
            const size_t idx = (size_t)rowi * DD + d;
            const float pvv = g_pv[idx];
            spc[b] = fmaf(cs, pvv, spc[b]);
            sps[b] = fmaf(sn, pvv, sps[b]);
            const float kvg = g_kv[idx] * g_vg[rowi];
            const float kcc = g_kc[idx], kss = g_ks[idx];
            skc[b] = fmaf(kcp[b], kvg, skc[b]);
            sks[b] = fmaf(ksp[b], kvg, sks[b]);
            kcp[b] = kcc; ksp[b] = kss;
            const float pos_ret = (cs * (spc[b] + opc[b]) + sn * (sps[b] + ops[b])) * invSqrtD;
            const float kv_ret  = (kcc * (skc[b] + okc[b]) + kss * (sks[b] + oks[b]))
                                  / g_gcs[rowi] * invSqrtD;
            g_blend[idx] = g_bw[2 * rowi] * pos_ret + g_bw[2 * rowi + 1] * kv_ret;
        }
    }
}

// ---------------- LayerNorm fused with fp16 pair-split output ----------------
__global__ void k_ln(const float* __restrict__ lng, const float* __restrict__ lnb,
                     __half* __restrict__ out2)
{
    int row = blockIdx.x, tid = threadIdx.x;
    float v[4], s = 0.f, sq = 0.f;
#pragma unroll
    for (int i = 0; i < 4; i++) {
        v[i] = g_blend[(size_t)row * DD + tid + i * 256];
        s += v[i]; sq += v[i] * v[i];
    }
    __shared__ float shs[256], shq[256];
    shs[tid] = s; shq[tid] = sq; __syncthreads();
    for (int o = 128; o > 0; o >>= 1) {
        if (tid < o) { shs[tid] += shs[tid + o]; shq[tid] += shq[tid + o]; }
        __syncthreads();
    }
    __shared__ float smu, srstd;
    if (tid == 0) {
        float mu  = shs[0] * (1.f / DD);
        float var = shq[0] * (1.f / DD) - mu * mu;
        smu = mu;
        srstd = rsqrtf(var + 1e-5f);
    }
    __syncthreads();
#pragma unroll
    for (int i = 0; i < 4; i++) {
        int dd = tid + i * 256;
        float t = (v[i] - smu) * srstd * lng[dd] + lnb[dd];
        __half h = __float2half(t);
        __half l = __float2half(t - __half2float(h));
        __half2 hl = __halves2half2(h, l);
        *reinterpret_cast<__half2*>(out2 + (size_t)row * 2 * DD + 2 * dd) = hl;
    }
}

// ---------------- launch ----------------
extern "C" void kernel_launch(void* const* d_in, const int* in_sizes, int n_in,
                              void* d_out, int out_size)
{
    const float* x   = (const float*)d_in[0];
    const float* pp  = (const float*)d_in[1];
    const float* Wpv = (const float*)d_in[2];
    const float* bpv = (const float*)d_in[3];
    const float* Wk  = (const float*)d_in[4];
    const float* bk  = (const float*)d_in[5];
    const float* Wkv = (const float*)d_in[6];
    const float* bkv = (const float*)d_in[7];
    const float* Wg1 = (const float*)d_in[8];
    const float* bg1 = (const float*)d_in[9];
    const float* Wg2 = (const float*)d_in[10];
    const float* bg2 = (const float*)d_in[11];
    const float* Wb1 = (const float*)d_in[12];
    const float* bb1 = (const float*)d_in[13];
    const float* Wb2 = (const float*)d_in[14];
    const float* bb2 = (const float*)d_in[15];
    const float* lng = (const float*)d_in[16];
    const float* lnb = (const float*)d_in[17];
    const float* Wo  = (const float*)d_in[18];
    const float* bo  = (const float*)d_in[19];
    float* out = (float*)d_out;

    float *pv, *kc, *ks, *kv, *gh, *bh;
    cudaGetSymbolAddress((void**)&pv, g_pv);
    cudaGetSymbolAddress((void**)&kc, g_kc);
    cudaGetSymbolAddress((void**)&ks, g_ks);
    cudaGetSymbolAddress((void**)&kv, g_kv);
    cudaGetSymbolAddress((void**)&gh, g_gh);
    cudaGetSymbolAddress((void**)&bh, g_bh);

    __nv_bfloat16 *x3, *Wk3;
    __half *x2, *ln2, *Wpvkv2, *Wg12, *Wb12, *Wo2;
    cudaGetSymbolAddress((void**)&x3,     g_x3);
    cudaGetSymbolAddress((void**)&Wk3,    g_Wk3);
    cudaGetSymbolAddress((void**)&x2,     g_x2);
    cudaGetSymbolAddress((void**)&ln2,    g_ln2);
    cudaGetSymbolAddress((void**)&Wpvkv2, g_Wpvkv2);
    cudaGetSymbolAddress((void**)&Wg12,   g_Wg12);
    cudaGetSymbolAddress((void**)&Wb12,   g_Wb12);
    cudaGetSymbolAddress((void**)&Wo2,    g_Wo2);

    cudaFuncSetAttribute((const void*)gemm_mma<EP_KEY,  false>, cudaFuncAttributeMaxDynamicSharedMemorySize, GEMM_SMEM);
    cudaFuncSetAttribute((const void*)gemm_mma<EP_PVKV, true >, cudaFuncAttributeMaxDynamicSharedMemorySize, GEMM_SMEM);
    cudaFuncSetAttribute((const void*)gemm_mma<EP_GELU, true >, cudaFuncAttributeMaxDynamicSharedMemorySize, GEMM_SMEM);
    cudaFuncSetAttribute((const void*)gemm_mma<EP_OUT,  true >, cudaFuncAttributeMaxDynamicSharedMemorySize, GEMM_SMEM);
    cudaFuncSetAttribute((const void*)gemm_gate, cudaFuncAttributeMaxDynamicSharedMemorySize, GEMM_SMEM);

    // 0-1: activation + key weight conversions
    k_cvtA<<<(MM * DD / 4) / 256, 256>>>(x, x3, x2);
    k_cvtB3<<<dim3(DD / 32, DD / 32), dim3(32, 8)>>>(Wk, Wk3, DD, DD);
    // 2: key GEMM (bf16 3-product)
    gemm_mma<EP_KEY, false><<<dim3(4, MM / 128), 512, GEMM_SMEM>>>(
        (const uint16_t*)x3, (const uint16_t*)Wk3, bk, nullptr, kc, ks, nullptr, DD, 3 * DD);
    // 3-4: pv+kv weights (fp16 pairs, packed)
    k_cvtB2<<<dim3(DD / 32, DD / 32), dim3(32, 8)>>>(Wpv, Wpvkv2, DD, DD);
    k_cvtB2<<<dim3(DD / 32, DD / 32), dim3(32, 8)>>>(Wkv, Wpvkv2 + (size_t)DD * 2 * DD, DD, DD);
    // 5: merged pv+kv GEMM (fp16 2-product, N=2048)
    gemm_mma<EP_PVKV, true><<<dim3(8, MM / 128), 512, GEMM_SMEM>>>(
        (const uint16_t*)x2, (const uint16_t*)Wpvkv2, bpv, bkv, pv, kv, nullptr, 2 * DD, 2 * DD);
    // 6-7: gate path
    k_cvtB2<<<dim3(DD / 32, 2 * DD / 32), dim3(32, 8)>>>(Wg1, Wg12, 2 * DD, DD);
    gemm_gate<<<dim3(4, MM / 128), 512, GEMM_SMEM>>>((const uint16_t*)x2, (const uint16_t*)Wg12, bg1, gh);
    // 8-9: blend hidden
    k_cvtB2<<<dim3((DD / 2) / 32, DD / 32), dim3(32, 8)>>>(Wb1, Wb12, DD, DD / 2);
    gemm_mma<EP_GELU, true><<<dim3(2, MM / 128), 512, GEMM_SMEM>>>(
        (const uint16_t*)x2, (const uint16_t*)Wb12, bb1, nullptr, bh, nullptr, nullptr, DD / 2, 2 * DD);
    // 10: pos phase cos/sin
    k_sincos<<<(LL * DD) / 256, 256>>>(pp);
    // 11-13: gates / blend softmax / gate cumsum
    k_vg<<<MM / 8, 256>>>(Wg2, bg2);
    k_bw<<<MM / 8, 256>>>(Wb2, bb2);
    k_gatescan<<<BBATCH, 1024>>>();
    // 14-15: batch-fused scans
    dim3 gscan(DD / 128, NCHUNK);
    k_scanT<<<gscan, 128>>>();
    k_scanC<<<gscan, 128>>>();
    // 16: LayerNorm (fused fp16 pair-split)
    k_ln<<<MM, 256>>>(lng, lnb, ln2);
    // 17-18: output path (+residual)
    k_cvtB2<<<dim3(DD / 32, DD / 32), dim3(32, 8)>>>(Wo, Wo2, DD, DD);
    gemm_mma<EP_OUT, true><<<dim3(4, MM / 128), 512, GEMM_SMEM>>>(
        (const uint16_t*)ln2, (const uint16_t*)Wo2, bo, nullptr, out, nullptr, x, DD, 2 * DD);
}

// round 11
// speedup vs baseline: 1.0857x; 1.0457x over previous
#include <cuda_runtime.h>
#include <cuda_bf16.h>
#include <cuda_fp16.h>
#include <math.h>
#include <stdint.h>

// ---------------- problem constants ----------------
#define BBATCH 4
#define LL 4096
#define DD 1024
#define MM (BBATCH * LL)          // 16384 rows
#define NCHUNK 64
#define TCHUNK (LL / NCHUNK)      // 64
#define TOTN (BBATCH * NCHUNK * DD)

// ---------------- fp32 scratch ----------------
__device__ float g_pv[(size_t)MM * DD];
__device__ float g_kc[(size_t)MM * DD];
__device__ float g_ks[(size_t)MM * DD];
__device__ float g_kv[(size_t)MM * DD];
__device__ float g_gh[(size_t)MM * DD];
__device__ float g_bh[(size_t)MM * (DD / 2)];
__device__ float g_vg[MM];
__device__ float g_gcs[MM];
__device__ float g_bw[MM * 2];
__device__ float g_tot[4 * TOTN];
__device__ float g_blend[(size_t)MM * DD];
__device__ float g_pc[(size_t)LL * DD];
__device__ float g_ps[(size_t)LL * DD];

// ---------------- split-precision operand scratch ----------------
__device__ __nv_bfloat16 g_x3 [(size_t)MM * 3 * DD];
__device__ __nv_bfloat16 g_Wk3[(size_t)DD * 3 * DD];
__device__ __half g_x2   [(size_t)MM * 2 * DD];
__device__ __half g_ln2  [(size_t)MM * 2 * DD];
__device__ __half g_Wpvkv2[(size_t)2 * DD * 2 * DD];
__device__ __half g_Wg12 [(size_t)DD * 4 * DD];
__device__ __half g_Wb12 [(size_t)(DD / 2) * 2 * DD];
__device__ __half g_Wo2  [(size_t)DD * 2 * DD];

// ================= PTX helpers (family-safe) =================
__device__ __forceinline__ uint32_t s2u(const void* p) {
    return (uint32_t)__cvta_generic_to_shared(p);
}
__device__ __forceinline__ void ldsm4(uint32_t& r0, uint32_t& r1, uint32_t& r2, uint32_t& r3, uint32_t a) {
    asm volatile("ldmatrix.sync.aligned.m8n8.x4.shared.b16 {%0,%1,%2,%3}, [%4];"
                 : "=r"(r0), "=r"(r1), "=r"(r2), "=r"(r3) : "r"(a));
}
template <bool F16>
__device__ __forceinline__ void mma16816(float* d, const uint32_t* a, uint32_t b0, uint32_t b1);
template <>
__device__ __forceinline__ void mma16816<false>(float* d, const uint32_t* a, uint32_t b0, uint32_t b1) {
    asm volatile("mma.sync.aligned.m16n8k16.row.col.f32.bf16.bf16.f32 "
                 "{%0,%1,%2,%3},{%4,%5,%6,%7},{%8,%9},{%0,%1,%2,%3};"
                 : "+f"(d[0]), "+f"(d[1]), "+f"(d[2]), "+f"(d[3])
                 : "r"(a[0]), "r"(a[1]), "r"(a[2]), "r"(a[3]), "r"(b0), "r"(b1));
}
template <>
__device__ __forceinline__ void mma16816<true>(float* d, const uint32_t* a, uint32_t b0, uint32_t b1) {
    asm volatile("mma.sync.aligned.m16n8k16.row.col.f32.f16.f16.f32 "
                 "{%0,%1,%2,%3},{%4,%5,%6,%7},{%8,%9},{%0,%1,%2,%3};"
                 : "+f"(d[0]), "+f"(d[1]), "+f"(d[2]), "+f"(d[3])
                 : "r"(a[0]), "r"(a[1]), "r"(a[2]), "r"(a[3]), "r"(b0), "r"(b1));
}
__device__ __forceinline__ void cpasync16(uint32_t s, const void* g) {
    asm volatile("cp.async.cg.shared.global [%0], [%1], 16;" :: "r"(s), "l"(g));
}
__device__ __forceinline__ void sts_zero16(uint32_t a) {
    asm volatile("st.shared.v4.b32 [%0], {%1,%1,%1,%1};" :: "r"(a), "r"(0) : "memory");
}
__device__ __forceinline__ void cp_commit() { asm volatile("cp.async.commit_group;"); }
template <int n> __device__ __forceinline__ void cp_wait() {
    asm volatile("cp.async.wait_group %0;" :: "n"(n));
}

// ================= GEMM core (R8 config: 512 thr, 16 warps 4x4, warp tile 32x64) =================
constexpr int EP_KEY  = 1;
constexpr int EP_GELU = 2;
constexpr int EP_OUT  = 3;
constexpr int EP_PVKV = 4;

#define STG 49152
#define GEMM_SMEM (1024 + 3 * STG)

struct MmaCtx {
    uint32_t aBase[2]; int aXor[2];
    uint32_t bBase[4]; int bXor[4];
    int chi;
};
__device__ __forceinline__ void mma_ctx_init(MmaCtx& cx, int lane, int wm, int wn) {
    const int mat = lane >> 3, mr = lane & 7;
    cx.chi = mat >> 1;
#pragma unroll
    for (int mi = 0; mi < 2; mi++) {
        int row = wm * 32 + mi * 16 + mr + (mat & 1) * 8;
        cx.aBase[mi] = row * 128; cx.aXor[mi] = row & 7;
    }
#pragma unroll
    for (int g = 0; g < 4; g++) {
        int row = wn * 64 + g * 16 + mr + (mat & 1) * 8;
        cx.bBase[g] = 16384 + row * 128; cx.bXor[g] = row & 7;
    }
}
template <bool F16>
__device__ __forceinline__ void mma_tile(const MmaCtx& cx, uint32_t ps, float acc[2][8][4]) {
#pragma unroll
    for (int kk = 0; kk < 4; kk++) {
        const int cb = kk * 2 + cx.chi;
        uint32_t a0[4], a1[4];
        ldsm4(a0[0], a0[1], a0[2], a0[3], ps + cx.aBase[0] + ((cb ^ cx.aXor[0]) << 4));
        ldsm4(a1[0], a1[1], a1[2], a1[3], ps + cx.aBase[1] + ((cb ^ cx.aXor[1]) << 4));
#pragma unroll
        for (int g = 0; g < 4; g++) {
            uint32_t b0, b1, b2, b3;
            ldsm4(b0, b1, b2, b3, ps + cx.bBase[g] + ((cb ^ cx.bXor[g]) << 4));
            mma16816<F16>(acc[0][2 * g],     a0, b0, b2);
            mma16816<F16>(acc[0][2 * g + 1], a0, b1, b3);
            mma16816<F16>(acc[1][2 * g],     a1, b0, b2);
            mma16816<F16>(acc[1][2 * g + 1], a1, b1, b3);
        }
    }
}

// ================= generic GEMM =================
template <int MODE, bool F16>
__global__ void __launch_bounds__(512, 1)
gemm_mma(const uint16_t* __restrict__ A, const uint16_t* __restrict__ Bt,
         const float* __restrict__ bias, const float* __restrict__ bias2,
         float* __restrict__ C, float* __restrict__ C2,
         const float* __restrict__ addsrc, int N, int K)
{
    extern __shared__ __align__(16) char smem_[];
    const uint32_t sbase = (s2u(smem_) + 1023u) & ~1023u;
    const int tid = threadIdx.x, lane = tid & 31, warp = tid >> 5;
    const int wm = warp >> 2, wn = warp & 3;
    const int brow = blockIdx.y, bcol = blockIdx.x;

    const uint16_t* Ag = A  + (size_t)brow * 128 * K;
    const uint16_t* Bg = Bt + (size_t)bcol * 256 * K;

    uint32_t so[6];
    const uint16_t* gp[6];
#pragma unroll
    for (int j = 0; j < 6; j++) {
        int id = tid + j * 512;
        int q; const uint16_t* base; uint32_t off;
        if (id < 1024) { q = id;        base = Ag; off = 0; }
        else           { q = id - 1024; base = Bg; off = 16384; }
        int r = q >> 3, c = q & 7;
        gp[j] = base + (size_t)r * K + c * 8;
        so[j] = off + r * 128 + ((uint32_t)(c ^ (r & 7)) << 4);
    }
    MmaCtx cx; mma_ctx_init(cx, lane, wm, wn);

    float acc[2][8][4];
#pragma unroll
    for (int i = 0; i < 2; i++)
#pragma unroll
        for (int j = 0; j < 8; j++)
#pragma unroll
            for (int q = 0; q < 4; q++) acc[i][j][q] = 0.f;

    const int nk = K >> 6;
#pragma unroll
    for (int j = 0; j < 6; j++) cpasync16(sbase + so[j], gp[j]);
    cp_commit();
#pragma unroll
    for (int j = 0; j < 6; j++) { gp[j] += 64; cpasync16(sbase + STG + so[j], gp[j]); }
    cp_commit();

    for (int it = 0; it < nk; it++) {
        if (it < nk - 1) cp_wait<1>(); else cp_wait<0>();
        __syncthreads();
        if (it + 2 < nk) {
            const uint32_t dst = sbase + (uint32_t)((it + 2) % 3) * STG;
#pragma unroll
            for (int j = 0; j < 6; j++) { gp[j] += 64; cpasync16(dst + so[j], gp[j]); }
            cp_commit();
        }
        mma_tile<F16>(cx, sbase + (uint32_t)(it % 3) * STG, acc);
    }

    // -------- epilogue --------
    const int r0 = brow * 128 + wm * 32 + (lane >> 2);
    const int sect = (MODE == EP_PVKV) ? (bcol >> 2) : 0;
    const float* bp = (MODE == EP_PVKV && sect) ? bias2 : bias;
    float* Cp = (MODE == EP_PVKV && sect) ? C2 : C;
    const int ostride = (MODE == EP_PVKV) ? DD : N;
    const int c0 = ((MODE == EP_PVKV) ? ((bcol & 3) * 256) : (bcol * 256)) + wn * 64 + (lane & 3) * 2;
#pragma unroll
    for (int mi = 0; mi < 2; mi++) {
#pragma unroll
        for (int nj = 0; nj < 8; nj++) {
            const int col = c0 + nj * 8;
            const float bv0 = bp[col], bv1 = bp[col + 1];
#pragma unroll
            for (int h = 0; h < 2; h++) {
                const int row = r0 + mi * 16 + h * 8;
                const size_t base = (size_t)row * ostride + col;
                float v0 = acc[mi][nj][2 * h]     + bv0;
                float v1 = acc[mi][nj][2 * h + 1] + bv1;
                if (MODE == EP_GELU) {
                    v0 = 0.5f * v0 * (1.f + erff(v0 * 0.70710678118654752f));
                    v1 = 0.5f * v1 * (1.f + erff(v1 * 0.70710678118654752f));
                }
                if (MODE == EP_OUT) { v0 += addsrc[base]; v1 += addsrc[base + 1]; }
                if (MODE == EP_KEY) {
                    float s0, cc0, s1, cc1;
                    sincosf(tanhf(v0) * 3.14159265358979323846f, &s0, &cc0);
                    sincosf(tanhf(v1) * 3.14159265358979323846f, &s1, &cc1);
                    *reinterpret_cast<float2*>(C  + base) = make_float2(cc0, cc1);
                    *reinterpret_cast<float2*>(C2 + base) = make_float2(s0, s1);
                } else {
                    *reinterpret_cast<float2*>(Cp + base) = make_float2(v0, v1);
                }
            }
        }
    }
}

// ================= gate GEMM: A = [x2 | shift1(x2)] virtual concat (fp16 pairs) =================
__global__ void __launch_bounds__(512, 1)
gemm_gate(const uint16_t* __restrict__ X2, const uint16_t* __restrict__ Bt,
          const float* __restrict__ bias, float* __restrict__ C)
{
    extern __shared__ __align__(16) char smem_[];
    const uint32_t sbase = (s2u(smem_) + 1023u) & ~1023u;
    const int tid = threadIdx.x, lane = tid & 31, warp = tid >> 5;
    const int wm = warp >> 2, wn = warp & 3;
    const int brow = blockIdx.y, bcol = blockIdx.x;
    const int K = 4 * DD;
    const int KH = 2 * DD;
    const int nkh = 32;

    uint32_t soA[2];
    const uint16_t *aCur[2], *aPrev[2];
    bool validA[2];
#pragma unroll
    for (int j = 0; j < 2; j++) {
        int q = tid + j * 512;
        int r = q >> 3, c = q & 7;
        int R = brow * 128 + r;
        aCur[j]  = X2 + (size_t)R * KH + c * 8;
        aPrev[j] = X2 + ((size_t)R - 1) * KH + c * 8;
        validA[j] = (R & (LL - 1)) != 0;
        soA[j] = r * 128 + ((uint32_t)(c ^ (r & 7)) << 4);
    }
    uint32_t soB[4];
    const uint16_t* bgp[4];
#pragma unroll
    for (int j = 0; j < 4; j++) {
        int q = tid + j * 512;
        int r = q >> 3, c = q & 7;
        bgp[j] = Bt + (size_t)(bcol * 256 + r) * K + c * 8;
        soB[j] = 16384 + r * 128 + ((uint32_t)(c ^ (r & 7)) << 4);
    }
    MmaCtx cx; mma_ctx_init(cx, lane, wm, wn);

    float acc[2][8][4];
#pragma unroll
    for (int i = 0; i < 2; i++)
#pragma unroll
        for (int j = 0; j < 8; j++)
#pragma unroll
            for (int q = 0; q < 4; q++) acc[i][j][q] = 0.f;

    const int nk = K >> 6;   // 64
#define GATE_LOAD(ITP, DST)                                                           \
    do {                                                                              \
        int itp_ = (ITP);                                                             \
        if (itp_ < nkh) {                                                             \
            cpasync16((DST) + soA[0], aCur[0] + itp_ * 64);                           \
            cpasync16((DST) + soA[1], aCur[1] + itp_ * 64);                           \
        } else {                                                                      \
            if (validA[0]) cpasync16((DST) + soA[0], aPrev[0] + (itp_ - nkh) * 64);   \
            else sts_zero16((DST) + soA[0]);                                          \
            if (validA[1]) cpasync16((DST) + soA[1], aPrev[1] + (itp_ - nkh) * 64);   \
            else sts_zero16((DST) + soA[1]);                                          \
        }                                                                             \
        cpasync16((DST) + soB[0], bgp[0] + itp_ * 64);                                \
        cpasync16((DST) + soB[1], bgp[1] + itp_ * 64);                                \
        cpasync16((DST) + soB[2], bgp[2] + itp_ * 64);                                \
        cpasync16((DST) + soB[3], bgp[3] + itp_ * 64);                                \
        cp_commit();                                                                  \
    } while (0)

    GATE_LOAD(0, sbase);
    GATE_LOAD(1, sbase + STG);

    for (int it = 0; it < nk; it++) {
        if (it < nk - 1) cp_wait<1>(); else cp_wait<0>();
        __syncthreads();
        if (it + 2 < nk) {
            const uint32_t dst = sbase + (uint32_t)((it + 2) % 3) * STG;
            GATE_LOAD(it + 2, dst);
        }
        mma_tile<true>(cx, sbase + (uint32_t)(it % 3) * STG, acc);
    }
#undef GATE_LOAD

    const int r0 = brow * 128 + wm * 32 + (lane >> 2);
    const int c0 = bcol * 256 + wn * 64 + (lane & 3) * 2;
#pragma unroll
    for (int mi = 0; mi < 2; mi++) {
#pragma unroll
        for (int nj = 0; nj < 8; nj++) {
            const int col = c0 + nj * 8;
            const float bv0 = bias[col], bv1 = bias[col + 1];
#pragma unroll
            for (int h = 0; h < 2; h++) {
                const int row = r0 + mi * 16 + h * 8;
                const size_t base = (size_t)row * DD + col;
                float v0 = acc[mi][nj][2 * h]     + bv0;
                float v1 = acc[mi][nj][2 * h + 1] + bv1;
                v0 = 0.5f * v0 * (1.f + erff(v0 * 0.70710678118654752f));
                v1 = 0.5f * v1 * (1.f + erff(v1 * 0.70710678118654752f));
                *reinterpret_cast<float2*>(C + base) = make_float2(v0, v1);
            }
        }
    }
}

// ---------------- conversion kernels ----------------
__global__ void k_cvtA(const float* __restrict__ in, __nv_bfloat16* __restrict__ out3,
                       __half* __restrict__ out2)
{
    int t = blockIdx.x * 256 + threadIdx.x;
    int m = t >> 8, k4 = t & 255;
    float4 v = reinterpret_cast<const float4*>(in)[(size_t)m * 256 + k4];
    float vv[4] = {v.x, v.y, v.z, v.w};
    __align__(8) __nv_bfloat16 o3[12];
    __align__(16) __half o2[8];
#pragma unroll
    for (int j = 0; j < 4; j++) {
        __nv_bfloat16 h = __float2bfloat16(vv[j]);
        __nv_bfloat16 l = __float2bfloat16(vv[j] - __bfloat162float(h));
        o3[3 * j] = h; o3[3 * j + 1] = l; o3[3 * j + 2] = h;
        __half h2 = __float2half(vv[j]);
        __half l2 = __float2half(vv[j] - __half2float(h2));
        o2[2 * j] = h2; o2[2 * j + 1] = l2;
    }
    uint2* dst = reinterpret_cast<uint2*>(out3 + (size_t)m * 3 * DD + 12 * k4);
    const uint2* src = reinterpret_cast<const uint2*>(o3);
    dst[0] = src[0]; dst[1] = src[1]; dst[2] = src[2];
    reinterpret_cast<uint4*>(out2 + (size_t)m * 2 * DD + 8 * k4)[0] =
        *reinterpret_cast<const uint4*>(o2);
}

__global__ void k_cvtB3(const float* __restrict__ W, __nv_bfloat16* __restrict__ out, int K, int N)
{
    __shared__ float ts[32][33];
    const int k0 = blockIdx.y * 32, n0 = blockIdx.x * 32;
    const int tx = threadIdx.x, ty = threadIdx.y;
#pragma unroll
    for (int i = 0; i < 4; i++)
        ts[ty + i * 8][tx] = W[(size_t)(k0 + ty + i * 8) * N + n0 + tx];
    __syncthreads();
#pragma unroll
    for (int i = 0; i < 4; i++) {
        int n = ty + i * 8;
        float w = ts[tx][n];
        __nv_bfloat16 h = __float2bfloat16(w);
        __nv_bfloat16 l = __float2bfloat16(w - __bfloat162float(h));
        size_t ob = (size_t)(n0 + n) * 3 * K + 3 * (size_t)(k0 + tx);
        out[ob] = h; out[ob + 1] = h; out[ob + 2] = l;
    }
}

__global__ void k_cvtB2(const float* __restrict__ W, __half* __restrict__ out, int K, int N)
{
    __shared__ float ts[32][33];
    const int k0 = blockIdx.y * 32, n0 = blockIdx.x * 32;
    const int tx = threadIdx.x, ty = threadIdx.y;
#pragma unroll
    for (int i = 0; i < 4; i++)
        ts[ty + i * 8][tx] = W[(size_t)(k0 + ty + i * 8) * N + n0 + tx];
    __syncthreads();
#pragma unroll
    for (int i = 0; i < 4; i++) {
        int n = ty + i * 8;
        __half h = __float2half(ts[tx][n]);
        size_t ob = (size_t)(n0 + n) * 2 * K + 2 * (size_t)(k0 + tx);
        out[ob] = h; out[ob + 1] = h;
    }
}

__global__ void k_sincos(const float* __restrict__ pp)
{
    size_t t = (size_t)blockIdx.x * 256 + threadIdx.x;
    float sn, cs;
    sincosf(pp[t], &sn, &cs);
    g_pc[t] = cs; g_ps[t] = sn;
}

// ---------------- value_gates ----------------
__global__ void k_vg(const float* __restrict__ Wg2, const float* __restrict__ bg2)
{
    const int warp = threadIdx.x >> 5, lane = threadIdx.x & 31;
    const int row = blockIdx.x * 8 + warp;
    const float4* g = reinterpret_cast<const float4*>(g_gh + (size_t)row * DD);
    const float4* w = reinterpret_cast<const float4*>(Wg2);
    float s = 0.f;
#pragma unroll
    for (int i = 0; i < 8; i++) {
        float4 a = g[lane + i * 32], b = w[lane + i * 32];
        s += a.x * b.x + a.y * b.y + a.z * b.z + a.w * b.w;
    }
#pragma unroll
    for (int o = 16; o > 0; o >>= 1) s += __shfl_xor_sync(0xFFFFFFFFu, s, o);
    if (lane == 0) g_vg[row] = 1.f / (1.f + expf(-(s + bg2[0])));
}

// ---------------- blend weights ----------------
__global__ void k_bw(const float* __restrict__ Wb2, const float* __restrict__ bb2)
{
    const int warp = threadIdx.x >> 5, lane = threadIdx.x & 31;
    const int row = blockIdx.x * 8 + warp;
    const float4* hv = reinterpret_cast<const float4*>(g_bh + (size_t)row * (DD / 2));
    const float4* wv = reinterpret_cast<const float4*>(Wb2);
    float s0 = 0.f, s1 = 0.f;
#pragma unroll
    for (int i = 0; i < 4; i++) {
        int idx = lane + i * 32;
        float4 a = hv[idx];
        float4 w0 = wv[2 * idx], w1 = wv[2 * idx + 1];
        s0 += a.x * w0.x + a.y * w0.z + a.z * w1.x + a.w * w1.z;
        s1 += a.x * w0.y + a.y * w0.w + a.z * w1.y + a.w * w1.w;
    }
#pragma unroll
    for (int o = 16; o > 0; o >>= 1) {
        s0 += __shfl_xor_sync(0xFFFFFFFFu, s0, o);
        s1 += __shfl_xor_sync(0xFFFFFFFFu, s1, o);
    }
    if (lane == 0) {
        float a0 = s0 + bb2[0], a1 = s1 + bb2[1];
        float m = fmaxf(a0, a1);
        float e0 = expf(a0 - m), e1 = expf(a1 - m);
        float inv = 1.f / (e0 + e1);
        g_bw[2 * row]     = e0 * inv;
        g_bw[2 * row + 1] = e1 * inv;
    }
}

// ---------------- per-batch gate scan ----------------
__global__ void k_gatescan()
{
    int b = blockIdx.x;
    __shared__ float sh[1024];
    float carry = 0.f;
    for (int t0 = 0; t0 < LL; t0 += 1024) {
        int l = t0 + threadIdx.x;
        sh[threadIdx.x] = g_vg[b * LL + l];
        __syncthreads();
        for (int off = 1; off < 1024; off <<= 1) {
            float tv = (threadIdx.x >= off) ? sh[threadIdx.x - off] : 0.f;
            __syncthreads();
            sh[threadIdx.x] += tv;
            __syncthreads();
        }
        float inc = sh[threadIdx.x] + carry;
        float tot = sh[1023];
        g_gcs[b * LL + l] = sqrtf(fmaxf(inc, 1.f));
        carry += tot;
        __syncthreads();
    }
}

// ---------------- scan pass T (R8 grid shape + register-carried shift) ----------------
__global__ void k_scanT()
{
    const int d = blockIdx.x * 256 + threadIdx.x;
    const int c = blockIdx.y, b = blockIdx.z;
    const int l0 = c * TCHUNK;
    float spc = 0.f, sps = 0.f, skc = 0.f, sks = 0.f;
    float kcp, ksp;
    if (l0 == 0) { kcp = 0.f; ksp = 0.f; }
    else {
        size_t pidx = (size_t)(b * LL + l0 - 1) * DD + d;
        kcp = g_kc[pidx]; ksp = g_ks[pidx];
    }
    for (int t = 0; t < TCHUNK; t++) {
        const int l = l0 + t;
        const int rowi = b * LL + l;
        const size_t idx = (size_t)rowi * DD + d;
        const size_t pidx = (size_t)l * DD + d;
        const float pvv = g_pv[idx];
        spc = fmaf(g_pc[pidx], pvv, spc);
        sps = fmaf(g_ps[pidx], pvv, sps);
        const float kvg = g_kv[idx] * g_vg[rowi];
        skc = fmaf(kcp, kvg, skc);
        sks = fmaf(ksp, kvg, sks);
        kcp = g_kc[idx];
        ksp = g_ks[idx];
    }
    size_t tix = (size_t)(b * NCHUNK + c) * DD + d;
    g_tot[tix]            = spc;
    g_tot[TOTN + tix]     = sps;
    g_tot[2 * TOTN + tix] = skc;
    g_tot[3 * TOTN + tix] = sks;
}

// ---------------- scan pass C (R8 grid shape + register-carried shift) ----------------
__global__ void k_scanC()
{
    const int d = blockIdx.x * 256 + threadIdx.x;
    const int c = blockIdx.y, b = blockIdx.z;
    const int l0 = c * TCHUNK;
    float opc = 0.f, ops = 0.f, okc = 0.f, oks = 0.f;
    for (int cc = 0; cc < c; cc++) {
        size_t tix = (size_t)(b * NCHUNK + cc) * DD + d;
        opc += g_tot[tix];
        ops += g_tot[TOTN + tix];
        okc += g_tot[2 * TOTN + tix];
        oks += g_tot[3 * TOTN + tix];
    }
    const float invSqrtD = 0.03125f;
    float spc = 0.f, sps = 0.f, skc = 0.f, sks = 0.f;
    float kcp, ksp;
    if (l0 == 0) { kcp = 0.f; ksp = 0.f; }
    else {
        size_t pidx = (size_t)(b * LL + l0 - 1) * DD + d;
        kcp = g_kc[pidx]; ksp = g_ks[pidx];
    }
    for (int t = 0; t < TCHUNK; t++) {
        const int l = l0 + t;
        const int rowi = b * LL + l;
        const size_t idx = (size_t)rowi * DD + d;
        const size_t pidx = (size_t)l * DD + d;
        const float pvv = g_pv[idx];
        const float cs = g_pc[pidx], sn = g_ps[pidx];
        spc = fmaf(cs, pvv, spc);
        sps = fmaf(sn, pvv, sps);
        const float kvg = g_kv[idx] * g_vg[rowi];
        const float kcc = g_kc[idx], kss = g_ks[idx];
        skc = fmaf(kcp, kvg, skc);
        sks = fmaf(ksp, kvg, sks);
        kcp = kcc; ksp = kss;
        const float pos_ret = (cs * (spc + opc) + sn * (sps + ops)) * invSqrtD;
        const float kv_ret  = (kcc * (skc + okc) + kss * (sks + oks)) / g_gcs[rowi] * invSqrtD;
        g_blend[idx] = g_bw[2 * rowi] * pos_ret + g_bw[2 * rowi + 1] * kv_ret;
    }
}

// ---------------- LayerNorm fused with fp16 pair-split output ----------------
__global__ void k_ln(const float* __restrict__ lng, const float* __restrict__ lnb,
                     __half* __restrict__ out2)
{
    int row = blockIdx.x, tid = threadIdx.x;
    float v[4], s = 0.f, sq = 0.f;
#pragma unroll
    for (int i = 0; i < 4; i++) {
        v[i] = g_blend[(size_t)row * DD + tid + i * 256];
        s += v[i]; sq += v[i] * v[i];
    }
    __shared__ float shs[256], shq[256];
    shs[tid] = s; shq[tid] = sq; __syncthreads();
    for (int o = 128; o > 0; o >>= 1) {
        if (tid < o) { shs[tid] += shs[tid + o]; shq[tid] += shq[tid + o]; }
        __syncthreads();
    }
    __shared__ float smu, srstd;
    if (tid == 0) {
        float mu  = shs[0] * (1.f / DD);
        float var = shq[0] * (1.f / DD) - mu * mu;
        smu = mu;
        srstd = rsqrtf(var + 1e-5f);
    }
    __syncthreads();
#pragma unroll
    for (int i = 0; i < 4; i++) {
        int dd = tid + i * 256;
        float t = (v[i] - smu) * srstd * lng[dd] + lnb[dd];
        __half h = __float2half(t);
        __half l = __float2half(t - __half2float(h));
        __half2 hl = __halves2half2(h, l);
        *reinterpret_cast<__half2*>(out2 + (size_t)row * 2 * DD + 2 * dd) = hl;
    }
}

// ---------------- launch ----------------
extern "C" void kernel_launch(void* const* d_in, const int* in_sizes, int n_in,
                              void* d_out, int out_size)
{
    const float* x   = (const float*)d_in[0];
    const float* pp  = (const float*)d_in[1];
    const float* Wpv = (const float*)d_in[2];
    const float* bpv = (const float*)d_in[3];
    const float* Wk  = (const float*)d_in[4];
    const float* bk  = (const float*)d_in[5];
    const float* Wkv = (const float*)d_in[6];
    const float* bkv = (const float*)d_in[7];
    const float* Wg1 = (const float*)d_in[8];
    const float* bg1 = (const float*)d_in[9];
    const float* Wg2 = (const float*)d_in[10];
    const float* bg2 = (const float*)d_in[11];
    const float* Wb1 = (const float*)d_in[12];
    const float* bb1 = (const float*)d_in[13];
    const float* Wb2 = (const float*)d_in[14];
    const float* bb2 = (const float*)d_in[15];
    const float* lng = (const float*)d_in[16];
    const float* lnb = (const float*)d_in[17];
    const float* Wo  = (const float*)d_in[18];
    const float* bo  = (const float*)d_in[19];
    float* out = (float*)d_out;

    float *pv, *kc, *ks, *kv, *gh, *bh;
    cudaGetSymbolAddress((void**)&pv, g_pv);
    cudaGetSymbolAddress((void**)&kc, g_kc);
    cudaGetSymbolAddress((void**)&ks, g_ks);
    cudaGetSymbolAddress((void**)&kv, g_kv);
    cudaGetSymbolAddress((void**)&gh, g_gh);
    cudaGetSymbolAddress((void**)&bh, g_bh);

    __nv_bfloat16 *x3, *Wk3;
    __half *x2, *ln2, *Wpvkv2, *Wg12, *Wb12, *Wo2;
    cudaGetSymbolAddress((void**)&x3,     g_x3);
    cudaGetSymbolAddress((void**)&Wk3,    g_Wk3);
    cudaGetSymbolAddress((void**)&x2,     g_x2);
    cudaGetSymbolAddress((void**)&ln2,    g_ln2);
    cudaGetSymbolAddress((void**)&Wpvkv2, g_Wpvkv2);
    cudaGetSymbolAddress((void**)&Wg12,   g_Wg12);
    cudaGetSymbolAddress((void**)&Wb12,   g_Wb12);
    cudaGetSymbolAddress((void**)&Wo2,    g_Wo2);

    cudaFuncSetAttribute((const void*)gemm_mma<EP_KEY,  false>, cudaFuncAttributeMaxDynamicSharedMemorySize, GEMM_SMEM);
    cudaFuncSetAttribute((const void*)gemm_mma<EP_PVKV, true >, cudaFuncAttributeMaxDynamicSharedMemorySize, GEMM_SMEM);
    cudaFuncSetAttribute((const void*)gemm_mma<EP_GELU, true >, cudaFuncAttributeMaxDynamicSharedMemorySize, GEMM_SMEM);
    cudaFuncSetAttribute((const void*)gemm_mma<EP_OUT,  true >, cudaFuncAttributeMaxDynamicSharedMemorySize, GEMM_SMEM);
    cudaFuncSetAttribute((const void*)gemm_gate, cudaFuncAttributeMaxDynamicSharedMemorySize, GEMM_SMEM);

    // 0-1: activation + key weight conversions
    k_cvtA<<<(MM * DD / 4) / 256, 256>>>(x, x3, x2);
    k_cvtB3<<<dim3(DD / 32, DD / 32), dim3(32, 8)>>>(Wk, Wk3, DD, DD);
    // 2: key GEMM (bf16 3-product)
    gemm_mma<EP_KEY, false><<<dim3(4, MM / 128), 512, GEMM_SMEM>>>(
        (const uint16_t*)x3, (const uint16_t*)Wk3, bk, nullptr, kc, ks, nullptr, DD, 3 * DD);
    // 3-4: pv+kv weights (fp16 pairs, packed)
    k_cvtB2<<<dim3(DD / 32, DD / 32), dim3(32, 8)>>>(Wpv, Wpvkv2, DD, DD);
    k_cvtB2<<<dim3(DD / 32, DD / 32), dim3(32, 8)>>>(Wkv, Wpvkv2 + (size_t)DD * 2 * DD, DD, DD);
    // 5: merged pv+kv GEMM (fp16 2-product, N=2048)
    gemm_mma<EP_PVKV, true><<<dim3(8, MM / 128), 512, GEMM_SMEM>>>(
        (const uint16_t*)x2, (const uint16_t*)Wpvkv2, bpv, bkv, pv, kv, nullptr, 2 * DD, 2 * DD);
    // 6-7: gate path
    k_cvtB2<<<dim3(DD / 32, 2 * DD / 32), dim3(32, 8)>>>(Wg1, Wg12, 2 * DD, DD);
    gemm_gate<<<dim3(4, MM / 128), 512, GEMM_SMEM>>>((const uint16_t*)x2, (const uint16_t*)Wg12, bg1, gh);
    // 8-9: blend hidden
    k_cvtB2<<<dim3((DD / 2) / 32, DD / 32), dim3(32, 8)>>>(Wb1, Wb12, DD, DD / 2);
    gemm_mma<EP_GELU, true><<<dim3(2, MM / 128), 512, GEMM_SMEM>>>(
        (const uint16_t*)x2, (const uint16_t*)Wb12, bb1, nullptr, bh, nullptr, nullptr, DD / 2, 2 * DD);
    // 10: pos phase cos/sin
    k_sincos<<<(LL * DD) / 256, 256>>>(pp);
    // 11-13: gates / blend softmax / gate cumsum
    k_vg<<<MM / 8, 256>>>(Wg2, bg2);
    k_bw<<<MM / 8, 256>>>(Wb2, bb2);
    k_gatescan<<<BBATCH, 1024>>>();
    // 14-15: scans (R8 parallelism + register-carried shift)
    dim3 gscan(DD / 256, NCHUNK, BBATCH);
    k_scanT<<<gscan, 256>>>();
    k_scanC<<<gscan, 256>>>();
    // 16: LayerNorm (fused fp16 pair-split)
    k_ln<<<MM, 256>>>(lng, lnb, ln2);
    // 17-18: output path (+residual)
    k_cvtB2<<<dim3(DD / 32, DD / 32), dim3(32, 8)>>>(Wo, Wo2, DD, DD);
    gemm_mma<EP_OUT, true><<<dim3(4, MM / 128), 512, GEMM_SMEM>>>(
        (const uint16_t*)ln2, (const uint16_t*)Wo2, bo, nullptr, out, nullptr, x, DD, 2 * DD);
}

// round 12
// speedup vs baseline: 1.2002x; 1.1054x over previous
#include <cuda_runtime.h>
#include <cuda_fp16.h>
#include <math.h>
#include <stdint.h>

// ---------------- problem constants ----------------
#define BBATCH 4
#define LL 4096
#define DD 1024
#define MM (BBATCH * LL)          // 16384 rows
#define NCHUNK 64
#define TCHUNK (LL / NCHUNK)      // 64
#define TOTN (BBATCH * NCHUNK * DD)

// ---------------- fp32 scratch ----------------
__device__ float g_pv[(size_t)MM * DD];
__device__ float g_kc[(size_t)MM * DD];
__device__ float g_ks[(size_t)MM * DD];
__device__ float g_kv[(size_t)MM * DD];
__device__ float g_gh[(size_t)MM * DD];
__device__ float g_bh[(size_t)MM * (DD / 2)];
__device__ float g_vg[MM];
__device__ float g_gcs[MM];
__device__ float g_bw[MM * 2];
__device__ float g_tot[4 * TOTN];
__device__ float g_blend[(size_t)MM * DD];
__device__ float g_pc[(size_t)LL * DD];
__device__ float g_ps[(size_t)LL * DD];

// ---------------- fp16 pair operand scratch ----------------
__device__ __half g_x2    [(size_t)MM * 2 * DD];
__device__ __half g_ln2   [(size_t)MM * 2 * DD];
__device__ __half g_Wqkv2 [(size_t)3 * DD * 2 * DD];   // [pv | key | kv] each [1024][2K]
__device__ __half g_Wg12  [(size_t)DD * 4 * DD];
__device__ __half g_Wb12  [(size_t)(DD / 2) * 2 * DD];
__device__ __half g_Wo2   [(size_t)DD * 2 * DD];

// ================= PTX helpers (family-safe) =================
__device__ __forceinline__ uint32_t s2u(const void* p) {
    return (uint32_t)__cvta_generic_to_shared(p);
}
__device__ __forceinline__ void ldsm4(uint32_t& r0, uint32_t& r1, uint32_t& r2, uint32_t& r3, uint32_t a) {
    asm volatile("ldmatrix.sync.aligned.m8n8.x4.shared.b16 {%0,%1,%2,%3}, [%4];"
                 : "=r"(r0), "=r"(r1), "=r"(r2), "=r"(r3) : "r"(a));
}
__device__ __forceinline__ void mma16816(float* d, const uint32_t* a, uint32_t b0, uint32_t b1) {
    asm volatile("mma.sync.aligned.m16n8k16.row.col.f32.f16.f16.f32 "
                 "{%0,%1,%2,%3},{%4,%5,%6,%7},{%8,%9},{%0,%1,%2,%3};"
                 : "+f"(d[0]), "+f"(d[1]), "+f"(d[2]), "+f"(d[3])
                 : "r"(a[0]), "r"(a[1]), "r"(a[2]), "r"(a[3]), "r"(b0), "r"(b1));
}
__device__ __forceinline__ void cpasync16(uint32_t s, const void* g) {
    asm volatile("cp.async.cg.shared.global [%0], [%1], 16;" :: "r"(s), "l"(g));
}
__device__ __forceinline__ void sts_zero16(uint32_t a) {
    asm volatile("st.shared.v4.b32 [%0], {%1,%1,%1,%1};" :: "r"(a), "r"(0) : "memory");
}
__device__ __forceinline__ void cp_commit() { asm volatile("cp.async.commit_group;"); }
template <int n> __device__ __forceinline__ void cp_wait() {
    asm volatile("cp.async.wait_group %0;" :: "n"(n));
}
__device__ __forceinline__ float tanh_fast(float x) {
    float y;
    asm("tanh.approx.f32 %0, %1;" : "=f"(y) : "f"(x));
    return y;
}

// ================= GEMM core (R8 config: 512 thr, 16 warps 4x4, warp tile 32x64) =================
constexpr int EP_GELU = 2;
constexpr int EP_OUT  = 3;

#define STG 49152
#define GEMM_SMEM (1024 + 3 * STG)

struct MmaCtx {
    uint32_t aBase[2]; int aXor[2];
    uint32_t bBase[4]; int bXor[4];
    int chi;
};
__device__ __forceinline__ void mma_ctx_init(MmaCtx& cx, int lane, int wm, int wn) {
    const int mat = lane >> 3, mr = lane & 7;
    cx.chi = mat >> 1;
#pragma unroll
    for (int mi = 0; mi < 2; mi++) {
        int row = wm * 32 + mi * 16 + mr + (mat & 1) * 8;
        cx.aBase[mi] = row * 128; cx.aXor[mi] = row & 7;
    }
#pragma unroll
    for (int g = 0; g < 4; g++) {
        int row = wn * 64 + g * 16 + mr + (mat & 1) * 8;
        cx.bBase[g] = 16384 + row * 128; cx.bXor[g] = row & 7;
    }
}
__device__ __forceinline__ void mma_tile(const MmaCtx& cx, uint32_t ps, float acc[2][8][4]) {
#pragma unroll
    for (int kk = 0; kk < 4; kk++) {
        const int cb = kk * 2 + cx.chi;
        uint32_t a0[4], a1[4];
        ldsm4(a0[0], a0[1], a0[2], a0[3], ps + cx.aBase[0] + ((cb ^ cx.aXor[0]) << 4));
        ldsm4(a1[0], a1[1], a1[2], a1[3], ps + cx.aBase[1] + ((cb ^ cx.aXor[1]) << 4));
#pragma unroll
        for (int g = 0; g < 4; g++) {
            uint32_t b0, b1, b2, b3;
            ldsm4(b0, b1, b2, b3, ps + cx.bBase[g] + ((cb ^ cx.bXor[g]) << 4));
            mma16816(acc[0][2 * g],     a0, b0, b2);
            mma16816(acc[0][2 * g + 1], a0, b1, b3);
            mma16816(acc[1][2 * g],     a1, b0, b2);
            mma16816(acc[1][2 * g + 1], a1, b1, b3);
        }
    }
}

// shared loader/mainloop body: computes acc over K (all fp16 pairs)
#define GEMM_MAINLOOP(Aptr, Bptr, Kv)                                                  \
    uint32_t so[6];                                                                    \
    const uint16_t* gp[6];                                                             \
    _Pragma("unroll")                                                                  \
    for (int j = 0; j < 6; j++) {                                                      \
        int id = tid + j * 512;                                                        \
        int q; const uint16_t* base; uint32_t off;                                     \
        if (id < 1024) { q = id;        base = (Aptr); off = 0; }                      \
        else           { q = id - 1024; base = (Bptr); off = 16384; }                  \
        int r = q >> 3, c = q & 7;                                                     \
        gp[j] = base + (size_t)r * (Kv) + c * 8;                                       \
        so[j] = off + r * 128 + ((uint32_t)(c ^ (r & 7)) << 4);                        \
    }                                                                                  \
    MmaCtx cx; mma_ctx_init(cx, lane, wm, wn);                                         \
    float acc[2][8][4];                                                                \
    _Pragma("unroll")                                                                  \
    for (int i = 0; i < 2; i++)                                                        \
        _Pragma("unroll")                                                              \
        for (int j = 0; j < 8; j++)                                                    \
            _Pragma("unroll")                                                          \
            for (int q = 0; q < 4; q++) acc[i][j][q] = 0.f;                            \
    const int nk = (Kv) >> 6;                                                          \
    _Pragma("unroll")                                                                  \
    for (int j = 0; j < 6; j++) cpasync16(sbase + so[j], gp[j]);                       \
    cp_commit();                                                                       \
    _Pragma("unroll")                                                                  \
    for (int j = 0; j < 6; j++) { gp[j] += 64; cpasync16(sbase + STG + so[j], gp[j]); }\
    cp_commit();                                                                       \
    for (int it = 0; it < nk; it++) {                                                  \
        if (it < nk - 1) cp_wait<1>(); else cp_wait<0>();                              \
        __syncthreads();                                                               \
        if (it + 2 < nk) {                                                             \
            const uint32_t dst = sbase + (uint32_t)((it + 2) % 3) * STG;               \
            _Pragma("unroll")                                                          \
            for (int j = 0; j < 6; j++) { gp[j] += 64; cpasync16(dst + so[j], gp[j]); }\
            cp_commit();                                                               \
        }                                                                              \
        mma_tile(cx, sbase + (uint32_t)(it % 3) * STG, acc);                           \
    }

// ================= merged QKV GEMM (fp16 pairs, N=3072, dispatch epilogue) =================
__global__ void __launch_bounds__(512, 1)
gemm_qkv(const uint16_t* __restrict__ A, const uint16_t* __restrict__ Bt,
         const float* __restrict__ bpv, const float* __restrict__ bk,
         const float* __restrict__ bkv,
         float* __restrict__ pv, float* __restrict__ kc, float* __restrict__ ks,
         float* __restrict__ kv)
{
    extern __shared__ __align__(16) char smem_[];
    const uint32_t sbase = (s2u(smem_) + 1023u) & ~1023u;
    const int tid = threadIdx.x, lane = tid & 31, warp = tid >> 5;
    const int wm = warp >> 2, wn = warp & 3;
    const int brow = blockIdx.y, bcol = blockIdx.x;
    const int K = 2 * DD;

    const uint16_t* Ag = A  + (size_t)brow * 128 * K;
    const uint16_t* Bg = Bt + (size_t)bcol * 256 * K;
    GEMM_MAINLOOP(Ag, Bg, K)

    const int sect = bcol >> 2;                 // 0: pv, 1: key, 2: kv
    const float* bp = (sect == 0) ? bpv : (sect == 1) ? bk : bkv;
    float* Cm = (sect == 0) ? pv : kv;
    const int r0 = brow * 128 + wm * 32 + (lane >> 2);
    const int c0 = (bcol & 3) * 256 + wn * 64 + (lane & 3) * 2;
#pragma unroll
    for (int mi = 0; mi < 2; mi++) {
#pragma unroll
        for (int nj = 0; nj < 8; nj++) {
            const int col = c0 + nj * 8;
            const float bv0 = bp[col], bv1 = bp[col + 1];
#pragma unroll
            for (int h = 0; h < 2; h++) {
                const int row = r0 + mi * 16 + h * 8;
                const size_t base = (size_t)row * DD + col;
                float v0 = acc[mi][nj][2 * h]     + bv0;
                float v1 = acc[mi][nj][2 * h + 1] + bv1;
                if (sect == 1) {
                    float s0, cc0, s1, cc1;
                    __sincosf(tanh_fast(v0) * 3.14159265358979323846f, &s0, &cc0);
                    __sincosf(tanh_fast(v1) * 3.14159265358979323846f, &s1, &cc1);
                    *reinterpret_cast<float2*>(kc + base) = make_float2(cc0, cc1);
                    *reinterpret_cast<float2*>(ks + base) = make_float2(s0, s1);
                } else {
                    *reinterpret_cast<float2*>(Cm + base) = make_float2(v0, v1);
                }
            }
        }
    }
}

// ================= generic GEMM (gelu / out epilogues) =================
template <int MODE>
__global__ void __launch_bounds__(512, 1)
gemm_mma(const uint16_t* __restrict__ A, const uint16_t* __restrict__ Bt,
         const float* __restrict__ bias, float* __restrict__ C,
         const float* __restrict__ addsrc, int N, int K)
{
    extern __shared__ __align__(16) char smem_[];
    const uint32_t sbase = (s2u(smem_) + 1023u) & ~1023u;
    const int tid = threadIdx.x, lane = tid & 31, warp = tid >> 5;
    const int wm = warp >> 2, wn = warp & 3;
    const int brow = blockIdx.y, bcol = blockIdx.x;

    const uint16_t* Ag = A  + (size_t)brow * 128 * K;
    const uint16_t* Bg = Bt + (size_t)bcol * 256 * K;
    GEMM_MAINLOOP(Ag, Bg, K)

    const int r0 = brow * 128 + wm * 32 + (lane >> 2);
    const int c0 = bcol * 256 + wn * 64 + (lane & 3) * 2;
#pragma unroll
    for (int mi = 0; mi < 2; mi++) {
#pragma unroll
        for (int nj = 0; nj < 8; nj++) {
            const int col = c0 + nj * 8;
            const float bv0 = bias[col], bv1 = bias[col + 1];
#pragma unroll
            for (int h = 0; h < 2; h++) {
                const int row = r0 + mi * 16 + h * 8;
                const size_t base = (size_t)row * N + col;
                float v0 = acc[mi][nj][2 * h]     + bv0;
                float v1 = acc[mi][nj][2 * h + 1] + bv1;
                if (MODE == EP_GELU) {
                    v0 = 0.5f * v0 * (1.f + erff(v0 * 0.70710678118654752f));
                    v1 = 0.5f * v1 * (1.f + erff(v1 * 0.70710678118654752f));
                }
                if (MODE == EP_OUT) { v0 += addsrc[base]; v1 += addsrc[base + 1]; }
                *reinterpret_cast<float2*>(C + base) = make_float2(v0, v1);
            }
        }
    }
}

// ================= gate GEMM: A = [x2 | shift1(x2)] virtual concat =================
__global__ void __launch_bounds__(512, 1)
gemm_gate(const uint16_t* __restrict__ X2, const uint16_t* __restrict__ Bt,
          const float* __restrict__ bias, float* __restrict__ C)
{
    extern __shared__ __align__(16) char smem_[];
    const uint32_t sbase = (s2u(smem_) + 1023u) & ~1023u;
    const int tid = threadIdx.x, lane = tid & 31, warp = tid >> 5;
    const int wm = warp >> 2, wn = warp & 3;
    const int brow = blockIdx.y, bcol = blockIdx.x;
    const int K = 4 * DD;
    const int KH = 2 * DD;
    const int nkh = 32;

    uint32_t soA[2];
    const uint16_t *aCur[2], *aPrev[2];
    bool validA[2];
#pragma unroll
    for (int j = 0; j < 2; j++) {
        int q = tid + j * 512;
        int r = q >> 3, c = q & 7;
        int R = brow * 128 + r;
        aCur[j]  = X2 + (size_t)R * KH + c * 8;
        aPrev[j] = X2 + ((size_t)R - 1) * KH + c * 8;
        validA[j] = (R & (LL - 1)) != 0;
        soA[j] = r * 128 + ((uint32_t)(c ^ (r & 7)) << 4);
    }
    uint32_t soB[4];
    const uint16_t* bgp[4];
#pragma unroll
    for (int j = 0; j < 4; j++) {
        int q = tid + j * 512;
        int r = q >> 3, c = q & 7;
        bgp[j] = Bt + (size_t)(bcol * 256 + r) * K + c * 8;
        soB[j] = 16384 + r * 128 + ((uint32_t)(c ^ (r & 7)) << 4);
    }
    MmaCtx cx; mma_ctx_init(cx, lane, wm, wn);

    float acc[2][8][4];
#pragma unroll
    for (int i = 0; i < 2; i++)
#pragma unroll
        for (int j = 0; j < 8; j++)
#pragma unroll
            for (int q = 0; q < 4; q++) acc[i][j][q] = 0.f;

    const int nk = K >> 6;   // 64
#define GATE_LOAD(ITP, DST)                                                           \
    do {                                                                              \
        int itp_ = (ITP);                                                             \
        if (itp_ < nkh) {                                                             \
            cpasync16((DST) + soA[0], aCur[0] + itp_ * 64);                           \
            cpasync16((DST) + soA[1], aCur[1] + itp_ * 64);                           \
        } else {                                                                      \
            if (validA[0]) cpasync16((DST) + soA[0], aPrev[0] + (itp_ - nkh) * 64);   \
            else sts_zero16((DST) + soA[0]);                                          \
            if (validA[1]) cpasync16((DST) + soA[1], aPrev[1] + (itp_ - nkh) * 64);   \
            else sts_zero16((DST) + soA[1]);                                          \
        }                                                                             \
        cpasync16((DST) + soB[0], bgp[0] + itp_ * 64);                                \
        cpasync16((DST) + soB[1], bgp[1] + itp_ * 64);                                \
        cpasync16((DST) + soB[2], bgp[2] + itp_ * 64);                                \
        cpasync16((DST) + soB[3], bgp[3] + itp_ * 64);                                \
        cp_commit();                                                                  \
    } while (0)

    GATE_LOAD(0, sbase);
    GATE_LOAD(1, sbase + STG);

    for (int it = 0; it < nk; it++) {
        if (it < nk - 1) cp_wait<1>(); else cp_wait<0>();
        __syncthreads();
        if (it + 2 < nk) {
            const uint32_t dst = sbase + (uint32_t)((it + 2) % 3) * STG;
            GATE_LOAD(it + 2, dst);
        }
        mma_tile(cx, sbase + (uint32_t)(it % 3) * STG, acc);
    }
#undef GATE_LOAD

    const int r0 = brow * 128 + wm * 32 + (lane >> 2);
    const int c0 = bcol * 256 + wn * 64 + (lane & 3) * 2;
#pragma unroll
    for (int mi = 0; mi < 2; mi++) {
#pragma unroll
        for (int nj = 0; nj < 8; nj++) {
            const int col = c0 + nj * 8;
            const float bv0 = bias[col], bv1 = bias[col + 1];
#pragma unroll
            for (int h = 0; h < 2; h++) {
                const int row = r0 + mi * 16 + h * 8;
                const size_t base = (size_t)row * DD + col;
                float v0 = acc[mi][nj][2 * h]     + bv0;
                float v1 = acc[mi][nj][2 * h + 1] + bv1;
                v0 = 0.5f * v0 * (1.f + erff(v0 * 0.70710678118654752f));
                v1 = 0.5f * v1 * (1.f + erff(v1 * 0.70710678118654752f));
                *reinterpret_cast<float2*>(C + base) = make_float2(v0, v1);
            }
        }
    }
}

// ---------------- conversion kernels ----------------
__global__ void k_cvtA2(const float* __restrict__ in, __half* __restrict__ out)
{
    int t = blockIdx.x * 256 + threadIdx.x;
    int m = t >> 8, k4 = t & 255;
    float4 v = reinterpret_cast<const float4*>(in)[(size_t)m * 256 + k4];
    float vv[4] = {v.x, v.y, v.z, v.w};
    __align__(16) __half o2[8];
#pragma unroll
    for (int j = 0; j < 4; j++) {
        __half h = __float2half(vv[j]);
        __half l = __float2half(vv[j] - __half2float(h));
        o2[2 * j] = h; o2[2 * j + 1] = l;
    }
    reinterpret_cast<uint4*>(out + (size_t)m * 2 * DD + 8 * k4)[0] =
        *reinterpret_cast<const uint4*>(o2);
}

__global__ void k_cvtB2(const float* __restrict__ W, __half* __restrict__ out, int K, int N)
{
    __shared__ float ts[32][33];
    const int k0 = blockIdx.y * 32, n0 = blockIdx.x * 32;
    const int tx = threadIdx.x, ty = threadIdx.y;
#pragma unroll
    for (int i = 0; i < 4; i++)
        ts[ty + i * 8][tx] = W[(size_t)(k0 + ty + i * 8) * N + n0 + tx];
    __syncthreads();
#pragma unroll
    for (int i = 0; i < 4; i++) {
        int n = ty + i * 8;
        __half h = __float2half(ts[tx][n]);
        size_t ob = (size_t)(n0 + n) * 2 * K + 2 * (size_t)(k0 + tx);
        out[ob] = h; out[ob + 1] = h;
    }
}

// 3 square weights -> packed [pv|key|kv] fp16-pair buffer, one launch
__global__ void k_cvtB2x3(const float* __restrict__ W0, const float* __restrict__ W1,
                          const float* __restrict__ W2, __half* __restrict__ out)
{
    __shared__ float ts[32][33];
    const float* W = (blockIdx.z == 0) ? W0 : (blockIdx.z == 1) ? W1 : W2;
    __half* o = out + (size_t)blockIdx.z * DD * 2 * DD;
    const int k0 = blockIdx.y * 32, n0 = blockIdx.x * 32;
    const int tx = threadIdx.x, ty = threadIdx.y;
#pragma unroll
    for (int i = 0; i < 4; i++)
        ts[ty + i * 8][tx] = W[(size_t)(k0 + ty + i * 8) * DD + n0 + tx];
    __syncthreads();
#pragma unroll
    for (int i = 0; i < 4; i++) {
        int n = ty + i * 8;
        __half h = __float2half(ts[tx][n]);
        size_t ob = (size_t)(n0 + n) * 2 * DD + 2 * (size_t)(k0 + tx);
        o[ob] = h; o[ob + 1] = h;
    }
}

__global__ void k_sincos(const float* __restrict__ pp)
{
    size_t t = (size_t)blockIdx.x * 256 + threadIdx.x;
    float sn, cs;
    __sincosf(pp[t], &sn, &cs);
    g_pc[t] = cs; g_ps[t] = sn;
}

// ---------------- value_gates ----------------
__global__ void k_vg(const float* __restrict__ Wg2, const float* __restrict__ bg2)
{
    const int warp = threadIdx.x >> 5, lane = threadIdx.x & 31;
    const int row = blockIdx.x * 8 + warp;
    const float4* g = reinterpret_cast<const float4*>(g_gh + (size_t)row * DD);
    const float4* w = reinterpret_cast<const float4*>(Wg2);
    float s = 0.f;
#pragma unroll
    for (int i = 0; i < 8; i++) {
        float4 a = g[lane + i * 32], b = w[lane + i * 32];
        s += a.x * b.x + a.y * b.y + a.z * b.z + a.w * b.w;
    }
#pragma unroll
    for (int o = 16; o > 0; o >>= 1) s += __shfl_xor_sync(0xFFFFFFFFu, s, o);
    if (lane == 0) g_vg[row] = 1.f / (1.f + expf(-(s + bg2[0])));
}

// ---------------- blend weights ----------------
__global__ void k_bw(const float* __restrict__ Wb2, const float* __restrict__ bb2)
{
    const int warp = threadIdx.x >> 5, lane = threadIdx.x & 31;
    const int row = blockIdx.x * 8 + warp;
    const float4* hv = reinterpret_cast<const float4*>(g_bh + (size_t)row * (DD / 2));
    const float4* wv = reinterpret_cast<const float4*>(Wb2);
    float s0 = 0.f, s1 = 0.f;
#pragma unroll
    for (int i = 0; i < 4; i++) {
        int idx = lane + i * 32;
        float4 a = hv[idx];
        float4 w0 = wv[2 * idx], w1 = wv[2 * idx + 1];
        s0 += a.x * w0.x + a.y * w0.z + a.z * w1.x + a.w * w1.z;
        s1 += a.x * w0.y + a.y * w0.w + a.z * w1.y + a.w * w1.w;
    }
#pragma unroll
    for (int o = 16; o > 0; o >>= 1) {
        s0 += __shfl_xor_sync(0xFFFFFFFFu, s0, o);
        s1 += __shfl_xor_sync(0xFFFFFFFFu, s1, o);
    }
    if (lane == 0) {
        float a0 = s0 + bb2[0], a1 = s1 + bb2[1];
        float m = fmaxf(a0, a1);
        float e0 = expf(a0 - m), e1 = expf(a1 - m);
        float inv = 1.f / (e0 + e1);
        g_bw[2 * row]     = e0 * inv;
        g_bw[2 * row + 1] = e1 * inv;
    }
}

// ---------------- per-batch gate scan ----------------
__global__ void k_gatescan()
{
    int b = blockIdx.x;
    __shared__ float sh[1024];
    float carry = 0.f;
    for (int t0 = 0; t0 < LL; t0 += 1024) {
        int l = t0 + threadIdx.x;
        sh[threadIdx.x] = g_vg[b * LL + l];
        __syncthreads();
        for (int off = 1; off < 1024; off <<= 1) {
            float tv = (threadIdx.x >= off) ? sh[threadIdx.x - off] : 0.f;
            __syncthreads();
            sh[threadIdx.x] += tv;
            __syncthreads();
        }
        float inc = sh[threadIdx.x] + carry;
        float tot = sh[1023];
        g_gcs[b * LL + l] = sqrtf(fmaxf(inc, 1.f));
        carry += tot;
        __syncthreads();
    }
}

// ---------------- scan pass T ----------------
__global__ void k_scanT()
{
    const int d = blockIdx.x * 256 + threadIdx.x;
    const int c = blockIdx.y, b = blockIdx.z;
    const int l0 = c * TCHUNK;
    float spc = 0.f, sps = 0.f, skc = 0.f, sks = 0.f;
    float kcp, ksp;
    if (l0 == 0) { kcp = 0.f; ksp = 0.f; }
    else {
        size_t pidx = (size_t)(b * LL + l0 - 1) * DD + d;
        kcp = g_kc[pidx]; ksp = g_ks[pidx];
    }
    for (int t = 0; t < TCHUNK; t++) {
        const int l = l0 + t;
        const int rowi = b * LL + l;
        const size_t idx = (size_t)rowi * DD + d;
        const size_t pidx = (size_t)l * DD + d;
        const float pvv = g_pv[idx];
        spc = fmaf(g_pc[pidx], pvv, spc);
        sps = fmaf(g_ps[pidx], pvv, sps);
        const float kvg = g_kv[idx] * g_vg[rowi];
        skc = fmaf(kcp, kvg, skc);
        sks = fmaf(ksp, kvg, sks);
        kcp = g_kc[idx];
        ksp = g_ks[idx];
    }
    size_t tix = (size_t)(b * NCHUNK + c) * DD + d;
    g_tot[tix]            = spc;
    g_tot[TOTN + tix]     = sps;
    g_tot[2 * TOTN + tix] = skc;
    g_tot[3 * TOTN + tix] = sks;
}

// ---------------- scan pass C ----------------
__global__ void k_scanC()
{
    const int d = blockIdx.x * 256 + threadIdx.x;
    const int c = blockIdx.y, b = blockIdx.z;
    const int l0 = c * TCHUNK;
    float opc = 0.f, ops = 0.f, okc = 0.f, oks = 0.f;
    for (int cc = 0; cc < c; cc++) {
        size_t tix = (size_t)(b * NCHUNK + cc) * DD + d;
        opc += g_tot[tix];
        ops += g_tot[TOTN + tix];
        okc += g_tot[2 * TOTN + tix];
        oks += g_tot[3 * TOTN + tix];
    }
    const float invSqrtD = 0.03125f;
    float spc = 0.f, sps = 0.f, skc = 0.f, sks = 0.f;
    float kcp, ksp;
    if (l0 == 0) { kcp = 0.f; ksp = 0.f; }
    else {
        size_t pidx = (size_t)(b * LL + l0 - 1) * DD + d;
        kcp = g_kc[pidx]; ksp = g_ks[pidx];
    }
    for (int t = 0; t < TCHUNK; t++) {
        const int l = l0 + t;
        const int rowi = b * LL + l;
        const size_t idx = (size_t)rowi * DD + d;
        const size_t pidx = (size_t)l * DD + d;
        const float pvv = g_pv[idx];
        const float cs = g_pc[pidx], sn = g_ps[pidx];
        spc = fmaf(cs, pvv, spc);
        sps = fmaf(sn, pvv, sps);
        const float kvg = g_kv[idx] * g_vg[rowi];
        const float kcc = g_kc[idx], kss = g_ks[idx];
        skc = fmaf(kcp, kvg, skc);
        sks = fmaf(ksp, kvg, sks);
        kcp = kcc; ksp = kss;
        const float pos_ret = (cs * (spc + opc) + sn * (sps + ops)) * invSqrtD;
        const float kv_ret  = (kcc * (skc + okc) + kss * (sks + oks)) / g_gcs[rowi] * invSqrtD;
        g_blend[idx] = g_bw[2 * rowi] * pos_ret + g_bw[2 * rowi + 1] * kv_ret;
    }
}

// ---------------- LayerNorm fused with fp16 pair-split output ----------------
__global__ void k_ln(const float* __restrict__ lng, const float* __restrict__ lnb,
                     __half* __restrict__ out2)
{
    int row = blockIdx.x, tid = threadIdx.x;
    float v[4], s = 0.f, sq = 0.f;
#pragma unroll
    for (int i = 0; i < 4; i++) {
        v[i] = g_blend[(size_t)row * DD + tid + i * 256];
        s += v[i]; sq += v[i] * v[i];
    }
    __shared__ float shs[256], shq[256];
    shs[tid] = s; shq[tid] = sq; __syncthreads();
    for (int o = 128; o > 0; o >>= 1) {
        if (tid < o) { shs[tid] += shs[tid + o]; shq[tid] += shq[tid + o]; }
        __syncthreads();
    }
    __shared__ float smu, srstd;
    if (tid == 0) {
        float mu  = shs[0] * (1.f / DD);
        float var = shq[0] * (1.f / DD) - mu * mu;
        smu = mu;
        srstd = rsqrtf(var + 1e-5f);
    }
    __syncthreads();
#pragma unroll
    for (int i = 0; i < 4; i++) {
        int dd = tid + i * 256;
        float t = (v[i] - smu) * srstd * lng[dd] + lnb[dd];
        __half h = __float2half(t);
        __half l = __float2half(t - __half2float(h));
        __half2 hl = __halves2half2(h, l);
        *reinterpret_cast<__half2*>(out2 + (size_t)row * 2 * DD + 2 * dd) = hl;
    }
}

// ---------------- launch ----------------
extern "C" void kernel_launch(void* const* d_in, const int* in_sizes, int n_in,
                              void* d_out, int out_size)
{
    const float* x   = (const float*)d_in[0];
    const float* pp  = (const float*)d_in[1];
    const float* Wpv = (const float*)d_in[2];
    const float* bpv = (const float*)d_in[3];
    const float* Wk  = (const float*)d_in[4];
    const float* bk  = (const float*)d_in[5];
    const float* Wkv = (const float*)d_in[6];
    const float* bkv = (const float*)d_in[7];
    const float* Wg1 = (const float*)d_in[8];
    const float* bg1 = (const float*)d_in[9];
    const float* Wg2 = (const float*)d_in[10];
    const float* bg2 = (const float*)d_in[11];
    const float* Wb1 = (const float*)d_in[12];
    const float* bb1 = (const float*)d_in[13];
    const float* Wb2 = (const float*)d_in[14];
    const float* bb2 = (const float*)d_in[15];
    const float* lng = (const float*)d_in[16];
    const float* lnb = (const float*)d_in[17];
    const float* Wo  = (const float*)d_in[18];
    const float* bo  = (const float*)d_in[19];
    float* out = (float*)d_out;

    float *pv, *kc, *ks, *kv, *gh, *bh;
    cudaGetSymbolAddress((void**)&pv, g_pv);
    cudaGetSymbolAddress((void**)&kc, g_kc);
    cudaGetSymbolAddress((void**)&ks, g_ks);
    cudaGetSymbolAddress((void**)&kv, g_kv);
    cudaGetSymbolAddress((void**)&gh, g_gh);
    cudaGetSymbolAddress((void**)&bh, g_bh);

    __half *x2, *ln2, *Wqkv2, *Wg12, *Wb12, *Wo2;
    cudaGetSymbolAddress((void**)&x2,    g_x2);
    cudaGetSymbolAddress((void**)&ln2,   g_ln2);
    cudaGetSymbolAddress((void**)&Wqkv2, g_Wqkv2);
    cudaGetSymbolAddress((void**)&Wg12,  g_Wg12);
    cudaGetSymbolAddress((void**)&Wb12,  g_Wb12);
    cudaGetSymbolAddress((void**)&Wo2,   g_Wo2);

    cudaFuncSetAttribute((const void*)gemm_qkv,          cudaFuncAttributeMaxDynamicSharedMemorySize, GEMM_SMEM);
    cudaFuncSetAttribute((const void*)gemm_mma<EP_GELU>, cudaFuncAttributeMaxDynamicSharedMemorySize, GEMM_SMEM);
    cudaFuncSetAttribute((const void*)gemm_mma<EP_OUT >, cudaFuncAttributeMaxDynamicSharedMemorySize, GEMM_SMEM);
    cudaFuncSetAttribute((const void*)gemm_gate,         cudaFuncAttributeMaxDynamicSharedMemorySize, GEMM_SMEM);

    // 0-1: conversions (activations, packed qkv weights)
    k_cvtA2<<<(MM * DD / 4) / 256, 256>>>(x, x2);
    k_cvtB2x3<<<dim3(DD / 32, DD / 32, 3), dim3(32, 8)>>>(Wpv, Wk, Wkv, Wqkv2);
    // 2: merged QKV GEMM (fp16 pairs, N=3072, epilogue dispatch)
    gemm_qkv<<<dim3(12, MM / 128), 512, GEMM_SMEM>>>(
        (const uint16_t*)x2, (const uint16_t*)Wqkv2, bpv, bk, bkv, pv, kc, ks, kv);
    // 3-4: gate path
    k_cvtB2<<<dim3(DD / 32, 2 * DD / 32), dim3(32, 8)>>>(Wg1, Wg12, 2 * DD, DD);
    gemm_gate<<<dim3(4, MM / 128), 512, GEMM_SMEM>>>((const uint16_t*)x2, (const uint16_t*)Wg12, bg1, gh);
    // 5-6: blend hidden
    k_cvtB2<<<dim3((DD / 2) / 32, DD / 32), dim3(32, 8)>>>(Wb1, Wb12, DD, DD / 2);
    gemm_mma<EP_GELU><<<dim3(2, MM / 128), 512, GEMM_SMEM>>>(
        (const uint16_t*)x2, (const uint16_t*)Wb12, bb1, bh, nullptr, DD / 2, 2 * DD);
    // 7: pos phase cos/sin (fast approx)
    k_sincos<<<(LL * DD) / 256, 256>>>(pp);
    // 8-10: gates / blend softmax / gate cumsum
    k_vg<<<MM / 8, 256>>>(Wg2, bg2);
    k_bw<<<MM / 8, 256>>>(Wb2, bb2);
    k_gatescan<<<BBATCH, 1024>>>();
    // 11-12: scans
    dim3 gscan(DD / 256, NCHUNK, BBATCH);
    k_scanT<<<gscan, 256>>>();
    k_scanC<<<gscan, 256>>>();
    // 13: LayerNorm (fused fp16 pair-split)
    k_ln<<<MM, 256>>>(lng, lnb, ln2);
    // 14-15: output path (+residual)
    k_cvtB2<<<dim3(DD / 32, DD / 32), dim3(32, 8)>>>(Wo, Wo2, DD, DD);
    gemm_mma<EP_OUT><<<dim3(4, MM / 128), 512, GEMM_SMEM>>>(
        (const uint16_t*)ln2, (const uint16_t*)Wo2, bo, out, x, DD, 2 * DD);
}

// round 13
// speedup vs baseline: 1.9077x; 1.5895x over previous
#include <cuda_runtime.h>
#include <cuda_fp16.h>
#include <math.h>
#include <stdint.h>

// ---------------- problem constants ----------------
#define BBATCH 4
#define LL 4096
#define DD 1024
#define MM (BBATCH * LL)          // 16384 rows
#define NCHUNK 64
#define TCHUNK (LL / NCHUNK)      // 64
#define TOTN (BBATCH * NCHUNK * DD)

// ---------------- fp32 scratch ----------------
__device__ float g_pv[(size_t)MM * DD];
__device__ float g_kc[(size_t)MM * DD];
__device__ float g_ks[(size_t)MM * DD];
__device__ float g_kv[(size_t)MM * DD];
__device__ float g_gh[(size_t)MM * DD];
__device__ float g_bh[(size_t)MM * (DD / 2)];
__device__ float g_vg[MM];
__device__ float g_gcs[MM];
__device__ float g_bw[MM * 2];
__device__ float g_tot[4 * TOTN];
__device__ float g_blend[(size_t)MM * DD];
__device__ float g_pc[(size_t)LL * DD];
__device__ float g_ps[(size_t)LL * DD];

// ---------------- plain fp16 operand scratch ----------------
__device__ __half g_x2   [(size_t)MM * DD];
__device__ __half g_ln2  [(size_t)MM * DD];
__device__ __half g_Wqkv2[(size_t)3 * DD * DD];   // [pv | key | kv] each [1024][K=1024]
__device__ __half g_Wg12 [(size_t)DD * 2 * DD];   // [1024][2048]
__device__ __half g_Wb12 [(size_t)(DD / 2) * DD]; // [512][1024]
__device__ __half g_Wo2  [(size_t)DD * DD];

// ================= PTX helpers (family-safe) =================
__device__ __forceinline__ uint32_t s2u(const void* p) {
    return (uint32_t)__cvta_generic_to_shared(p);
}
__device__ __forceinline__ void ldsm4(uint32_t& r0, uint32_t& r1, uint32_t& r2, uint32_t& r3, uint32_t a) {
    asm volatile("ldmatrix.sync.aligned.m8n8.x4.shared.b16 {%0,%1,%2,%3}, [%4];"
                 : "=r"(r0), "=r"(r1), "=r"(r2), "=r"(r3) : "r"(a));
}
__device__ __forceinline__ void mma16816(float* d, const uint32_t* a, uint32_t b0, uint32_t b1) {
    asm volatile("mma.sync.aligned.m16n8k16.row.col.f32.f16.f16.f32 "
                 "{%0,%1,%2,%3},{%4,%5,%6,%7},{%8,%9},{%0,%1,%2,%3};"
                 : "+f"(d[0]), "+f"(d[1]), "+f"(d[2]), "+f"(d[3])
                 : "r"(a[0]), "r"(a[1]), "r"(a[2]), "r"(a[3]), "r"(b0), "r"(b1));
}
__device__ __forceinline__ void cpasync16(uint32_t s, const void* g) {
    asm volatile("cp.async.cg.shared.global [%0], [%1], 16;" :: "r"(s), "l"(g));
}
__device__ __forceinline__ void sts_zero16(uint32_t a) {
    asm volatile("st.shared.v4.b32 [%0], {%1,%1,%1,%1};" :: "r"(a), "r"(0) : "memory");
}
__device__ __forceinline__ void cp_commit() { asm volatile("cp.async.commit_group;"); }
template <int n> __device__ __forceinline__ void cp_wait() {
    asm volatile("cp.async.wait_group %0;" :: "n"(n));
}
__device__ __forceinline__ float tanh_fast(float x) {
    float y;
    asm("tanh.approx.f32 %0, %1;" : "=f"(y) : "f"(x));
    return y;
}

// ================= GEMM core (512 thr, 16 warps 4x4, warp tile 32x64) =================
constexpr int EP_GELU = 2;
constexpr int EP_OUT  = 3;

#define STG 49152
#define GEMM_SMEM (1024 + 3 * STG)

struct MmaCtx {
    uint32_t aBase[2]; int aXor[2];
    uint32_t bBase[4]; int bXor[4];
    int chi;
};
__device__ __forceinline__ void mma_ctx_init(MmaCtx& cx, int lane, int wm, int wn) {
    const int mat = lane >> 3, mr = lane & 7;
    cx.chi = mat >> 1;
#pragma unroll
    for (int mi = 0; mi < 2; mi++) {
        int row = wm * 32 + mi * 16 + mr + (mat & 1) * 8;
        cx.aBase[mi] = row * 128; cx.aXor[mi] = row & 7;
    }
#pragma unroll
    for (int g = 0; g < 4; g++) {
        int row = wn * 64 + g * 16 + mr + (mat & 1) * 8;
        cx.bBase[g] = 16384 + row * 128; cx.bXor[g] = row & 7;
    }
}
__device__ __forceinline__ void mma_tile(const MmaCtx& cx, uint32_t ps, float acc[2][8][4]) {
#pragma unroll
    for (int kk = 0; kk < 4; kk++) {
        const int cb = kk * 2 + cx.chi;
        uint32_t a0[4], a1[4];
        ldsm4(a0[0], a0[1], a0[2], a0[3], ps + cx.aBase[0] + ((cb ^ cx.aXor[0]) << 4));
        ldsm4(a1[0], a1[1], a1[2], a1[3], ps + cx.aBase[1] + ((cb ^ cx.aXor[1]) << 4));
#pragma unroll
        for (int g = 0; g < 4; g++) {
            uint32_t b0, b1, b2, b3;
            ldsm4(b0, b1, b2, b3, ps + cx.bBase[g] + ((cb ^ cx.bXor[g]) << 4));
            mma16816(acc[0][2 * g],     a0, b0, b2);
            mma16816(acc[0][2 * g + 1], a0, b1, b3);
            mma16816(acc[1][2 * g],     a1, b0, b2);
            mma16816(acc[1][2 * g + 1], a1, b1, b3);
        }
    }
}

// shared loader/mainloop body
#define GEMM_MAINLOOP(Aptr, Bptr, Kv)                                                  \
    uint32_t so[6];                                                                    \
    const uint16_t* gp[6];                                                             \
    _Pragma("unroll")                                                                  \
    for (int j = 0; j < 6; j++) {                                                      \
        int id = tid + j * 512;                                                        \
        int q; const uint16_t* base; uint32_t off;                                     \
        if (id < 1024) { q = id;        base = (Aptr); off = 0; }                      \
        else           { q = id - 1024; base = (Bptr); off = 16384; }                  \
        int r = q >> 3, c = q & 7;                                                     \
        gp[j] = base + (size_t)r * (Kv) + c * 8;                                       \
        so[j] = off + r * 128 + ((uint32_t)(c ^ (r & 7)) << 4);                        \
    }                                                                                  \
    MmaCtx cx; mma_ctx_init(cx, lane, wm, wn);                                         \
    float acc[2][8][4];                                                                \
    _Pragma("unroll")                                                                  \
    for (int i = 0; i < 2; i++)                                                        \
        _Pragma("unroll")                                                              \
        for (int j = 0; j < 8; j++)                                                    \
            _Pragma("unroll")                                                          \
            for (int q = 0; q < 4; q++) acc[i][j][q] = 0.f;                            \
    const int nk = (Kv) >> 6;                                                          \
    _Pragma("unroll")                                                                  \
    for (int j = 0; j < 6; j++) cpasync16(sbase + so[j], gp[j]);                       \
    cp_commit();                                                                       \
    _Pragma("unroll")                                                                  \
    for (int j = 0; j < 6; j++) { gp[j] += 64; cpasync16(sbase + STG + so[j], gp[j]); }\
    cp_commit();                                                                       \
    for (int it = 0; it < nk; it++) {                                                  \
        if (it < nk - 1) cp_wait<1>(); else cp_wait<0>();                              \
        __syncthreads();                                                               \
        if (it + 2 < nk) {                                                             \
            const uint32_t dst = sbase + (uint32_t)((it + 2) % 3) * STG;               \
            _Pragma("unroll")                                                          \
            for (int j = 0; j < 6; j++) { gp[j] += 64; cpasync16(dst + so[j], gp[j]); }\
            cp_commit();                                                               \
        }                                                                              \
        mma_tile(cx, sbase + (uint32_t)(it % 3) * STG, acc);                           \
    }

// ================= merged QKV GEMM (plain fp16, N=3072, dispatch epilogue) =================
__global__ void __launch_bounds__(512, 1)
gemm_qkv(const uint16_t* __restrict__ A, const uint16_t* __restrict__ Bt,
         const float* __restrict__ bpv, const float* __restrict__ bk,
         const float* __restrict__ bkv,
         float* __restrict__ pv, float* __restrict__ kc, float* __restrict__ ks,
         float* __restrict__ kv)
{
    extern __shared__ __align__(16) char smem_[];
    const uint32_t sbase = (s2u(smem_) + 1023u) & ~1023u;
    const int tid = threadIdx.x, lane = tid & 31, warp = tid >> 5;
    const int wm = warp >> 2, wn = warp & 3;
    const int brow = blockIdx.y, bcol = blockIdx.x;
    const int K = DD;

    const uint16_t* Ag = A  + (size_t)brow * 128 * K;
    const uint16_t* Bg = Bt + (size_t)bcol * 256 * K;
    GEMM_MAINLOOP(Ag, Bg, K)

    const int sect = bcol >> 2;                 // 0: pv, 1: key, 2: kv
    const float* bp = (sect == 0) ? bpv : (sect == 1) ? bk : bkv;
    float* Cm = (sect == 0) ? pv : kv;
    const int r0 = brow * 128 + wm * 32 + (lane >> 2);
    const int c0 = (bcol & 3) * 256 + wn * 64 + (lane & 3) * 2;
#pragma unroll
    for (int mi = 0; mi < 2; mi++) {
#pragma unroll
        for (int nj = 0; nj < 8; nj++) {
            const int col = c0 + nj * 8;
            const float bv0 = bp[col], bv1 = bp[col + 1];
#pragma unroll
            for (int h = 0; h < 2; h++) {
                const int row = r0 + mi * 16 + h * 8;
                const size_t base = (size_t)row * DD + col;
                float v0 = acc[mi][nj][2 * h]     + bv0;
                float v1 = acc[mi][nj][2 * h + 1] + bv1;
                if (sect == 1) {
                    float s0, cc0, s1, cc1;
                    __sincosf(tanh_fast(v0) * 3.14159265358979323846f, &s0, &cc0);
                    __sincosf(tanh_fast(v1) * 3.14159265358979323846f, &s1, &cc1);
                    *reinterpret_cast<float2*>(kc + base) = make_float2(cc0, cc1);
                    *reinterpret_cast<float2*>(ks + base) = make_float2(s0, s1);
                } else {
                    *reinterpret_cast<float2*>(Cm + base) = make_float2(v0, v1);
                }
            }
        }
    }
}

// ================= generic GEMM (gelu / out epilogues) =================
template <int MODE>
__global__ void __launch_bounds__(512, 1)
gemm_mma(const uint16_t* __restrict__ A, const uint16_t* __restrict__ Bt,
         const float* __restrict__ bias, float* __restrict__ C,
         const float* __restrict__ addsrc, int N, int K)
{
    extern __shared__ __align__(16) char smem_[];
    const uint32_t sbase = (s2u(smem_) + 1023u) & ~1023u;
    const int tid = threadIdx.x, lane = tid & 31, warp = tid >> 5;
    const int wm = warp >> 2, wn = warp & 3;
    const int brow = blockIdx.y, bcol = blockIdx.x;

    const uint16_t* Ag = A  + (size_t)brow * 128 * K;
    const uint16_t* Bg = Bt + (size_t)bcol * 256 * K;
    GEMM_MAINLOOP(Ag, Bg, K)

    const int r0 = brow * 128 + wm * 32 + (lane >> 2);
    const int c0 = bcol * 256 + wn * 64 + (lane & 3) * 2;
#pragma unroll
    for (int mi = 0; mi < 2; mi++) {
#pragma unroll
        for (int nj = 0; nj < 8; nj++) {
            const int col = c0 + nj * 8;
            const float bv0 = bias[col], bv1 = bias[col + 1];
#pragma unroll
            for (int h = 0; h < 2; h++) {
                const int row = r0 + mi * 16 + h * 8;
                const size_t base = (size_t)row * N + col;
                float v0 = acc[mi][nj][2 * h]     + bv0;
                float v1 = acc[mi][nj][2 * h + 1] + bv1;
                if (MODE == EP_GELU) {
                    v0 = 0.5f * v0 * (1.f + erff(v0 * 0.70710678118654752f));
                    v1 = 0.5f * v1 * (1.f + erff(v1 * 0.70710678118654752f));
                }
                if (MODE == EP_OUT) { v0 += addsrc[base]; v1 += addsrc[base + 1]; }
                *reinterpret_cast<float2*>(C + base) = make_float2(v0, v1);
            }
        }
    }
}

// ================= gate GEMM: A = [x2 | shift1(x2)] virtual concat (plain fp16) =================
__global__ void __launch_bounds__(512, 1)
gemm_gate(const uint16_t* __restrict__ X2, const uint16_t* __restrict__ Bt,
          const float* __restrict__ bias, float* __restrict__ C)
{
    extern __shared__ __align__(16) char smem_[];
    const uint32_t sbase = (s2u(smem_) + 1023u) & ~1023u;
    const int tid = threadIdx.x, lane = tid & 31, warp = tid >> 5;
    const int wm = warp >> 2, wn = warp & 3;
    const int brow = blockIdx.y, bcol = blockIdx.x;
    const int K = 2 * DD;        // virtual 2048
    const int KH = DD;           // 1024
    const int nkh = 16;

    uint32_t soA[2];
    const uint16_t *aCur[2], *aPrev[2];
    bool validA[2];
#pragma unroll
    for (int j = 0; j < 2; j++) {
        int q = tid + j * 512;
        int r = q >> 3, c = q & 7;
        int R = brow * 128 + r;
        aCur[j]  = X2 + (size_t)R * KH + c * 8;
        aPrev[j] = X2 + ((size_t)R - 1) * KH + c * 8;
        validA[j] = (R & (LL - 1)) != 0;
        soA[j] = r * 128 + ((uint32_t)(c ^ (r & 7)) << 4);
    }
    uint32_t soB[4];
    const uint16_t* bgp[4];
#pragma unroll
    for (int j = 0; j < 4; j++) {
        int q = tid + j * 512;
        int r = q >> 3, c = q & 7;
        bgp[j] = Bt + (size_t)(bcol * 256 + r) * K + c * 8;
        soB[j] = 16384 + r * 128 + ((uint32_t)(c ^ (r & 7)) << 4);
    }
    MmaCtx cx; mma_ctx_init(cx, lane, wm, wn);

    float acc[2][8][4];
#pragma unroll
    for (int i = 0; i < 2; i++)
#pragma unroll
        for (int j = 0; j < 8; j++)
#pragma unroll
            for (int q = 0; q < 4; q++) acc[i][j][q] = 0.f;

    const int nk = K >> 6;   // 32
#define GATE_LOAD(ITP, DST)                                                           \
    do {                                                                              \
        int itp_ = (ITP);                                                             \
        if (itp_ < nkh) {                                                             \
            cpasync16((DST) + soA[0], aCur[0] + itp_ * 64);                           \
            cpasync16((DST) + soA[1], aCur[1] + itp_ * 64);                           \
        } else {                                                                      \
            if (validA[0]) cpasync16((DST) + soA[0], aPrev[0] + (itp_ - nkh) * 64);   \
            else sts_zero16((DST) + soA[0]);                                          \
            if (validA[1]) cpasync16((DST) + soA[1], aPrev[1] + (itp_ - nkh) * 64);   \
            else sts_zero16((DST) + soA[1]);                                          \
        }                                                                             \
        cpasync16((DST) + soB[0], bgp[0] + itp_ * 64);                                \
        cpasync16((DST) + soB[1], bgp[1] + itp_ * 64);                                \
        cpasync16((DST) + soB[2], bgp[2] + itp_ * 64);                                \
        cpasync16((DST) + soB[3], bgp[3] + itp_ * 64);                                \
        cp_commit();                                                                  \
    } while (0)

    GATE_LOAD(0, sbase);
    GATE_LOAD(1, sbase + STG);

    for (int it = 0; it < nk; it++) {
        if (it < nk - 1) cp_wait<1>(); else cp_wait<0>();
        __syncthreads();
        if (it + 2 < nk) {
            const uint32_t dst = sbase + (uint32_t)((it + 2) % 3) * STG;
            GATE_LOAD(it + 2, dst);
        }
        mma_tile(cx, sbase + (uint32_t)(it % 3) * STG, acc);
    }
#undef GATE_LOAD

    const int r0 = brow * 128 + wm * 32 + (lane >> 2);
    const int c0 = bcol * 256 + wn * 64 + (lane & 3) * 2;
#pragma unroll
    for (int mi = 0; mi < 2; mi++) {
#pragma unroll
        for (int nj = 0; nj < 8; nj++) {
            const int col = c0 + nj * 8;
            const float bv0 = bias[col], bv1 = bias[col + 1];
#pragma unroll
            for (int h = 0; h < 2; h++) {
                const int row = r0 + mi * 16 + h * 8;
                const size_t base = (size_t)row * DD + col;
                float v0 = acc[mi][nj][2 * h]     + bv0;
                float v1 = acc[mi][nj][2 * h + 1] + bv1;
                v0 = 0.5f * v0 * (1.f + erff(v0 * 0.70710678118654752f));
                v1 = 0.5f * v1 * (1.f + erff(v1 * 0.70710678118654752f));
                *reinterpret_cast<float2*>(C + base) = make_float2(v0, v1);
            }
        }
    }
}

// ---------------- conversion kernels ----------------
// fp32 -> plain fp16 cast
__global__ void k_cvtA2(const float* __restrict__ in, __half* __restrict__ out)
{
    size_t t = (size_t)blockIdx.x * 256 + threadIdx.x;   // one float4 -> 4 halfs
    float4 v = reinterpret_cast<const float4*>(in)[t];
    __align__(8) __half o[4];
    o[0] = __float2half(v.x); o[1] = __float2half(v.y);
    o[2] = __float2half(v.z); o[3] = __float2half(v.w);
    reinterpret_cast<uint2*>(out)[t] = *reinterpret_cast<const uint2*>(o);
}

// W[K,N] fp32 -> fp16 [N][K] transposed
__global__ void k_cvtB2(const float* __restrict__ W, __half* __restrict__ out, int K, int N)
{
    __shared__ float ts[32][33];
    const int k0 = blockIdx.y * 32, n0 = blockIdx.x * 32;
    const int tx = threadIdx.x, ty = threadIdx.y;
#pragma unroll
    for (int i = 0; i < 4; i++)
        ts[ty + i * 8][tx] = W[(size_t)(k0 + ty + i * 8) * N + n0 + tx];
    __syncthreads();
#pragma unroll
    for (int i = 0; i < 4; i++) {
        int n = ty + i * 8;
        out[(size_t)(n0 + n) * K + k0 + tx] = __float2half(ts[tx][n]);
    }
}

// 3 square weights -> packed [pv|key|kv] fp16 buffer, one launch
__global__ void k_cvtB2x3(const float* __restrict__ W0, const float* __restrict__ W1,
                          const float* __restrict__ W2, __half* __restrict__ out)
{
    __shared__ float ts[32][33];
    const float* W = (blockIdx.z == 0) ? W0 : (blockIdx.z == 1) ? W1 : W2;
    __half* o = out + (size_t)blockIdx.z * DD * DD;
    const int k0 = blockIdx.y * 32, n0 = blockIdx.x * 32;
    const int tx = threadIdx.x, ty = threadIdx.y;
#pragma unroll
    for (int i = 0; i < 4; i++)
        ts[ty + i * 8][tx] = W[(size_t)(k0 + ty + i * 8) * DD + n0 + tx];
    __syncthreads();
#pragma unroll
    for (int i = 0; i < 4; i++) {
        int n = ty + i * 8;
        o[(size_t)(n0 + n) * DD + k0 + tx] = __float2half(ts[tx][n]);
    }
}

__global__ void k_sincos(const float* __restrict__ pp)
{
    size_t t = (size_t)blockIdx.x * 256 + threadIdx.x;
    float sn, cs;
    __sincosf(pp[t], &sn, &cs);
    g_pc[t] = cs; g_ps[t] = sn;
}

// ---------------- value_gates ----------------
__global__ void k_vg(const float* __restrict__ Wg2, const float* __restrict__ bg2)
{
    const int warp = threadIdx.x >> 5, lane = threadIdx.x & 31;
    const int row = blockIdx.x * 8 + warp;
    const float4* g = reinterpret_cast<const float4*>(g_gh + (size_t)row * DD);
    const float4* w = reinterpret_cast<const float4*>(Wg2);
    float s = 0.f;
#pragma unroll
    for (int i = 0; i < 8; i++) {
        float4 a = g[lane + i * 32], b = w[lane + i * 32];
        s += a.x * b.x + a.y * b.y + a.z * b.z + a.w * b.w;
    }
#pragma unroll
    for (int o = 16; o > 0; o >>= 1) s += __shfl_xor_sync(0xFFFFFFFFu, s, o);
    if (lane == 0) g_vg[row] = 1.f / (1.f + expf(-(s + bg2[0])));
}

// ---------------- blend weights ----------------
__global__ void k_bw(const float* __restrict__ Wb2, const float* __restrict__ bb2)
{
    const int warp = threadIdx.x >> 5, lane = threadIdx.x & 31;
    const int row = blockIdx.x * 8 + warp;
    const float4* hv = reinterpret_cast<const float4*>(g_bh + (size_t)row * (DD / 2));
    const float4* wv = reinterpret_cast<const float4*>(Wb2);
    float s0 = 0.f, s1 = 0.f;
#pragma unroll
    for (int i = 0; i < 4; i++) {
        int idx = lane + i * 32;
        float4 a = hv[idx];
        float4 w0 = wv[2 * idx], w1 = wv[2 * idx + 1];
        s0 += a.x * w0.x + a.y * w0.z + a.z * w1.x + a.w * w1.z;
        s1 += a.x * w0.y + a.y * w0.w + a.z * w1.y + a.w * w1.w;
    }
#pragma unroll
    for (int o = 16; o > 0; o >>= 1) {
        s0 += __shfl_xor_sync(0xFFFFFFFFu, s0, o);
        s1 += __shfl_xor_sync(0xFFFFFFFFu, s1, o);
    }
    if (lane == 0) {
        float a0 = s0 + bb2[0], a1 = s1 + bb2[1];
        float m = fmaxf(a0, a1);
        float e0 = expf(a0 - m), e1 = expf(a1 - m);
        float inv = 1.f / (e0 + e1);
        g_bw[2 * row]     = e0 * inv;
        g_bw[2 * row + 1] = e1 * inv;
    }
}

// ---------------- per-batch gate scan ----------------
__global__ void k_gatescan()
{
    int b = blockIdx.x;
    __shared__ float sh[1024];
    float carry = 0.f;
    for (int t0 = 0; t0 < LL; t0 += 1024) {
        int l = t0 + threadIdx.x;
        sh[threadIdx.x] = g_vg[b * LL + l];
        __syncthreads();
        for (int off = 1; off < 1024; off <<= 1) {
            float tv = (threadIdx.x >= off) ? sh[threadIdx.x - off] : 0.f;
            __syncthreads();
            sh[threadIdx.x] += tv;
            __syncthreads();
        }
        float inc = sh[threadIdx.x] + carry;
        float tot = sh[1023];
        g_gcs[b * LL + l] = sqrtf(fmaxf(inc, 1.f));
        carry += tot;
        __syncthreads();
    }
}

// ---------------- scan pass T ----------------
__global__ void k_scanT()
{
    const int d = blockIdx.x * 256 + threadIdx.x;
    const int c = blockIdx.y, b = blockIdx.z;
    const int l0 = c * TCHUNK;
    float spc = 0.f, sps = 0.f, skc = 0.f, sks = 0.f;
    float kcp, ksp;
    if (l0 == 0) { kcp = 0.f; ksp = 0.f; }
    else {
        size_t pidx = (size_t)(b * LL + l0 - 1) * DD + d;
        kcp = g_kc[pidx]; ksp = g_ks[pidx];
    }
    for (int t = 0; t < TCHUNK; t++) {
        const int l = l0 + t;
        const int rowi = b * LL + l;
        const size_t idx = (size_t)rowi * DD + d;
        const size_t pidx = (size_t)l * DD + d;
        const float pvv = g_pv[idx];
        spc = fmaf(g_pc[pidx], pvv, spc);
        sps = fmaf(g_ps[pidx], pvv, sps);
        const float kvg = g_kv[idx] * g_vg[rowi];
        skc = fmaf(kcp, kvg, skc);
        sks = fmaf(ksp, kvg, sks);
        kcp = g_kc[idx];
        ksp = g_ks[idx];
    }
    size_t tix = (size_t)(b * NCHUNK + c) * DD + d;
    g_tot[tix]            = spc;
    g_tot[TOTN + tix]     = sps;
    g_tot[2 * TOTN + tix] = skc;
    g_tot[3 * TOTN + tix] = sks;
}

// ---------------- scan pass C ----------------
__global__ void k_scanC()
{
    const int d = blockIdx.x * 256 + threadIdx.x;
    const int c = blockIdx.y, b = blockIdx.z;
    const int l0 = c * TCHUNK;
    float opc = 0.f, ops = 0.f, okc = 0.f, oks = 0.f;
    for (int cc = 0; cc < c; cc++) {
        size_t tix = (size_t)(b * NCHUNK + cc) * DD + d;
        opc += g_tot[tix];
        ops += g_tot[TOTN + tix];
        okc += g_tot[2 * TOTN + tix];
        oks += g_tot[3 * TOTN + tix];
    }
    const float invSqrtD = 0.03125f;
    float spc = 0.f, sps = 0.f, skc = 0.f, sks = 0.f;
    float kcp, ksp;
    if (l0 == 0) { kcp = 0.f; ksp = 0.f; }
    else {
        size_t pidx = (size_t)(b * LL + l0 - 1) * DD + d;
        kcp = g_kc[pidx]; ksp = g_ks[pidx];
    }
    for (int t = 0; t < TCHUNK; t++) {
        const int l = l0 + t;
        const int rowi = b * LL + l;
        const size_t idx = (size_t)rowi * DD + d;
        const size_t pidx = (size_t)l * DD + d;
        const float pvv = g_pv[idx];
        const float cs = g_pc[pidx], sn = g_ps[pidx];
        spc = fmaf(cs, pvv, spc);
        sps = fmaf(sn, pvv, sps);
        const float kvg = g_kv[idx] * g_vg[rowi];
        const float kcc = g_kc[idx], kss = g_ks[idx];
        skc = fmaf(kcp, kvg, skc);
        sks = fmaf(ksp, kvg, sks);
        kcp = kcc; ksp = kss;
        const float pos_ret = (cs * (spc + opc) + sn * (sps + ops)) * invSqrtD;
        const float kv_ret  = (kcc * (skc + okc) + kss * (sks + oks)) / g_gcs[rowi] * invSqrtD;
        g_blend[idx] = g_bw[2 * rowi] * pos_ret + g_bw[2 * rowi + 1] * kv_ret;
    }
}

// ---------------- LayerNorm fused with fp16 cast output ----------------
__global__ void k_ln(const float* __restrict__ lng, const float* __restrict__ lnb,
                     __half* __restrict__ out2)
{
    int row = blockIdx.x, tid = threadIdx.x;
    float v[4], s = 0.f, sq = 0.f;
#pragma unroll
    for (int i = 0; i < 4; i++) {
        v[i] = g_blend[(size_t)row * DD + tid + i * 256];
        s += v[i]; sq += v[i] * v[i];
    }
    __shared__ float shs[256], shq[256];
    shs[tid] = s; shq[tid] = sq; __syncthreads();
    for (int o = 128; o > 0; o >>= 1) {
        if (tid < o) { shs[tid] += shs[tid + o]; shq[tid] += shq[tid + o]; }
        __syncthreads();
    }
    __shared__ float smu, srstd;
    if (tid == 0) {
        float mu  = shs[0] * (1.f / DD);
        float var = shq[0] * (1.f / DD) - mu * mu;
        smu = mu;
        srstd = rsqrtf(var + 1e-5f);
    }
    __syncthreads();
#pragma unroll
    for (int i = 0; i < 4; i++) {
        int dd = tid + i * 256;
        float t = (v[i] - smu) * srstd * lng[dd] + lnb[dd];
        out2[(size_t)row * DD + dd] = __float2half(t);
    }
}

// ---------------- launch ----------------
extern "C" void kernel_launch(void* const* d_in, const int* in_sizes, int n_in,
                              void* d_out, int out_size)
{
    const float* x   = (const float*)d_in[0];
    const float* pp  = (const float*)d_in[1];
    const float* Wpv = (const float*)d_in[2];
    const float* bpv = (const float*)d_in[3];
    const float* Wk  = (const float*)d_in[4];
    const float* bk  = (const float*)d_in[5];
    const float* Wkv = (const float*)d_in[6];
    const float* bkv = (const float*)d_in[7];
    const float* Wg1 = (const float*)d_in[8];
    const float* bg1 = (const float*)d_in[9];
    const float* Wg2 = (const float*)d_in[10];
    const float* bg2 = (const float*)d_in[11];
    const float* Wb1 = (const float*)d_in[12];
    const float* bb1 = (const float*)d_in[13];
    const float* Wb2 = (const float*)d_in[14];
    const float* bb2 = (const float*)d_in[15];
    const float* lng = (const float*)d_in[16];
    const float* lnb = (const float*)d_in[17];
    const float* Wo  = (const float*)d_in[18];
    const float* bo  = (const float*)d_in[19];
    float* out = (float*)d_out;

    float *pv, *kc, *ks, *kv, *gh, *bh;
    cudaGetSymbolAddress((void**)&pv, g_pv);
    cudaGetSymbolAddress((void**)&kc, g_kc);
    cudaGetSymbolAddress((void**)&ks, g_ks);
    cudaGetSymbolAddress((void**)&kv, g_kv);
    cudaGetSymbolAddress((void**)&gh, g_gh);
    cudaGetSymbolAddress((void**)&bh, g_bh);

    __half *x2, *ln2, *Wqkv2, *Wg12, *Wb12, *Wo2;
    cudaGetSymbolAddress((void**)&x2,    g_x2);
    cudaGetSymbolAddress((void**)&ln2,   g_ln2);
    cudaGetSymbolAddress((void**)&Wqkv2, g_Wqkv2);
    cudaGetSymbolAddress((void**)&Wg12,  g_Wg12);
    cudaGetSymbolAddress((void**)&Wb12,  g_Wb12);
    cudaGetSymbolAddress((void**)&Wo2,   g_Wo2);

    cudaFuncSetAttribute((const void*)gemm_qkv,          cudaFuncAttributeMaxDynamicSharedMemorySize, GEMM_SMEM);
    cudaFuncSetAttribute((const void*)gemm_mma<EP_GELU>, cudaFuncAttributeMaxDynamicSharedMemorySize, GEMM_SMEM);
    cudaFuncSetAttribute((const void*)gemm_mma<EP_OUT >, cudaFuncAttributeMaxDynamicSharedMemorySize, GEMM_SMEM);
    cudaFuncSetAttribute((const void*)gemm_gate,         cudaFuncAttributeMaxDynamicSharedMemorySize, GEMM_SMEM);

    // 0-1: conversions (activations, packed qkv weights)
    k_cvtA2<<<(MM * DD / 4) / 256, 256>>>(x, x2);
    k_cvtB2x3<<<dim3(DD / 32, DD / 32, 3), dim3(32, 8)>>>(Wpv, Wk, Wkv, Wqkv2);
    // 2: merged QKV GEMM (plain fp16, N=3072, K=1024, epilogue dispatch)
    gemm_qkv<<<dim3(12, MM / 128), 512, GEMM_SMEM>>>(
        (const uint16_t*)x2, (const uint16_t*)Wqkv2, bpv, bk, bkv, pv, kc, ks, kv);
    // 3-4: gate path (virtual concat, K=2048)
    k_cvtB2<<<dim3(DD / 32, 2 * DD / 32), dim3(32, 8)>>>(Wg1, Wg12, 2 * DD, DD);
    gemm_gate<<<dim3(4, MM / 128), 512, GEMM_SMEM>>>((const uint16_t*)x2, (const uint16_t*)Wg12, bg1, gh);
    // 5-6: blend hidden (K=1024)
    k_cvtB2<<<dim3((DD / 2) / 32, DD / 32), dim3(32, 8)>>>(Wb1, Wb12, DD, DD / 2);
    gemm_mma<EP_GELU><<<dim3(2, MM / 128), 512, GEMM_SMEM>>>(
        (const uint16_t*)x2, (const uint16_t*)Wb12, bb1, bh, nullptr, DD / 2, DD);
    // 7: pos phase cos/sin (fast approx)
    k_sincos<<<(LL * DD) / 256, 256>>>(pp);
    // 8-10: gates / blend softmax / gate cumsum
    k_vg<<<MM / 8, 256>>>(Wg2, bg2);
    k_bw<<<MM / 8, 256>>>(Wb2, bb2);
    k_gatescan<<<BBATCH, 1024>>>();
    // 11-12: scans
    dim3 gscan(DD / 256, NCHUNK, BBATCH);
    k_scanT<<<gscan, 256>>>();
    k_scanC<<<gscan, 256>>>();
    // 13: LayerNorm (fused fp16 cast)
    k_ln<<<MM, 256>>>(lng, lnb, ln2);
    // 14-15: output path (K=1024, +residual)
    k_cvtB2<<<dim3(DD / 32, DD / 32), dim3(32, 8)>>>(Wo, Wo2, DD, DD);
    gemm_mma<EP_OUT><<<dim3(4, MM / 128), 512, GEMM_SMEM>>>(
        (const uint16_t*)ln2, (const uint16_t*)Wo2, bo, out, x, DD, DD);
}

// round 14
// speedup vs baseline: 2.0147x; 1.0561x over previous
#include <cuda_runtime.h>
#include <cuda_fp16.h>
#include <math.h>
#include <stdint.h>

// ---------------- problem constants ----------------
#define BBATCH 4
#define LL 4096
#define DD 1024
#define MM (BBATCH * LL)          // 16384 rows
#define NCHUNK 64
#define TCHUNK (LL / NCHUNK)      // 64
#define TOTN (BBATCH * NCHUNK * DD)

// ---------------- scratch ----------------
__device__ __half  g_pvh[(size_t)MM * DD];
__device__ __half  g_kvh[(size_t)MM * DD];
__device__ __half2 g_kcs[(size_t)MM * DD];       // (cos, sin) packed
__device__ __half  g_gh [(size_t)MM * DD];
__device__ __half  g_bh [(size_t)MM * (DD / 2)];
__device__ float g_vg[MM];
__device__ float g_gcs[MM];
__device__ float g_bw[MM * 2];
__device__ float g_tot[4 * TOTN];
__device__ float g_blend[(size_t)MM * DD];

// ---------------- plain fp16 operand scratch ----------------
__device__ __half g_x2   [(size_t)MM * DD];
__device__ __half g_ln2  [(size_t)MM * DD];
__device__ __half g_Wqkv2[(size_t)3 * DD * DD];
__device__ __half g_Wg12 [(size_t)DD * 2 * DD];
__device__ __half g_Wb12 [(size_t)(DD / 2) * DD];
__device__ __half g_Wo2  [(size_t)DD * DD];

// ================= PTX helpers (family-safe) =================
__device__ __forceinline__ uint32_t s2u(const void* p) {
    return (uint32_t)__cvta_generic_to_shared(p);
}
__device__ __forceinline__ void ldsm4(uint32_t& r0, uint32_t& r1, uint32_t& r2, uint32_t& r3, uint32_t a) {
    asm volatile("ldmatrix.sync.aligned.m8n8.x4.shared.b16 {%0,%1,%2,%3}, [%4];"
                 : "=r"(r0), "=r"(r1), "=r"(r2), "=r"(r3) : "r"(a));
}
__device__ __forceinline__ void mma16816(float* d, const uint32_t* a, uint32_t b0, uint32_t b1) {
    asm volatile("mma.sync.aligned.m16n8k16.row.col.f32.f16.f16.f32 "
                 "{%0,%1,%2,%3},{%4,%5,%6,%7},{%8,%9},{%0,%1,%2,%3};"
                 : "+f"(d[0]), "+f"(d[1]), "+f"(d[2]), "+f"(d[3])
                 : "r"(a[0]), "r"(a[1]), "r"(a[2]), "r"(a[3]), "r"(b0), "r"(b1));
}
__device__ __forceinline__ void cpasync16(uint32_t s, const void* g) {
    asm volatile("cp.async.cg.shared.global [%0], [%1], 16;" :: "r"(s), "l"(g));
}
__device__ __forceinline__ void sts_zero16(uint32_t a) {
    asm volatile("st.shared.v4.b32 [%0], {%1,%1,%1,%1};" :: "r"(a), "r"(0) : "memory");
}
__device__ __forceinline__ void cp_commit() { asm volatile("cp.async.commit_group;"); }
template <int n> __device__ __forceinline__ void cp_wait() {
    asm volatile("cp.async.wait_group %0;" :: "n"(n));
}
__device__ __forceinline__ float tanh_fast(float x) {
    float y;
    asm("tanh.approx.f32 %0, %1;" : "=f"(y) : "f"(x));
    return y;
}

// ================= GEMM core (512 thr, 16 warps 4x4, warp tile 32x64) =================
constexpr int EP_GELU = 2;
constexpr int EP_OUT  = 3;

#define STG 49152
#define GEMM_SMEM (1024 + 3 * STG)

struct MmaCtx {
    uint32_t aBase[2]; int aXor[2];
    uint32_t bBase[4]; int bXor[4];
    int chi;
};
__device__ __forceinline__ void mma_ctx_init(MmaCtx& cx, int lane, int wm, int wn) {
    const int mat = lane >> 3, mr = lane & 7;
    cx.chi = mat >> 1;
#pragma unroll
    for (int mi = 0; mi < 2; mi++) {
        int row = wm * 32 + mi * 16 + mr + (mat & 1) * 8;
        cx.aBase[mi] = row * 128; cx.aXor[mi] = row & 7;
    }
#pragma unroll
    for (int g = 0; g < 4; g++) {
        int row = wn * 64 + g * 16 + mr + (mat & 1) * 8;
        cx.bBase[g] = 16384 + row * 128; cx.bXor[g] = row & 7;
    }
}
__device__ __forceinline__ void mma_tile(const MmaCtx& cx, uint32_t ps, float acc[2][8][4]) {
#pragma unroll
    for (int kk = 0; kk < 4; kk++) {
        const int cb = kk * 2 + cx.chi;
        uint32_t a0[4], a1[4];
        ldsm4(a0[0], a0[1], a0[2], a0[3], ps + cx.aBase[0] + ((cb ^ cx.aXor[0]) << 4));
        ldsm4(a1[0], a1[1], a1[2], a1[3], ps + cx.aBase[1] + ((cb ^ cx.aXor[1]) << 4));
#pragma unroll
        for (int g = 0; g < 4; g++) {
            uint32_t b0, b1, b2, b3;
            ldsm4(b0, b1, b2, b3, ps + cx.bBase[g] + ((cb ^ cx.bXor[g]) << 4));
            mma16816(acc[0][2 * g],     a0, b0, b2);
            mma16816(acc[0][2 * g + 1], a0, b1, b3);
            mma16816(acc[1][2 * g],     a1, b0, b2);
            mma16816(acc[1][2 * g + 1], a1, b1, b3);
        }
    }
}

#define GEMM_MAINLOOP(Aptr, Bptr, Kv)                                                  \
    uint32_t so[6];                                                                    \
    const uint16_t* gp[6];                                                             \
    _Pragma("unroll")                                                                  \
    for (int j = 0; j < 6; j++) {                                                      \
        int id = tid + j * 512;                                                        \
        int q; const uint16_t* base; uint32_t off;                                     \
        if (id < 1024) { q = id;        base = (Aptr); off = 0; }                      \
        else           { q = id - 1024; base = (Bptr); off = 16384; }                  \
        int r = q >> 3, c = q & 7;                                                     \
        gp[j] = base + (size_t)r * (Kv) + c * 8;                                       \
        so[j] = off + r * 128 + ((uint32_t)(c ^ (r & 7)) << 4);                        \
    }                                                                                  \
    MmaCtx cx; mma_ctx_init(cx, lane, wm, wn);                                         \
    float acc[2][8][4];                                                                \
    _Pragma("unroll")                                                                  \
    for (int i = 0; i < 2; i++)                                                        \
        _Pragma("unroll")                                                              \
        for (int j = 0; j < 8; j++)                                                    \
            _Pragma("unroll")                                                          \
            for (int q = 0; q < 4; q++) acc[i][j][q] = 0.f;                            \
    const int nk = (Kv) >> 6;                                                          \
    _Pragma("unroll")                                                                  \
    for (int j = 0; j < 6; j++) cpasync16(sbase + so[j], gp[j]);                       \
    cp_commit();                                                                       \
    _Pragma("unroll")                                                                  \
    for (int j = 0; j < 6; j++) { gp[j] += 64; cpasync16(sbase + STG + so[j], gp[j]); }\
    cp_commit();                                                                       \
    for (int it = 0; it < nk; it++) {                                                  \
        if (it < nk - 1) cp_wait<1>(); else cp_wait<0>();                              \
        __syncthreads();                                                               \
        if (it + 2 < nk) {                                                             \
            const uint32_t dst = sbase + (uint32_t)((it + 2) % 3) * STG;               \
            _Pragma("unroll")                                                          \
            for (int j = 0; j < 6; j++) { gp[j] += 64; cpasync16(dst + so[j], gp[j]); }\
            cp_commit();                                                               \
        }                                                                              \
        mma_tile(cx, sbase + (uint32_t)(it % 3) * STG, acc);                           \
    }

// ================= merged QKV GEMM (fp16, N=3072, fp16 outputs) =================
__global__ void __launch_bounds__(512, 1)
gemm_qkv(const uint16_t* __restrict__ A, const uint16_t* __restrict__ Bt,
         const float* __restrict__ bpv, const float* __restrict__ bk,
         const float* __restrict__ bkv,
         __half* __restrict__ pvh, __half2* __restrict__ kcs, __half* __restrict__ kvh)
{
    extern __shared__ __align__(16) char smem_[];
    const uint32_t sbase = (s2u(smem_) + 1023u) & ~1023u;
    const int tid = threadIdx.x, lane = tid & 31, warp = tid >> 5;
    const int wm = warp >> 2, wn = warp & 3;
    const int brow = blockIdx.y, bcol = blockIdx.x;
    const int K = DD;

    const uint16_t* Ag = A  + (size_t)brow * 128 * K;
    const uint16_t* Bg = Bt + (size_t)bcol * 256 * K;
    GEMM_MAINLOOP(Ag, Bg, K)

    const int sect = bcol >> 2;                 // 0: pv, 1: key, 2: kv
    const float* bp = (sect == 0) ? bpv : (sect == 1) ? bk : bkv;
    __half* Cm = (sect == 0) ? pvh : kvh;
    const int r0 = brow * 128 + wm * 32 + (lane >> 2);
    const int c0 = (bcol & 3) * 256 + wn * 64 + (lane & 3) * 2;
#pragma unroll
    for (int mi = 0; mi < 2; mi++) {
#pragma unroll
        for (int nj = 0; nj < 8; nj++) {
            const int col = c0 + nj * 8;
            const float bv0 = bp[col], bv1 = bp[col + 1];
#pragma unroll
            for (int h = 0; h < 2; h++) {
                const int row = r0 + mi * 16 + h * 8;
                const size_t base = (size_t)row * DD + col;
                float v0 = acc[mi][nj][2 * h]     + bv0;
                float v1 = acc[mi][nj][2 * h + 1] + bv1;
                if (sect == 1) {
                    float s0, cc0, s1, cc1;
                    __sincosf(tanh_fast(v0) * 3.14159265358979323846f, &s0, &cc0);
                    __sincosf(tanh_fast(v1) * 3.14159265358979323846f, &s1, &cc1);
                    __half2 h0 = __floats2half2_rn(cc0, s0);
                    __half2 h1 = __floats2half2_rn(cc1, s1);
                    uint2 pk;
                    pk.x = *reinterpret_cast<uint32_t*>(&h0);
                    pk.y = *reinterpret_cast<uint32_t*>(&h1);
                    *reinterpret_cast<uint2*>(kcs + base) = pk;
                } else {
                    *reinterpret_cast<__half2*>(Cm + base) = __floats2half2_rn(v0, v1);
                }
            }
        }
    }
}

// ================= generic GEMM =================
// EP_GELU: C is __half* ; EP_OUT: C is float* with residual addsrc
template <int MODE>
__global__ void __launch_bounds__(512, 1)
gemm_mma(const uint16_t* __restrict__ A, const uint16_t* __restrict__ Bt,
         const float* __restrict__ bias, void* __restrict__ Cv,
         const float* __restrict__ addsrc, int N, int K)
{
    extern __shared__ __align__(16) char smem_[];
    const uint32_t sbase = (s2u(smem_) + 1023u) & ~1023u;
    const int tid = threadIdx.x, lane = tid & 31, warp = tid >> 5;
    const int wm = warp >> 2, wn = warp & 3;
    const int brow = blockIdx.y, bcol = blockIdx.x;

    const uint16_t* Ag = A  + (size_t)brow * 128 * K;
    const uint16_t* Bg = Bt + (size_t)bcol * 256 * K;
    GEMM_MAINLOOP(Ag, Bg, K)

    const int r0 = brow * 128 + wm * 32 + (lane >> 2);
    const int c0 = bcol * 256 + wn * 64 + (lane & 3) * 2;
#pragma unroll
    for (int mi = 0; mi < 2; mi++) {
#pragma unroll
        for (int nj = 0; nj < 8; nj++) {
            const int col = c0 + nj * 8;
            const float bv0 = bias[col], bv1 = bias[col + 1];
#pragma unroll
            for (int h = 0; h < 2; h++) {
                const int row = r0 + mi * 16 + h * 8;
                const size_t base = (size_t)row * N + col;
                float v0 = acc[mi][nj][2 * h]     + bv0;
                float v1 = acc[mi][nj][2 * h + 1] + bv1;
                if (MODE == EP_GELU) {
                    v0 = 0.5f * v0 * (1.f + erff(v0 * 0.70710678118654752f));
                    v1 = 0.5f * v1 * (1.f + erff(v1 * 0.70710678118654752f));
                    *reinterpret_cast<__half2*>((__half*)Cv + base) = __floats2half2_rn(v0, v1);
                } else {
                    v0 += addsrc[base]; v1 += addsrc[base + 1];
                    *reinterpret_cast<float2*>((float*)Cv + base) = make_float2(v0, v1);
                }
            }
        }
    }
}

// ================= gate GEMM: A = [x2 | shift1(x2)] virtual concat, fp16 out =================
__global__ void __launch_bounds__(512, 1)
gemm_gate(const uint16_t* __restrict__ X2, const uint16_t* __restrict__ Bt,
          const float* __restrict__ bias, __half* __restrict__ C)
{
    extern __shared__ __align__(16) char smem_[];
    const uint32_t sbase = (s2u(smem_) + 1023u) & ~1023u;
    const int tid = threadIdx.x, lane = tid & 31, warp = tid >> 5;
    const int wm = warp >> 2, wn = warp & 3;
    const int brow = blockIdx.y, bcol = blockIdx.x;
    const int K = 2 * DD;
    const int KH = DD;
    const int nkh = 16;

    uint32_t soA[2];
    const uint16_t *aCur[2], *aPrev[2];
    bool validA[2];
#pragma unroll
    for (int j = 0; j < 2; j++) {
        int q = tid + j * 512;
        int r = q >> 3, c = q & 7;
        int R = brow * 128 + r;
        aCur[j]  = X2 + (size_t)R * KH + c * 8;
        aPrev[j] = X2 + ((size_t)R - 1) * KH + c * 8;
        validA[j] = (R & (LL - 1)) != 0;
        soA[j] = r * 128 + ((uint32_t)(c ^ (r & 7)) << 4);
    }
    uint32_t soB[4];
    const uint16_t* bgp[4];
#pragma unroll
    for (int j = 0; j < 4; j++) {
        int q = tid + j * 512;
        int r = q >> 3, c = q & 7;
        bgp[j] = Bt + (size_t)(bcol * 256 + r) * K + c * 8;
        soB[j] = 16384 + r * 128 + ((uint32_t)(c ^ (r & 7)) << 4);
    }
    MmaCtx cx; mma_ctx_init(cx, lane, wm, wn);

    float acc[2][8][4];
#pragma unroll
    for (int i = 0; i < 2; i++)
#pragma unroll
        for (int j = 0; j < 8; j++)
#pragma unroll
            for (int q = 0; q < 4; q++) acc[i][j][q] = 0.f;

    const int nk = K >> 6;   // 32
#define GATE_LOAD(ITP, DST)                                                           \
    do {                                                                              \
        int itp_ = (ITP);                                                             \
        if (itp_ < nkh) {                                                             \
            cpasync16((DST) + soA[0], aCur[0] + itp_ * 64);                           \
            cpasync16((DST) + soA[1], aCur[1] + itp_ * 64);                           \
        } else {                                                                      \
            if (validA[0]) cpasync16((DST) + soA[0], aPrev[0] + (itp_ - nkh) * 64);   \
            else sts_zero16((DST) + soA[0]);                                          \
            if (validA[1]) cpasync16((DST) + soA[1], aPrev[1] + (itp_ - nkh) * 64);   \
            else sts_zero16((DST) + soA[1]);                                          \
        }                                                                             \
        cpasync16((DST) + soB[0], bgp[0] + itp_ * 64);                                \
        cpasync16((DST) + soB[1], bgp[1] + itp_ * 64);                                \
        cpasync16((DST) + soB[2], bgp[2] + itp_ * 64);                                \
        cpasync16((DST) + soB[3], bgp[3] + itp_ * 64);                                \
        cp_commit();                                                                  \
    } while (0)

    GATE_LOAD(0, sbase);
    GATE_LOAD(1, sbase + STG);

    for (int it = 0; it < nk; it++) {
        if (it < nk - 1) cp_wait<1>(); else cp_wait<0>();
        __syncthreads();
        if (it + 2 < nk) {
            const uint32_t dst = sbase + (uint32_t)((it + 2) % 3) * STG;
            GATE_LOAD(it + 2, dst);
        }
        mma_tile(cx, sbase + (uint32_t)(it % 3) * STG, acc);
    }
#undef GATE_LOAD

    const int r0 = brow * 128 + wm * 32 + (lane >> 2);
    const int c0 = bcol * 256 + wn * 64 + (lane & 3) * 2;
#pragma unroll
    for (int mi = 0; mi < 2; mi++) {
#pragma unroll
        for (int nj = 0; nj < 8; nj++) {
            const int col = c0 + nj * 8;
            const float bv0 = bias[col], bv1 = bias[col + 1];
#pragma unroll
            for (int h = 0; h < 2; h++) {
                const int row = r0 + mi * 16 + h * 8;
                const size_t base = (size_t)row * DD + col;
                float v0 = acc[mi][nj][2 * h]     + bv0;
                float v1 = acc[mi][nj][2 * h + 1] + bv1;
                v0 = 0.5f * v0 * (1.f + erff(v0 * 0.70710678118654752f));
                v1 = 0.5f * v1 * (1.f + erff(v1 * 0.70710678118654752f));
                *reinterpret_cast<__half2*>(C + base) = __floats2half2_rn(v0, v1);
            }
        }
    }
}

// ---------------- conversion kernels ----------------
__global__ void k_cvtA2(const float* __restrict__ in, __half* __restrict__ out)
{
    size_t t = (size_t)blockIdx.x * 256 + threadIdx.x;
    float4 v = reinterpret_cast<const float4*>(in)[t];
    __align__(8) __half o[4];
    o[0] = __float2half(v.x); o[1] = __float2half(v.y);
    o[2] = __float2half(v.z); o[3] = __float2half(v.w);
    reinterpret_cast<uint2*>(out)[t] = *reinterpret_cast<const uint2*>(o);
}

__global__ void k_cvtB2(const float* __restrict__ W, __half* __restrict__ out, int K, int N)
{
    __shared__ float ts[32][33];
    const int k0 = blockIdx.y * 32, n0 = blockIdx.x * 32;
    const int tx = threadIdx.x, ty = threadIdx.y;
#pragma unroll
    for (int i = 0; i < 4; i++)
        ts[ty + i * 8][tx] = W[(size_t)(k0 + ty + i * 8) * N + n0 + tx];
    __syncthreads();
#pragma unroll
    for (int i = 0; i < 4; i++) {
        int n = ty + i * 8;
        out[(size_t)(n0 + n) * K + k0 + tx] = __float2half(ts[tx][n]);
    }
}

__global__ void k_cvtB2x3(const float* __restrict__ W0, const float* __restrict__ W1,
                          const float* __restrict__ W2, __half* __restrict__ out)
{
    __shared__ float ts[32][33];
    const float* W = (blockIdx.z == 0) ? W0 : (blockIdx.z == 1) ? W1 : W2;
    __half* o = out + (size_t)blockIdx.z * DD * DD;
    const int k0 = blockIdx.y * 32, n0 = blockIdx.x * 32;
    const int tx = threadIdx.x, ty = threadIdx.y;
#pragma unroll
    for (int i = 0; i < 4; i++)
        ts[ty + i * 8][tx] = W[(size_t)(k0 + ty + i * 8) * DD + n0 + tx];
    __syncthreads();
#pragma unroll
    for (int i = 0; i < 4; i++) {
        int n = ty + i * 8;
        o[(size_t)(n0 + n) * DD + k0 + tx] = __float2half(ts[tx][n]);
    }
}

// ---------------- fused value_gates + blend weights ----------------
__global__ void k_vgbw(const float* __restrict__ Wg2, const float* __restrict__ bg2,
                       const float* __restrict__ Wb2, const float* __restrict__ bb2)
{
    const int warp = threadIdx.x >> 5, lane = threadIdx.x & 31;
    const int bx = blockIdx.x;
    if (bx < MM / 8) {
        const int row = bx * 8 + warp;
        const uint4* g = reinterpret_cast<const uint4*>(g_gh + (size_t)row * DD);
        const float4* w = reinterpret_cast<const float4*>(Wg2);
        float s = 0.f;
#pragma unroll
        for (int i = 0; i < 4; i++) {
            int idx = lane + i * 32;
            uint4 hv = g[idx];
            const __half2* hp = reinterpret_cast<const __half2*>(&hv);
            float4 w0 = w[2 * idx], w1 = w[2 * idx + 1];
            float2 a0 = __half22float2(hp[0]);
            float2 a1 = __half22float2(hp[1]);
            float2 a2 = __half22float2(hp[2]);
            float2 a3 = __half22float2(hp[3]);
            s += a0.x * w0.x + a0.y * w0.y + a1.x * w0.z + a1.y * w0.w;
            s += a2.x * w1.x + a2.y * w1.y + a3.x * w1.z + a3.y * w1.w;
        }
#pragma unroll
        for (int o = 16; o > 0; o >>= 1) s += __shfl_xor_sync(0xFFFFFFFFu, s, o);
        if (lane == 0) g_vg[row] = 1.f / (1.f + expf(-(s + bg2[0])));
    } else {
        const int row = (bx - MM / 8) * 8 + warp;
        const uint4* hv4 = reinterpret_cast<const uint4*>(g_bh + (size_t)row * (DD / 2));
        const float4* wv = reinterpret_cast<const float4*>(Wb2);
        float s0 = 0.f, s1 = 0.f;
#pragma unroll
        for (int i = 0; i < 2; i++) {
            int idx = lane + i * 32;      // uint4 idx, covers bh[8*idx .. 8*idx+7]
            uint4 hv = hv4[idx];
            const __half2* hp = reinterpret_cast<const __half2*>(&hv);
#pragma unroll
            for (int j = 0; j < 4; j++) {
                float2 a = __half22float2(hp[j]);
                float4 wA = wv[4 * idx + j];   // rows 8idx+2j, 8idx+2j+1
                s0 += a.x * wA.x + a.y * wA.z;
                s1 += a.x * wA.y + a.y * wA.w;
            }
        }
#pragma unroll
        for (int o = 16; o > 0; o >>= 1) {
            s0 += __shfl_xor_sync(0xFFFFFFFFu, s0, o);
            s1 += __shfl_xor_sync(0xFFFFFFFFu, s1, o);
        }
        if (lane == 0) {
            float a0 = s0 + bb2[0], a1 = s1 + bb2[1];
            float m = fmaxf(a0, a1);
            float e0 = expf(a0 - m), e1 = expf(a1 - m);
            float inv = 1.f / (e0 + e1);
            g_bw[2 * row]     = e0 * inv;
            g_bw[2 * row + 1] = e1 * inv;
        }
    }
}

// ---------------- per-batch gate scan ----------------
__global__ void k_gatescan()
{
    int b = blockIdx.x;
    __shared__ float sh[1024];
    float carry = 0.f;
    for (int t0 = 0; t0 < LL; t0 += 1024) {
        int l = t0 + threadIdx.x;
        sh[threadIdx.x] = g_vg[b * LL + l];
        __syncthreads();
        for (int off = 1; off < 1024; off <<= 1) {
            float tv = (threadIdx.x >= off) ? sh[threadIdx.x - off] : 0.f;
            __syncthreads();
            sh[threadIdx.x] += tv;
            __syncthreads();
        }
        float inc = sh[threadIdx.x] + carry;
        float tot = sh[1023];
        g_gcs[b * LL + l] = sqrtf(fmaxf(inc, 1.f));
        carry += tot;
        __syncthreads();
    }
}

// ---------------- scan pass T (fp16 inputs, sincos recompute) ----------------
__global__ void k_scanT(const float* __restrict__ pp)
{
    const int d = blockIdx.x * 256 + threadIdx.x;
    const int c = blockIdx.y, b = blockIdx.z;
    const int l0 = c * TCHUNK;
    float spc = 0.f, sps = 0.f, skc = 0.f, sks = 0.f;
    float kcp, ksp;
    if (l0 == 0) { kcp = 0.f; ksp = 0.f; }
    else {
        __half2 kk = g_kcs[(size_t)(b * LL + l0 - 1) * DD + d];
        kcp = __low2float(kk); ksp = __high2float(kk);
    }
    for (int t = 0; t < TCHUNK; t++) {
        const int l = l0 + t;
        const int rowi = b * LL + l;
        const size_t idx = (size_t)rowi * DD + d;
        float sn, cs;
        __sincosf(pp[(size_t)l * DD + d], &sn, &cs);
        const float pvv = __half2float(g_pvh[idx]);
        spc = fmaf(cs, pvv, spc);
        sps = fmaf(sn, pvv, sps);
        const float kvg = __half2float(g_kvh[idx]) * g_vg[rowi];
        skc = fmaf(kcp, kvg, skc);
        sks = fmaf(ksp, kvg, sks);
        __half2 kk = g_kcs[idx];
        kcp = __low2float(kk); ksp = __high2float(kk);
    }
    size_t tix = (size_t)(b * NCHUNK + c) * DD + d;
    g_tot[tix]            = spc;
    g_tot[TOTN + tix]     = sps;
    g_tot[2 * TOTN + tix] = skc;
    g_tot[3 * TOTN + tix] = sks;
}

// ---------------- scan pass C ----------------
__global__ void k_scanC(const float* __restrict__ pp)
{
    const int d = blockIdx.x * 256 + threadIdx.x;
    const int c = blockIdx.y, b = blockIdx.z;
    const int l0 = c * TCHUNK;
    float opc = 0.f, ops = 0.f, okc = 0.f, oks = 0.f;
    for (int cc = 0; cc < c; cc++) {
        size_t tix = (size_t)(b * NCHUNK + cc) * DD + d;
        opc += g_tot[tix];
        ops += g_tot[TOTN + tix];
        okc += g_tot[2 * TOTN + tix];
        oks += g_tot[3 * TOTN + tix];
    }
    const float invSqrtD = 0.03125f;
    float spc = 0.f, sps = 0.f, skc = 0.f, sks = 0.f;
    float kcp, ksp;
    if (l0 == 0) { kcp = 0.f; ksp = 0.f; }
    else {
        __half2 kk = g_kcs[(size_t)(b * LL + l0 - 1) * DD + d];
        kcp = __low2float(kk); ksp = __high2float(kk);
    }
    for (int t = 0; t < TCHUNK; t++) {
        const int l = l0 + t;
        const int rowi = b * LL + l;
        const size_t idx = (size_t)rowi * DD + d;
        float sn, cs;
        __sincosf(pp[(size_t)l * DD + d], &sn, &cs);
        const float pvv = __half2float(g_pvh[idx]);
        spc = fmaf(cs, pvv, spc);
        sps = fmaf(sn, pvv, sps);
        const float kvg = __half2float(g_kvh[idx]) * g_vg[rowi];
        __half2 kk = g_kcs[idx];
        const float kcc = __low2float(kk), kss = __high2float(kk);
        skc = fmaf(kcp, kvg, skc);
        sks = fmaf(ksp, kvg, sks);
        kcp = kcc; ksp = kss;
        const float pos_ret = (cs * (spc + opc) + sn * (sps + ops)) * invSqrtD;
        const float kv_ret  = (kcc * (skc + okc) + kss * (sks + oks)) / g_gcs[rowi] * invSqrtD;
        g_blend[idx] = g_bw[2 * rowi] * pos_ret + g_bw[2 * rowi + 1] * kv_ret;
    }
}

// ---------------- LayerNorm fused with fp16 cast output ----------------
__global__ void k_ln(const float* __restrict__ lng, const float* __restrict__ lnb,
                     __half* __restrict__ out2)
{
    int row = blockIdx.x, tid = threadIdx.x;
    float v[4], s = 0.f, sq = 0.f;
#pragma unroll
    for (int i = 0; i < 4; i++) {
        v[i] = g_blend[(size_t)row * DD + tid + i * 256];
        s += v[i]; sq += v[i] * v[i];
    }
    __shared__ float shs[256], shq[256];
    shs[tid] = s; shq[tid] = sq; __syncthreads();
    for (int o = 128; o > 0; o >>= 1) {
        if (tid < o) { shs[tid] += shs[tid + o]; shq[tid] += shq[tid + o]; }
        __syncthreads();
    }
    __shared__ float smu, srstd;
    if (tid == 0) {
        float mu  = shs[0] * (1.f / DD);
        float var = shq[0] * (1.f / DD) - mu * mu;
        smu = mu;
        srstd = rsqrtf(var + 1e-5f);
    }
    __syncthreads();
#pragma unroll
    for (int i = 0; i < 4; i++) {
        int dd = tid + i * 256;
        float t = (v[i] - smu) * srstd * lng[dd] + lnb[dd];
        out2[(size_t)row * DD + dd] = __float2half(t);
    }
}

// ---------------- launch ----------------
extern "C" void kernel_launch(void* const* d_in, const int* in_sizes, int n_in,
                              void* d_out, int out_size)
{
    const float* x   = (const float*)d_in[0];
    const float* pp  = (const float*)d_in[1];
    const float* Wpv = (const float*)d_in[2];
    const float* bpv = (const float*)d_in[3];
    const float* Wk  = (const float*)d_in[4];
    const float* bk  = (const float*)d_in[5];
    const float* Wkv = (const float*)d_in[6];
    const float* bkv = (const float*)d_in[7];
    const float* Wg1 = (const float*)d_in[8];
    const float* bg1 = (const float*)d_in[9];
    const float* Wg2 = (const float*)d_in[10];
    const float* bg2 = (const float*)d_in[11];
    const float* Wb1 = (const float*)d_in[12];
    const float* bb1 = (const float*)d_in[13];
    const float* Wb2 = (const float*)d_in[14];
    const float* bb2 = (const float*)d_in[15];
    const float* lng = (const float*)d_in[16];
    const float* lnb = (const float*)d_in[17];
    const float* Wo  = (const float*)d_in[18];
    const float* bo  = (const float*)d_in[19];
    float* out = (float*)d_out;

    __half *pvh, *kvh, *gh, *bh, *x2, *ln2, *Wqkv2, *Wg12, *Wb12, *Wo2;
    __half2* kcs;
    cudaGetSymbolAddress((void**)&pvh,   g_pvh);
    cudaGetSymbolAddress((void**)&kvh,   g_kvh);
    cudaGetSymbolAddress((void**)&kcs,   g_kcs);
    cudaGetSymbolAddress((void**)&gh,    g_gh);
    cudaGetSymbolAddress((void**)&bh,    g_bh);
    cudaGetSymbolAddress((void**)&x2,    g_x2);
    cudaGetSymbolAddress((void**)&ln2,   g_ln2);
    cudaGetSymbolAddress((void**)&Wqkv2, g_Wqkv2);
    cudaGetSymbolAddress((void**)&Wg12,  g_Wg12);
    cudaGetSymbolAddress((void**)&Wb12,  g_Wb12);
    cudaGetSymbolAddress((void**)&Wo2,   g_Wo2);

    cudaFuncSetAttribute((const void*)gemm_qkv,          cudaFuncAttributeMaxDynamicSharedMemorySize, GEMM_SMEM);
    cudaFuncSetAttribute((const void*)gemm_mma<EP_GELU>, cudaFuncAttributeMaxDynamicSharedMemorySize, GEMM_SMEM);
    cudaFuncSetAttribute((const void*)gemm_mma<EP_OUT >, cudaFuncAttributeMaxDynamicSharedMemorySize, GEMM_SMEM);
    cudaFuncSetAttribute((const void*)gemm_gate,         cudaFuncAttributeMaxDynamicSharedMemorySize, GEMM_SMEM);

    // 0-1: conversions
    k_cvtA2<<<(MM * DD / 4) / 256, 256>>>(x, x2);
    k_cvtB2x3<<<dim3(DD / 32, DD / 32, 3), dim3(32, 8)>>>(Wpv, Wk, Wkv, Wqkv2);
    // 2: merged QKV GEMM (fp16 in/out, N=3072)
    gemm_qkv<<<dim3(12, MM / 128), 512, GEMM_SMEM>>>(
        (const uint16_t*)x2, (const uint16_t*)Wqkv2, bpv, bk, bkv, pvh, kcs, kvh);
    // 3-4: gate path
    k_cvtB2<<<dim3(DD / 32, 2 * DD / 32), dim3(32, 8)>>>(Wg1, Wg12, 2 * DD, DD);
    gemm_gate<<<dim3(4, MM / 128), 512, GEMM_SMEM>>>((const uint16_t*)x2, (const uint16_t*)Wg12, bg1, gh);
    // 5-6: blend hidden
    k_cvtB2<<<dim3((DD / 2) / 32, DD / 32), dim3(32, 8)>>>(Wb1, Wb12, DD, DD / 2);
    gemm_mma<EP_GELU><<<dim3(2, MM / 128), 512, GEMM_SMEM>>>(
        (const uint16_t*)x2, (const uint16_t*)Wb12, bb1, bh, nullptr, DD / 2, DD);
    // 7-8: fused gates+blend softmax, gate cumsum
    k_vgbw<<<2 * (MM / 8), 256>>>(Wg2, bg2, Wb2, bb2);
    k_gatescan<<<BBATCH, 1024>>>();
    // 9-10: scans (fp16 inputs, sincos recompute)
    dim3 gscan(DD / 256, NCHUNK, BBATCH);
    k_scanT<<<gscan, 256>>>(pp);
    k_scanC<<<gscan, 256>>>(pp);
    // 11: LayerNorm (fused fp16 cast)
    k_ln<<<MM, 256>>>(lng, lnb, ln2);
    // 12-13: output path (+residual)
    k_cvtB2<<<dim3(DD / 32, DD / 32), dim3(32, 8)>>>(Wo, Wo2, DD, DD);
    gemm_mma<EP_OUT><<<dim3(4, MM / 128), 512, GEMM_SMEM>>>(
        (const uint16_t*)ln2, (const uint16_t*)Wo2, bo, out, x, DD, DD);
}

// round 15
// speedup vs baseline: 2.0231x; 1.0042x over previous
#include <cuda_runtime.h>
#include <cuda_fp16.h>
#include <math.h>
#include <stdint.h>

// ---------------- problem constants ----------------
#define BBATCH 4
#define LL 4096
#define DD 1024
#define MM (BBATCH * LL)          // 16384 rows
#define NCHUNK 64
#define TCHUNK (LL / NCHUNK)      // 64
#define TOTN (BBATCH * NCHUNK * DD)

// ---------------- scratch ----------------
__device__ __half  g_pvh[(size_t)MM * DD];
__device__ __half  g_kvh[(size_t)MM * DD];
__device__ __half2 g_kcs[(size_t)MM * DD];       // (cos, sin) packed
__device__ __half  g_gh [(size_t)MM * DD];
__device__ __half  g_bh [(size_t)MM * (DD / 2)];
__device__ float g_vg[MM];
__device__ float g_gcs[MM];
__device__ float g_bw[MM * 2];
__device__ float g_tot[4 * TOTN];
__device__ __half g_blendh[(size_t)MM * DD];

// ---------------- plain fp16 operand scratch ----------------
__device__ __half g_x2   [(size_t)MM * DD];
__device__ __half g_ln2  [(size_t)MM * DD];
__device__ __half g_Wqkv2[(size_t)3 * DD * DD];
__device__ __half g_Wg12 [(size_t)DD * 2 * DD];
__device__ __half g_Wb12 [(size_t)(DD / 2) * DD];
__device__ __half g_Wo2  [(size_t)DD * DD];

// ================= PTX helpers (family-safe) =================
__device__ __forceinline__ uint32_t s2u(const void* p) {
    return (uint32_t)__cvta_generic_to_shared(p);
}
__device__ __forceinline__ void ldsm4(uint32_t& r0, uint32_t& r1, uint32_t& r2, uint32_t& r3, uint32_t a) {
    asm volatile("ldmatrix.sync.aligned.m8n8.x4.shared.b16 {%0,%1,%2,%3}, [%4];"
                 : "=r"(r0), "=r"(r1), "=r"(r2), "=r"(r3) : "r"(a));
}
__device__ __forceinline__ void mma16816(float* d, const uint32_t* a, uint32_t b0, uint32_t b1) {
    asm volatile("mma.sync.aligned.m16n8k16.row.col.f32.f16.f16.f32 "
                 "{%0,%1,%2,%3},{%4,%5,%6,%7},{%8,%9},{%0,%1,%2,%3};"
                 : "+f"(d[0]), "+f"(d[1]), "+f"(d[2]), "+f"(d[3])
                 : "r"(a[0]), "r"(a[1]), "r"(a[2]), "r"(a[3]), "r"(b0), "r"(b1));
}
__device__ __forceinline__ void cpasync16(uint32_t s, const void* g) {
    asm volatile("cp.async.cg.shared.global [%0], [%1], 16;" :: "r"(s), "l"(g));
}
__device__ __forceinline__ void sts_zero16(uint32_t a) {
    asm volatile("st.shared.v4.b32 [%0], {%1,%1,%1,%1};" :: "r"(a), "r"(0) : "memory");
}
__device__ __forceinline__ void cp_commit() { asm volatile("cp.async.commit_group;"); }
template <int n> __device__ __forceinline__ void cp_wait() {
    asm volatile("cp.async.wait_group %0;" :: "n"(n));
}
__device__ __forceinline__ float tanh_fast(float x) {
    float y;
    asm("tanh.approx.f32 %0, %1;" : "=f"(y) : "f"(x));
    return y;
}

// ================= GEMM core (512 thr, 16 warps 4x4, warp tile 32x64) =================
constexpr int EP_GELU = 2;
constexpr int EP_OUT  = 3;

#define STG 49152
#define GEMM_SMEM (1024 + 3 * STG)

struct MmaCtx {
    uint32_t aBase[2]; int aXor[2];
    uint32_t bBase[4]; int bXor[4];
    int chi;
};
__device__ __forceinline__ void mma_ctx_init(MmaCtx& cx, int lane, int wm, int wn) {
    const int mat = lane >> 3, mr = lane & 7;
    cx.chi = mat >> 1;
#pragma unroll
    for (int mi = 0; mi < 2; mi++) {
        int row = wm * 32 + mi * 16 + mr + (mat & 1) * 8;
        cx.aBase[mi] = row * 128; cx.aXor[mi] = row & 7;
    }
#pragma unroll
    for (int g = 0; g < 4; g++) {
        int row = wn * 64 + g * 16 + mr + (mat & 1) * 8;
        cx.bBase[g] = 16384 + row * 128; cx.bXor[g] = row & 7;
    }
}
__device__ __forceinline__ void mma_tile(const MmaCtx& cx, uint32_t ps, float acc[2][8][4]) {
#pragma unroll
    for (int kk = 0; kk < 4; kk++) {
        const int cb = kk * 2 + cx.chi;
        uint32_t a0[4], a1[4];
        ldsm4(a0[0], a0[1], a0[2], a0[3], ps + cx.aBase[0] + ((cb ^ cx.aXor[0]) << 4));
        ldsm4(a1[0], a1[1], a1[2], a1[3], ps + cx.aBase[1] + ((cb ^ cx.aXor[1]) << 4));
#pragma unroll
        for (int g = 0; g < 4; g++) {
            uint32_t b0, b1, b2, b3;
            ldsm4(b0, b1, b2, b3, ps + cx.bBase[g] + ((cb ^ cx.bXor[g]) << 4));
            mma16816(acc[0][2 * g],     a0, b0, b2);
            mma16816(acc[0][2 * g + 1], a0, b1, b3);
            mma16816(acc[1][2 * g],     a1, b0, b2);
            mma16816(acc[1][2 * g + 1], a1, b1, b3);
        }
    }
}

#define GEMM_MAINLOOP(Aptr, Bptr, Kv)                                                  \
    uint32_t so[6];                                                                    \
    const uint16_t* gp[6];                                                             \
    _Pragma("unroll")                                                                  \
    for (int j = 0; j < 6; j++) {                                                      \
        int id = tid + j * 512;                                                        \
        int q; const uint16_t* base; uint32_t off;                                     \
        if (id < 1024) { q = id;        base = (Aptr); off = 0; }                      \
        else           { q = id - 1024; base = (Bptr); off = 16384; }                  \
        int r = q >> 3, c = q & 7;                                                     \
        gp[j] = base + (size_t)r * (Kv) + c * 8;                                       \
        so[j] = off + r * 128 + ((uint32_t)(c ^ (r & 7)) << 4);                        \
    }                                                                                  \
    MmaCtx cx; mma_ctx_init(cx, lane, wm, wn);                                         \
    float acc[2][8][4];                                                                \
    _Pragma("unroll")                                                                  \
    for (int i = 0; i < 2; i++)                                                        \
        _Pragma("unroll")                                                              \
        for (int j = 0; j < 8; j++)                                                    \
            _Pragma("unroll")                                                          \
            for (int q = 0; q < 4; q++) acc[i][j][q] = 0.f;                            \
    const int nk = (Kv) >> 6;                                                          \
    _Pragma("unroll")                                                                  \
    for (int j = 0; j < 6; j++) cpasync16(sbase + so[j], gp[j]);                       \
    cp_commit();                                                                       \
    _Pragma("unroll")                                                                  \
    for (int j = 0; j < 6; j++) { gp[j] += 64; cpasync16(sbase + STG + so[j], gp[j]); }\
    cp_commit();                                                                       \
    for (int it = 0; it < nk; it++) {                                                  \
        if (it < nk - 1) cp_wait<1>(); else cp_wait<0>();                              \
        __syncthreads();                                                               \
        if (it + 2 < nk) {                                                             \
            const uint32_t dst = sbase + (uint32_t)((it + 2) % 3) * STG;               \
            _Pragma("unroll")                                                          \
            for (int j = 0; j < 6; j++) { gp[j] += 64; cpasync16(dst + so[j], gp[j]); }\
            cp_commit();                                                               \
        }                                                                              \
        mma_tile(cx, sbase + (uint32_t)(it % 3) * STG, acc);                           \
    }

// ================= merged QKV GEMM (fp16, N=3072, fp16 outputs) =================
__global__ void __launch_bounds__(512, 1)
gemm_qkv(const uint16_t* __restrict__ A, const uint16_t* __restrict__ Bt,
         const float* __restrict__ bpv, const float* __restrict__ bk,
         const float* __restrict__ bkv,
         __half* __restrict__ pvh, __half2* __restrict__ kcs, __half* __restrict__ kvh)
{
    extern __shared__ __align__(16) char smem_[];
    const uint32_t sbase = (s2u(smem_) + 1023u) & ~1023u;
    const int tid = threadIdx.x, lane = tid & 31, warp = tid >> 5;
    const int wm = warp >> 2, wn = warp & 3;
    const int brow = blockIdx.y, bcol = blockIdx.x;
    const int K = DD;

    const uint16_t* Ag = A  + (size_t)brow * 128 * K;
    const uint16_t* Bg = Bt + (size_t)bcol * 256 * K;
    GEMM_MAINLOOP(Ag, Bg, K)

    const int sect = bcol >> 2;                 // 0: pv, 1: key, 2: kv
    const float* bp = (sect == 0) ? bpv : (sect == 1) ? bk : bkv;
    __half* Cm = (sect == 0) ? pvh : kvh;
    const int r0 = brow * 128 + wm * 32 + (lane >> 2);
    const int c0 = (bcol & 3) * 256 + wn * 64 + (lane & 3) * 2;
#pragma unroll
    for (int mi = 0; mi < 2; mi++) {
#pragma unroll
        for (int nj = 0; nj < 8; nj++) {
            const int col = c0 + nj * 8;
            const float bv0 = bp[col], bv1 = bp[col + 1];
#pragma unroll
            for (int h = 0; h < 2; h++) {
                const int row = r0 + mi * 16 + h * 8;
                const size_t base = (size_t)row * DD + col;
                float v0 = acc[mi][nj][2 * h]     + bv0;
                float v1 = acc[mi][nj][2 * h + 1] + bv1;
                if (sect == 1) {
                    float s0, cc0, s1, cc1;
                    __sincosf(tanh_fast(v0) * 3.14159265358979323846f, &s0, &cc0);
                    __sincosf(tanh_fast(v1) * 3.14159265358979323846f, &s1, &cc1);
                    __half2 h0 = __floats2half2_rn(cc0, s0);
                    __half2 h1 = __floats2half2_rn(cc1, s1);
                    uint2 pk;
                    pk.x = *reinterpret_cast<uint32_t*>(&h0);
                    pk.y = *reinterpret_cast<uint32_t*>(&h1);
                    *reinterpret_cast<uint2*>(kcs + base) = pk;
                } else {
                    *reinterpret_cast<__half2*>(Cm + base) = __floats2half2_rn(v0, v1);
                }
            }
        }
    }
}

// ================= generic GEMM =================
template <int MODE>
__global__ void __launch_bounds__(512, 1)
gemm_mma(const uint16_t* __restrict__ A, const uint16_t* __restrict__ Bt,
         const float* __restrict__ bias, void* __restrict__ Cv,
         const float* __restrict__ addsrc, int N, int K)
{
    extern __shared__ __align__(16) char smem_[];
    const uint32_t sbase = (s2u(smem_) + 1023u) & ~1023u;
    const int tid = threadIdx.x, lane = tid & 31, warp = tid >> 5;
    const int wm = warp >> 2, wn = warp & 3;
    const int brow = blockIdx.y, bcol = blockIdx.x;

    const uint16_t* Ag = A  + (size_t)brow * 128 * K;
    const uint16_t* Bg = Bt + (size_t)bcol * 256 * K;
    GEMM_MAINLOOP(Ag, Bg, K)

    const int r0 = brow * 128 + wm * 32 + (lane >> 2);
    const int c0 = bcol * 256 + wn * 64 + (lane & 3) * 2;
#pragma unroll
    for (int mi = 0; mi < 2; mi++) {
#pragma unroll
        for (int nj = 0; nj < 8; nj++) {
            const int col = c0 + nj * 8;
            const float bv0 = bias[col], bv1 = bias[col + 1];
#pragma unroll
            for (int h = 0; h < 2; h++) {
                const int row = r0 + mi * 16 + h * 8;
                const size_t base = (size_t)row * N + col;
                float v0 = acc[mi][nj][2 * h]     + bv0;
                float v1 = acc[mi][nj][2 * h + 1] + bv1;
                if (MODE == EP_GELU) {
                    v0 = 0.5f * v0 * (1.f + erff(v0 * 0.70710678118654752f));
                    v1 = 0.5f * v1 * (1.f + erff(v1 * 0.70710678118654752f));
                    *reinterpret_cast<__half2*>((__half*)Cv + base) = __floats2half2_rn(v0, v1);
                } else {
                    v0 += addsrc[base]; v1 += addsrc[base + 1];
                    *reinterpret_cast<float2*>((float*)Cv + base) = make_float2(v0, v1);
                }
            }
        }
    }
}

// ================= gate GEMM: A = [x2 | shift1(x2)] virtual concat, fp16 out =================
__global__ void __launch_bounds__(512, 1)
gemm_gate(const uint16_t* __restrict__ X2, const uint16_t* __restrict__ Bt,
          const float* __restrict__ bias, __half* __restrict__ C)
{
    extern __shared__ __align__(16) char smem_[];
    const uint32_t sbase = (s2u(smem_) + 1023u) & ~1023u;
    const int tid = threadIdx.x, lane = tid & 31, warp = tid >> 5;
    const int wm = warp >> 2, wn = warp & 3;
    const int brow = blockIdx.y, bcol = blockIdx.x;
    const int K = 2 * DD;
    const int KH = DD;
    const int nkh = 16;

    uint32_t soA[2];
    const uint16_t *aCur[2], *aPrev[2];
    bool validA[2];
#pragma unroll
    for (int j = 0; j < 2; j++) {
        int q = tid + j * 512;
        int r = q >> 3, c = q & 7;
        int R = brow * 128 + r;
        aCur[j]  = X2 + (size_t)R * KH + c * 8;
        aPrev[j] = X2 + ((size_t)R - 1) * KH + c * 8;
        validA[j] = (R & (LL - 1)) != 0;
        soA[j] = r * 128 + ((uint32_t)(c ^ (r & 7)) << 4);
    }
    uint32_t soB[4];
    const uint16_t* bgp[4];
#pragma unroll
    for (int j = 0; j < 4; j++) {
        int q = tid + j * 512;
        int r = q >> 3, c = q & 7;
        bgp[j] = Bt + (size_t)(bcol * 256 + r) * K + c * 8;
        soB[j] = 16384 + r * 128 + ((uint32_t)(c ^ (r & 7)) << 4);
    }
    MmaCtx cx; mma_ctx_init(cx, lane, wm, wn);

    float acc[2][8][4];
#pragma unroll
    for (int i = 0; i < 2; i++)
#pragma unroll
        for (int j = 0; j < 8; j++)
#pragma unroll
            for (int q = 0; q < 4; q++) acc[i][j][q] = 0.f;

    const int nk = K >> 6;   // 32
#define GATE_LOAD(ITP, DST)                                                           \
    do {                                                                              \
        int itp_ = (ITP);                                                             \
        if (itp_ < nkh) {                                                             \
            cpasync16((DST) + soA[0], aCur[0] + itp_ * 64);                           \
            cpasync16((DST) + soA[1], aCur[1] + itp_ * 64);                           \
        } else {                                                                      \
            if (validA[0]) cpasync16((DST) + soA[0], aPrev[0] + (itp_ - nkh) * 64);   \
            else sts_zero16((DST) + soA[0]);                                          \
            if (validA[1]) cpasync16((DST) + soA[1], aPrev[1] + (itp_ - nkh) * 64);   \
            else sts_zero16((DST) + soA[1]);                                          \
        }                                                                             \
        cpasync16((DST) + soB[0], bgp[0] + itp_ * 64);                                \
        cpasync16((DST) + soB[1], bgp[1] + itp_ * 64);                                \
        cpasync16((DST) + soB[2], bgp[2] + itp_ * 64);                                \
        cpasync16((DST) + soB[3], bgp[3] + itp_ * 64);                                \
        cp_commit();                                                                  \
    } while (0)

    GATE_LOAD(0, sbase);
    GATE_LOAD(1, sbase + STG);

    for (int it = 0; it < nk; it++) {
        if (it < nk - 1) cp_wait<1>(); else cp_wait<0>();
        __syncthreads();
        if (it + 2 < nk) {
            const uint32_t dst = sbase + (uint32_t)((it + 2) % 3) * STG;
            GATE_LOAD(it + 2, dst);
        }
        mma_tile(cx, sbase + (uint32_t)(it % 3) * STG, acc);
    }
#undef GATE_LOAD

    const int r0 = brow * 128 + wm * 32 + (lane >> 2);
    const int c0 = bcol * 256 + wn * 64 + (lane & 3) * 2;
#pragma unroll
    for (int mi = 0; mi < 2; mi++) {
#pragma unroll
        for (int nj = 0; nj < 8; nj++) {
            const int col = c0 + nj * 8;
            const float bv0 = bias[col], bv1 = bias[col + 1];
#pragma unroll
            for (int h = 0; h < 2; h++) {
                const int row = r0 + mi * 16 + h * 8;
                const size_t base = (size_t)row * DD + col;
                float v0 = acc[mi][nj][2 * h]     + bv0;
                float v1 = acc[mi][nj][2 * h + 1] + bv1;
                v0 = 0.5f * v0 * (1.f + erff(v0 * 0.70710678118654752f));
                v1 = 0.5f * v1 * (1.f + erff(v1 * 0.70710678118654752f));
                *reinterpret_cast<__half2*>(C + base) = __floats2half2_rn(v0, v1);
            }
        }
    }
}

// ---------------- conversion kernels ----------------
__global__ void k_cvtA2(const float* __restrict__ in, __half* __restrict__ out)
{
    size_t t = (size_t)blockIdx.x * 256 + threadIdx.x;
    float4 v = reinterpret_cast<const float4*>(in)[t];
    __align__(8) __half o[4];
    o[0] = __float2half(v.x); o[1] = __float2half(v.y);
    o[2] = __float2half(v.z); o[3] = __float2half(v.w);
    reinterpret_cast<uint2*>(out)[t] = *reinterpret_cast<const uint2*>(o);
}

__global__ void k_cvtB2(const float* __restrict__ W, __half* __restrict__ out, int K, int N)
{
    __shared__ float ts[32][33];
    const int k0 = blockIdx.y * 32, n0 = blockIdx.x * 32;
    const int tx = threadIdx.x, ty = threadIdx.y;
#pragma unroll
    for (int i = 0; i < 4; i++)
        ts[ty + i * 8][tx] = W[(size_t)(k0 + ty + i * 8) * N + n0 + tx];
    __syncthreads();
#pragma unroll
    for (int i = 0; i < 4; i++) {
        int n = ty + i * 8;
        out[(size_t)(n0 + n) * K + k0 + tx] = __float2half(ts[tx][n]);
    }
}

__global__ void k_cvtB2x3(const float* __restrict__ W0, const float* __restrict__ W1,
                          const float* __restrict__ W2, __half* __restrict__ out)
{
    __shared__ float ts[32][33];
    const float* W = (blockIdx.z == 0) ? W0 : (blockIdx.z == 1) ? W1 : W2;
    __half* o = out + (size_t)blockIdx.z * DD * DD;
    const int k0 = blockIdx.y * 32, n0 = blockIdx.x * 32;
    const int tx = threadIdx.x, ty = threadIdx.y;
#pragma unroll
    for (int i = 0; i < 4; i++)
        ts[ty + i * 8][tx] = W[(size_t)(k0 + ty + i * 8) * DD + n0 + tx];
    __syncthreads();
#pragma unroll
    for (int i = 0; i < 4; i++) {
        int n = ty + i * 8;
        o[(size_t)(n0 + n) * DD + k0 + tx] = __float2half(ts[tx][n]);
    }
}

// ---------------- fused value_gates + blend weights ----------------
__global__ void k_vgbw(const float* __restrict__ Wg2, const float* __restrict__ bg2,
                       const float* __restrict__ Wb2, const float* __restrict__ bb2)
{
    const int warp = threadIdx.x >> 5, lane = threadIdx.x & 31;
    const int bx = blockIdx.x;
    if (bx < MM / 8) {
        const int row = bx * 8 + warp;
        const uint4* g = reinterpret_cast<const uint4*>(g_gh + (size_t)row * DD);
        const float4* w = reinterpret_cast<const float4*>(Wg2);
        float s = 0.f;
#pragma unroll
        for (int i = 0; i < 4; i++) {
            int idx = lane + i * 32;
            uint4 hv = g[idx];
            const __half2* hp = reinterpret_cast<const __half2*>(&hv);
            float4 w0 = w[2 * idx], w1 = w[2 * idx + 1];
            float2 a0 = __half22float2(hp[0]);
            float2 a1 = __half22float2(hp[1]);
            float2 a2 = __half22float2(hp[2]);
            float2 a3 = __half22float2(hp[3]);
            s += a0.x * w0.x + a0.y * w0.y + a1.x * w0.z + a1.y * w0.w;
            s += a2.x * w1.x + a2.y * w1.y + a3.x * w1.z + a3.y * w1.w;
        }
#pragma unroll
        for (int o = 16; o > 0; o >>= 1) s += __shfl_xor_sync(0xFFFFFFFFu, s, o);
        if (lane == 0) g_vg[row] = 1.f / (1.f + expf(-(s + bg2[0])));
    } else {
        const int row = (bx - MM / 8) * 8 + warp;
        const uint4* hv4 = reinterpret_cast<const uint4*>(g_bh + (size_t)row * (DD / 2));
        const float4* wv = reinterpret_cast<const float4*>(Wb2);
        float s0 = 0.f, s1 = 0.f;
#pragma unroll
        for (int i = 0; i < 2; i++) {
            int idx = lane + i * 32;
            uint4 hv = hv4[idx];
            const __half2* hp = reinterpret_cast<const __half2*>(&hv);
#pragma unroll
            for (int j = 0; j < 4; j++) {
                float2 a = __half22float2(hp[j]);
                float4 wA = wv[4 * idx + j];
                s0 += a.x * wA.x + a.y * wA.z;
                s1 += a.x * wA.y + a.y * wA.w;
            }
        }
#pragma unroll
        for (int o = 16; o > 0; o >>= 1) {
            s0 += __shfl_xor_sync(0xFFFFFFFFu, s0, o);
            s1 += __shfl_xor_sync(0xFFFFFFFFu, s1, o);
        }
        if (lane == 0) {
            float a0 = s0 + bb2[0], a1 = s1 + bb2[1];
            float m = fmaxf(a0, a1);
            float e0 = expf(a0 - m), e1 = expf(a1 - m);
            float inv = 1.f / (e0 + e1);
            g_bw[2 * row]     = e0 * inv;
            g_bw[2 * row + 1] = e1 * inv;
        }
    }
}

// ---------------- per-batch gate scan (shuffle-based) ----------------
__global__ void k_gatescan()
{
    const int b = blockIdx.x;
    const int tid = threadIdx.x, lane = tid & 31, warp = tid >> 5;
    __shared__ float shw[33];
    float carry = 0.f;
    for (int t0 = 0; t0 < LL; t0 += 1024) {
        float v = g_vg[b * LL + t0 + tid];
        float sc = v;
#pragma unroll
        for (int o = 1; o < 32; o <<= 1) {
            float t = __shfl_up_sync(0xFFFFFFFFu, sc, o);
            if (lane >= o) sc += t;
        }
        if (lane == 31) shw[warp] = sc;
        __syncthreads();
        if (warp == 0) {
            float w = shw[lane];
            float ws = w;
#pragma unroll
            for (int o = 1; o < 32; o <<= 1) {
                float t = __shfl_up_sync(0xFFFFFFFFu, ws, o);
                if (lane >= o) ws += t;
            }
            shw[lane] = ws - w;          // exclusive warp-prefix
            if (lane == 31) shw[32] = ws; // chunk total
        }
        __syncthreads();
        float inc = sc + shw[warp] + carry;
        g_gcs[b * LL + t0 + tid] = sqrtf(fmaxf(inc, 1.f));
        carry += shw[32];
        __syncthreads();
    }
}

// ---------------- scan pass T (fp16 inputs, sincos recompute) ----------------
__global__ void k_scanT(const float* __restrict__ pp)
{
    const int d = blockIdx.x * 256 + threadIdx.x;
    const int c = blockIdx.y, b = blockIdx.z;
    const int l0 = c * TCHUNK;
    float spc = 0.f, sps = 0.f, skc = 0.f, sks = 0.f;
    float kcp, ksp;
    if (l0 == 0) { kcp = 0.f; ksp = 0.f; }
    else {
        __half2 kk = g_kcs[(size_t)(b * LL + l0 - 1) * DD + d];
        kcp = __low2float(kk); ksp = __high2float(kk);
    }
    for (int t = 0; t < TCHUNK; t++) {
        const int l = l0 + t;
        const int rowi = b * LL + l;
        const size_t idx = (size_t)rowi * DD + d;
        float sn, cs;
        __sincosf(pp[(size_t)l * DD + d], &sn, &cs);
        const float pvv = __half2float(g_pvh[idx]);
        spc = fmaf(cs, pvv, spc);
        sps = fmaf(sn, pvv, sps);
        const float kvg = __half2float(g_kvh[idx]) * g_vg[rowi];
        skc = fmaf(kcp, kvg, skc);
        sks = fmaf(ksp, kvg, sks);
        __half2 kk = g_kcs[idx];
        kcp = __low2float(kk); ksp = __high2float(kk);
    }
    size_t tix = (size_t)(b * NCHUNK + c) * DD + d;
    g_tot[tix]            = spc;
    g_tot[TOTN + tix]     = sps;
    g_tot[2 * TOTN + tix] = skc;
    g_tot[3 * TOTN + tix] = sks;
}

// ---------------- chunk-total exclusive prefix (in place) ----------------
__global__ void k_totscan()
{
    const int d = blockIdx.x * 256 + threadIdx.x;
    const int b = blockIdx.y;
    float r0 = 0.f, r1 = 0.f, r2 = 0.f, r3 = 0.f;
    for (int c = 0; c < NCHUNK; c++) {
        size_t tix = (size_t)(b * NCHUNK + c) * DD + d;
        float v0 = g_tot[tix];
        float v1 = g_tot[TOTN + tix];
        float v2 = g_tot[2 * TOTN + tix];
        float v3 = g_tot[3 * TOTN + tix];
        g_tot[tix]            = r0;
        g_tot[TOTN + tix]     = r1;
        g_tot[2 * TOTN + tix] = r2;
        g_tot[3 * TOTN + tix] = r3;
        r0 += v0; r1 += v1; r2 += v2; r3 += v3;
    }
}

// ---------------- scan pass C (direct offsets, fp16 blend output) ----------------
__global__ void k_scanC(const float* __restrict__ pp)
{
    const int d = blockIdx.x * 256 + threadIdx.x;
    const int c = blockIdx.y, b = blockIdx.z;
    const int l0 = c * TCHUNK;
    const size_t otix = (size_t)(b * NCHUNK + c) * DD + d;
    const float opc = g_tot[otix];
    const float ops = g_tot[TOTN + otix];
    const float okc = g_tot[2 * TOTN + otix];
    const float oks = g_tot[3 * TOTN + otix];
    const float invSqrtD = 0.03125f;
    float spc = 0.f, sps = 0.f, skc = 0.f, sks = 0.f;
    float kcp, ksp;
    if (l0 == 0) { kcp = 0.f; ksp = 0.f; }
    else {
        __half2 kk = g_kcs[(size_t)(b * LL + l0 - 1) * DD + d];
        kcp = __low2float(kk); ksp = __high2float(kk);
    }
    for (int t = 0; t < TCHUNK; t++) {
        const int l = l0 + t;
        const int rowi = b * LL + l;
        const size_t idx = (size_t)rowi * DD + d;
        float sn, cs;
        __sincosf(pp[(size_t)l * DD + d], &sn, &cs);
        const float pvv = __half2float(g_pvh[idx]);
        spc = fmaf(cs, pvv, spc);
        sps = fmaf(sn, pvv, sps);
        const float kvg = __half2float(g_kvh[idx]) * g_vg[rowi];
        __half2 kk = g_kcs[idx];
        const float kcc = __low2float(kk), kss = __high2float(kk);
        skc = fmaf(kcp, kvg, skc);
        sks = fmaf(ksp, kvg, sks);
        kcp = kcc; ksp = kss;
        const float pos_ret = (cs * (spc + opc) + sn * (sps + ops)) * invSqrtD;
        const float kv_ret  = (kcc * (skc + okc) + kss * (sks + oks)) / g_gcs[rowi] * invSqrtD;
        g_blendh[idx] = __float2half(g_bw[2 * rowi] * pos_ret + g_bw[2 * rowi + 1] * kv_ret);
    }
}

// ---------------- LayerNorm fused with fp16 cast output ----------------
__global__ void k_ln(const float* __restrict__ lng, const float* __restrict__ lnb,
                     __half* __restrict__ out2)
{
    int row = blockIdx.x, tid = threadIdx.x;
    float v[4], s = 0.f, sq = 0.f;
#pragma unroll
    for (int i = 0; i < 4; i++) {
        v[i] = __half2float(g_blendh[(size_t)row * DD + tid + i * 256]);
        s += v[i]; sq += v[i] * v[i];
    }
    __shared__ float shs[256], shq[256];
    shs[tid] = s; shq[tid] = sq; __syncthreads();
    for (int o = 128; o > 0; o >>= 1) {
        if (tid < o) { shs[tid] += shs[tid + o]; shq[tid] += shq[tid + o]; }
        __syncthreads();
    }
    __shared__ float smu, srstd;
    if (tid == 0) {
        float mu  = shs[0] * (1.f / DD);
        float var = shq[0] * (1.f / DD) - mu * mu;
        smu = mu;
        srstd = rsqrtf(var + 1e-5f);
    }
    __syncthreads();
#pragma unroll
    for (int i = 0; i < 4; i++) {
        int dd = tid + i * 256;
        float t = (v[i] - smu) * srstd * lng[dd] + lnb[dd];
        out2[(size_t)row * DD + dd] = __float2half(t);
    }
}

// ---------------- launch ----------------
extern "C" void kernel_launch(void* const* d_in, const int* in_sizes, int n_in,
                              void* d_out, int out_size)
{
    const float* x   = (const float*)d_in[0];
    const float* pp  = (const float*)d_in[1];
    const float* Wpv = (const float*)d_in[2];
    const float* bpv = (const float*)d_in[3];
    const float* Wk  = (const float*)d_in[4];
    const float* bk  = (const float*)d_in[5];
    const float* Wkv = (const float*)d_in[6];
    const float* bkv = (const float*)d_in[7];
    const float* Wg1 = (const float*)d_in[8];
    const float* bg1 = (const float*)d_in[9];
    const float* Wg2 = (const float*)d_in[10];
    const float* bg2 = (const float*)d_in[11];
    const float* Wb1 = (const float*)d_in[12];
    const float* bb1 = (const float*)d_in[13];
    const float* Wb2 = (const float*)d_in[14];
    const float* bb2 = (const float*)d_in[15];
    const float* lng = (const float*)d_in[16];
    const float* lnb = (const float*)d_in[17];
    const float* Wo  = (const float*)d_in[18];
    const float* bo  = (const float*)d_in[19];
    float* out = (float*)d_out;

    __half *pvh, *kvh, *gh, *bh, *x2, *ln2, *Wqkv2, *Wg12, *Wb12, *Wo2;
    __half2* kcs;
    cudaGetSymbolAddress((void**)&pvh,   g_pvh);
    cudaGetSymbolAddress((void**)&kvh,   g_kvh);
    cudaGetSymbolAddress((void**)&kcs,   g_kcs);
    cudaGetSymbolAddress((void**)&gh,    g_gh);
    cudaGetSymbolAddress((void**)&bh,    g_bh);
    cudaGetSymbolAddress((void**)&x2,    g_x2);
    cudaGetSymbolAddress((void**)&ln2,   g_ln2);
    cudaGetSymbolAddress((void**)&Wqkv2, g_Wqkv2);
    cudaGetSymbolAddress((void**)&Wg12,  g_Wg12);
    cudaGetSymbolAddress((void**)&Wb12,  g_Wb12);
    cudaGetSymbolAddress((void**)&Wo2,   g_Wo2);

    cudaFuncSetAttribute((const void*)gemm_qkv,          cudaFuncAttributeMaxDynamicSharedMemorySize, GEMM_SMEM);
    cudaFuncSetAttribute((const void*)gemm_mma<EP_GELU>, cudaFuncAttributeMaxDynamicSharedMemorySize, GEMM_SMEM);
    cudaFuncSetAttribute((const void*)gemm_mma<EP_OUT >, cudaFuncAttributeMaxDynamicSharedMemorySize, GEMM_SMEM);
    cudaFuncSetAttribute((const void*)gemm_gate,         cudaFuncAttributeMaxDynamicSharedMemorySize, GEMM_SMEM);

    // 0-1: conversions
    k_cvtA2<<<(MM * DD / 4) / 256, 256>>>(x, x2);
    k_cvtB2x3<<<dim3(DD / 32, DD / 32, 3), dim3(32, 8)>>>(Wpv, Wk, Wkv, Wqkv2);
    // 2: merged QKV GEMM (fp16 in/out, N=3072)
    gemm_qkv<<<dim3(12, MM / 128), 512, GEMM_SMEM>>>(
        (const uint16_t*)x2, (const uint16_t*)Wqkv2, bpv, bk, bkv, pvh, kcs, kvh);
    // 3-4: gate path
    k_cvtB2<<<dim3(DD / 32, 2 * DD / 32), dim3(32, 8)>>>(Wg1, Wg12, 2 * DD, DD);
    gemm_gate<<<dim3(4, MM / 128), 512, GEMM_SMEM>>>((const uint16_t*)x2, (const uint16_t*)Wg12, bg1, gh);
    // 5-6: blend hidden
    k_cvtB2<<<dim3((DD / 2) / 32, DD / 32), dim3(32, 8)>>>(Wb1, Wb12, DD, DD / 2);
    gemm_mma<EP_GELU><<<dim3(2, MM / 128), 512, GEMM_SMEM>>>(
        (const uint16_t*)x2, (const uint16_t*)Wb12, bb1, bh, nullptr, DD / 2, DD);
    // 7-8: fused gates+blend softmax, gate cumsum
    k_vgbw<<<2 * (MM / 8), 256>>>(Wg2, bg2, Wb2, bb2);
    k_gatescan<<<BBATCH, 1024>>>();
    // 9-11: scans with pre-scanned chunk totals
    dim3 gscan(DD / 256, NCHUNK, BBATCH);
    k_scanT<<<gscan, 256>>>(pp);
    k_totscan<<<dim3(DD / 256, BBATCH), 256>>>();
    k_scanC<<<gscan, 256>>>(pp);
    // 12: LayerNorm (fused fp16 cast)
    k_ln<<<MM, 256>>>(lng, lnb, ln2);
    // 13-14: output path (+residual)
    k_cvtB2<<<dim3(DD / 32, DD / 32), dim3(32, 8)>>>(Wo, Wo2, DD, DD);
    gemm_mma<EP_OUT><<<dim3(4, MM / 128), 512, GEMM_SMEM>>>(
        (const uint16_t*)ln2, (const uint16_t*)Wo2, bo, out, x, DD, DD);
}

// round 16
// speedup vs baseline: 2.0950x; 1.0356x over previous
#include <cuda_runtime.h>
#include <cuda_fp16.h>
#include <math.h>
#include <stdint.h>

// ---------------- problem constants ----------------
#define BBATCH 4
#define LL 4096
#define DD 1024
#define MM (BBATCH * LL)          // 16384 rows
#define NCHUNK 128
#define TCHUNK (LL / NCHUNK)      // 32
#define TOTN (BBATCH * NCHUNK * DD)

// ---------------- scratch ----------------
__device__ __half  g_pvh[(size_t)MM * DD];
__device__ __half  g_kvh[(size_t)MM * DD];
__device__ __half2 g_kcs[(size_t)MM * DD];       // (cos, sin) packed
__device__ __half  g_gh [(size_t)MM * DD];
__device__ __half  g_bh [(size_t)MM * (DD / 2)];
__device__ float g_vg[MM];
__device__ float g_gcs[MM];
__device__ float g_bw[MM * 2];
__device__ float g_tot[4 * TOTN];
__device__ __half g_blendh[(size_t)MM * DD];

// ---------------- plain fp16 operand scratch ----------------
__device__ __half g_x2   [(size_t)MM * DD];
__device__ __half g_ln2  [(size_t)MM * DD];
__device__ __half g_Wqkv2[(size_t)3 * DD * DD];
__device__ __half g_Wg12 [(size_t)DD * 2 * DD];
__device__ __half g_Wb12 [(size_t)(DD / 2) * DD];
__device__ __half g_Wo2  [(size_t)DD * DD];

// ================= PTX helpers (family-safe) =================
__device__ __forceinline__ uint32_t s2u(const void* p) {
    return (uint32_t)__cvta_generic_to_shared(p);
}
__device__ __forceinline__ void ldsm4(uint32_t& r0, uint32_t& r1, uint32_t& r2, uint32_t& r3, uint32_t a) {
    asm volatile("ldmatrix.sync.aligned.m8n8.x4.shared.b16 {%0,%1,%2,%3}, [%4];"
                 : "=r"(r0), "=r"(r1), "=r"(r2), "=r"(r3) : "r"(a));
}
__device__ __forceinline__ void mma16816(float* d, const uint32_t* a, uint32_t b0, uint32_t b1) {
    asm volatile("mma.sync.aligned.m16n8k16.row.col.f32.f16.f16.f32 "
                 "{%0,%1,%2,%3},{%4,%5,%6,%7},{%8,%9},{%0,%1,%2,%3};"
                 : "+f"(d[0]), "+f"(d[1]), "+f"(d[2]), "+f"(d[3])
                 : "r"(a[0]), "r"(a[1]), "r"(a[2]), "r"(a[3]), "r"(b0), "r"(b1));
}
__device__ __forceinline__ void cpasync16(uint32_t s, const void* g) {
    asm volatile("cp.async.cg.shared.global [%0], [%1], 16;" :: "r"(s), "l"(g));
}
__device__ __forceinline__ void sts_zero16(uint32_t a) {
    asm volatile("st.shared.v4.b32 [%0], {%1,%1,%1,%1};" :: "r"(a), "r"(0) : "memory");
}
__device__ __forceinline__ void cp_commit() { asm volatile("cp.async.commit_group;"); }
template <int n> __device__ __forceinline__ void cp_wait() {
    asm volatile("cp.async.wait_group %0;" :: "n"(n));
}
__device__ __forceinline__ float tanh_fast(float x) {
    float y;
    asm("tanh.approx.f32 %0, %1;" : "=f"(y) : "f"(x));
    return y;
}

// ================= GEMM core (512 thr, 16 warps 4x4, warp tile 32x64) =================
constexpr int EP_GELU = 2;
constexpr int EP_OUT  = 3;

#define STG 49152
#define GEMM_SMEM (1024 + 3 * STG)

struct MmaCtx {
    uint32_t aBase[2]; int aXor[2];
    uint32_t bBase[4]; int bXor[4];
    int chi;
};
__device__ __forceinline__ void mma_ctx_init(MmaCtx& cx, int lane, int wm, int wn) {
    const int mat = lane >> 3, mr = lane & 7;
    cx.chi = mat >> 1;
#pragma unroll
    for (int mi = 0; mi < 2; mi++) {
        int row = wm * 32 + mi * 16 + mr + (mat & 1) * 8;
        cx.aBase[mi] = row * 128; cx.aXor[mi] = row & 7;
    }
#pragma unroll
    for (int g = 0; g < 4; g++) {
        int row = wn * 64 + g * 16 + mr + (mat & 1) * 8;
        cx.bBase[g] = 16384 + row * 128; cx.bXor[g] = row & 7;
    }
}
__device__ __forceinline__ void mma_tile(const MmaCtx& cx, uint32_t ps, float acc[2][8][4]) {
#pragma unroll
    for (int kk = 0; kk < 4; kk++) {
        const int cb = kk * 2 + cx.chi;
        uint32_t a0[4], a1[4];
        ldsm4(a0[0], a0[1], a0[2], a0[3], ps + cx.aBase[0] + ((cb ^ cx.aXor[0]) << 4));
        ldsm4(a1[0], a1[1], a1[2], a1[3], ps + cx.aBase[1] + ((cb ^ cx.aXor[1]) << 4));
#pragma unroll
        for (int g = 0; g < 4; g++) {
            uint32_t b0, b1, b2, b3;
            ldsm4(b0, b1, b2, b3, ps + cx.bBase[g] + ((cb ^ cx.bXor[g]) << 4));
            mma16816(acc[0][2 * g],     a0, b0, b2);
            mma16816(acc[0][2 * g + 1], a0, b1, b3);
            mma16816(acc[1][2 * g],     a1, b0, b2);
            mma16816(acc[1][2 * g + 1], a1, b1, b3);
        }
    }
}

#define GEMM_MAINLOOP(Aptr, Bptr, Kv)                                                  \
    uint32_t so[6];                                                                    \
    const uint16_t* gp[6];                                                             \
    _Pragma("unroll")                                                                  \
    for (int j = 0; j < 6; j++) {                                                      \
        int id = tid + j * 512;                                                        \
        int q; const uint16_t* base; uint32_t off;                                     \
        if (id < 1024) { q = id;        base = (Aptr); off = 0; }                      \
        else           { q = id - 1024; base = (Bptr); off = 16384; }                  \
        int r = q >> 3, c = q & 7;                                                     \
        gp[j] = base + (size_t)r * (Kv) + c * 8;                                       \
        so[j] = off + r * 128 + ((uint32_t)(c ^ (r & 7)) << 4);                        \
    }                                                                                  \
    MmaCtx cx; mma_ctx_init(cx, lane, wm, wn);                                         \
    float acc[2][8][4];                                                                \
    _Pragma("unroll")                                                                  \
    for (int i = 0; i < 2; i++)                                                        \
        _Pragma("unroll")                                                              \
        for (int j = 0; j < 8; j++)                                                    \
            _Pragma("unroll")                                                          \
            for (int q = 0; q < 4; q++) acc[i][j][q] = 0.f;                            \
    const int nk = (Kv) >> 6;                                                          \
    _Pragma("unroll")                                                                  \
    for (int j = 0; j < 6; j++) cpasync16(sbase + so[j], gp[j]);                       \
    cp_commit();                                                                       \
    _Pragma("unroll")                                                                  \
    for (int j = 0; j < 6; j++) { gp[j] += 64; cpasync16(sbase + STG + so[j], gp[j]); }\
    cp_commit();                                                                       \
    for (int it = 0; it < nk; it++) {                                                  \
        if (it < nk - 1) cp_wait<1>(); else cp_wait<0>();                              \
        __syncthreads();                                                               \
        if (it + 2 < nk) {                                                             \
            const uint32_t dst = sbase + (uint32_t)((it + 2) % 3) * STG;               \
            _Pragma("unroll")                                                          \
            for (int j = 0; j < 6; j++) { gp[j] += 64; cpasync16(dst + so[j], gp[j]); }\
            cp_commit();                                                               \
        }                                                                              \
        mma_tile(cx, sbase + (uint32_t)(it % 3) * STG, acc);                           \
    }

// ================= merged QKV GEMM (fp16, N=3072, fp16 outputs) =================
__global__ void __launch_bounds__(512, 1)
gemm_qkv(const uint16_t* __restrict__ A, const uint16_t* __restrict__ Bt,
         const float* __restrict__ bpv, const float* __restrict__ bk,
         const float* __restrict__ bkv,
         __half* __restrict__ pvh, __half2* __restrict__ kcs, __half* __restrict__ kvh)
{
    extern __shared__ __align__(16) char smem_[];
    const uint32_t sbase = (s2u(smem_) + 1023u) & ~1023u;
    const int tid = threadIdx.x, lane = tid & 31, warp = tid >> 5;
    const int wm = warp >> 2, wn = warp & 3;
    const int brow = blockIdx.y, bcol = blockIdx.x;
    const int K = DD;

    const uint16_t* Ag = A  + (size_t)brow * 128 * K;
    const uint16_t* Bg = Bt + (size_t)bcol * 256 * K;
    GEMM_MAINLOOP(Ag, Bg, K)

    const int sect = bcol >> 2;                 // 0: pv, 1: key, 2: kv
    const float* bp = (sect == 0) ? bpv : (sect == 1) ? bk : bkv;
    __half* Cm = (sect == 0) ? pvh : kvh;
    const int r0 = brow * 128 + wm * 32 + (lane >> 2);
    const int c0 = (bcol & 3) * 256 + wn * 64 + (lane & 3) * 2;
#pragma unroll
    for (int mi = 0; mi < 2; mi++) {
#pragma unroll
        for (int nj = 0; nj < 8; nj++) {
            const int col = c0 + nj * 8;
            const float bv0 = bp[col], bv1 = bp[col + 1];
#pragma unroll
            for (int h = 0; h < 2; h++) {
                const int row = r0 + mi * 16 + h * 8;
                const size_t base = (size_t)row * DD + col;
                float v0 = acc[mi][nj][2 * h]     + bv0;
                float v1 = acc[mi][nj][2 * h + 1] + bv1;
                if (sect == 1) {
                    float s0, cc0, s1, cc1;
                    __sincosf(tanh_fast(v0) * 3.14159265358979323846f, &s0, &cc0);
                    __sincosf(tanh_fast(v1) * 3.14159265358979323846f, &s1, &cc1);
                    __half2 h0 = __floats2half2_rn(cc0, s0);
                    __half2 h1 = __floats2half2_rn(cc1, s1);
                    uint2 pk;
                    pk.x = *reinterpret_cast<uint32_t*>(&h0);
                    pk.y = *reinterpret_cast<uint32_t*>(&h1);
                    *reinterpret_cast<uint2*>(kcs + base) = pk;
                } else {
                    *reinterpret_cast<__half2*>(Cm + base) = __floats2half2_rn(v0, v1);
                }
            }
        }
    }
}

// ================= generic GEMM =================
template <int MODE>
__global__ void __launch_bounds__(512, 1)
gemm_mma(const uint16_t* __restrict__ A, const uint16_t* __restrict__ Bt,
         const float* __restrict__ bias, void* __restrict__ Cv,
         const float* __restrict__ addsrc, int N, int K)
{
    extern __shared__ __align__(16) char smem_[];
    const uint32_t sbase = (s2u(smem_) + 1023u) & ~1023u;
    const int tid = threadIdx.x, lane = tid & 31, warp = tid >> 5;
    const int wm = warp >> 2, wn = warp & 3;
    const int brow = blockIdx.y, bcol = blockIdx.x;

    const uint16_t* Ag = A  + (size_t)brow * 128 * K;
    const uint16_t* Bg = Bt + (size_t)bcol * 256 * K;
    GEMM_MAINLOOP(Ag, Bg, K)

    const int r0 = brow * 128 + wm * 32 + (lane >> 2);
    const int c0 = bcol * 256 + wn * 64 + (lane & 3) * 2;
#pragma unroll
    for (int mi = 0; mi < 2; mi++) {
#pragma unroll
        for (int nj = 0; nj < 8; nj++) {
            const int col = c0 + nj * 8;
            const float bv0 = bias[col], bv1 = bias[col + 1];
#pragma unroll
            for (int h = 0; h < 2; h++) {
                const int row = r0 + mi * 16 + h * 8;
                const size_t base = (size_t)row * N + col;
                float v0 = acc[mi][nj][2 * h]     + bv0;
                float v1 = acc[mi][nj][2 * h + 1] + bv1;
                if (MODE == EP_GELU) {
                    v0 = 0.5f * v0 * (1.f + erff(v0 * 0.70710678118654752f));
                    v1 = 0.5f * v1 * (1.f + erff(v1 * 0.70710678118654752f));
                    *reinterpret_cast<__half2*>((__half*)Cv + base) = __floats2half2_rn(v0, v1);
                } else {
                    v0 += addsrc[base]; v1 += addsrc[base + 1];
                    *reinterpret_cast<float2*>((float*)Cv + base) = make_float2(v0, v1);
                }
            }
        }
    }
}

// ================= gate GEMM: A = [x2 | shift1(x2)] virtual concat, fp16 out =================
__global__ void __launch_bounds__(512, 1)
gemm_gate(const uint16_t* __restrict__ X2, const uint16_t* __restrict__ Bt,
          const float* __restrict__ bias, __half* __restrict__ C)
{
    extern __shared__ __align__(16) char smem_[];
    const uint32_t sbase = (s2u(smem_) + 1023u) & ~1023u;
    const int tid = threadIdx.x, lane = tid & 31, warp = tid >> 5;
    const int wm = warp >> 2, wn = warp & 3;
    const int brow = blockIdx.y, bcol = blockIdx.x;
    const int K = 2 * DD;
    const int KH = DD;
    const int nkh = 16;

    uint32_t soA[2];
    const uint16_t *aCur[2], *aPrev[2];
    bool validA[2];
#pragma unroll
    for (int j = 0; j < 2; j++) {
        int q = tid + j * 512;
        int r = q >> 3, c = q & 7;
        int R = brow * 128 + r;
        aCur[j]  = X2 + (size_t)R * KH + c * 8;
        aPrev[j] = X2 + ((size_t)R - 1) * KH + c * 8;
        validA[j] = (R & (LL - 1)) != 0;
        soA[j] = r * 128 + ((uint32_t)(c ^ (r & 7)) << 4);
    }
    uint32_t soB[4];
    const uint16_t* bgp[4];
#pragma unroll
    for (int j = 0; j < 4; j++) {
        int q = tid + j * 512;
        int r = q >> 3, c = q & 7;
        bgp[j] = Bt + (size_t)(bcol * 256 + r) * K + c * 8;
        soB[j] = 16384 + r * 128 + ((uint32_t)(c ^ (r & 7)) << 4);
    }
    MmaCtx cx; mma_ctx_init(cx, lane, wm, wn);

    float acc[2][8][4];
#pragma unroll
    for (int i = 0; i < 2; i++)
#pragma unroll
        for (int j = 0; j < 8; j++)
#pragma unroll
            for (int q = 0; q < 4; q++) acc[i][j][q] = 0.f;

    const int nk = K >> 6;   // 32
#define GATE_LOAD(ITP, DST)                                                           \
    do {                                                                              \
        int itp_ = (ITP);                                                             \
        if (itp_ < nkh) {                                                             \
            cpasync16((DST) + soA[0], aCur[0] + itp_ * 64);                           \
            cpasync16((DST) + soA[1], aCur[1] + itp_ * 64);                           \
        } else {                                                                      \
            if (validA[0]) cpasync16((DST) + soA[0], aPrev[0] + (itp_ - nkh) * 64);   \
            else sts_zero16((DST) + soA[0]);                                          \
            if (validA[1]) cpasync16((DST) + soA[1], aPrev[1] + (itp_ - nkh) * 64);   \
            else sts_zero16((DST) + soA[1]);                                          \
        }                                                                             \
        cpasync16((DST) + soB[0], bgp[0] + itp_ * 64);                                \
        cpasync16((DST) + soB[1], bgp[1] + itp_ * 64);                                \
        cpasync16((DST) + soB[2], bgp[2] + itp_ * 64);                                \
        cpasync16((DST) + soB[3], bgp[3] + itp_ * 64);                                \
        cp_commit();                                                                  \
    } while (0)

    GATE_LOAD(0, sbase);
    GATE_LOAD(1, sbase + STG);

    for (int it = 0; it < nk; it++) {
        if (it < nk - 1) cp_wait<1>(); else cp_wait<0>();
        __syncthreads();
        if (it + 2 < nk) {
            const uint32_t dst = sbase + (uint32_t)((it + 2) % 3) * STG;
            GATE_LOAD(it + 2, dst);
        }
        mma_tile(cx, sbase + (uint32_t)(it % 3) * STG, acc);
    }
#undef GATE_LOAD

    const int r0 = brow * 128 + wm * 32 + (lane >> 2);
    const int c0 = bcol * 256 + wn * 64 + (lane & 3) * 2;
#pragma unroll
    for (int mi = 0; mi < 2; mi++) {
#pragma unroll
        for (int nj = 0; nj < 8; nj++) {
            const int col = c0 + nj * 8;
            const float bv0 = bias[col], bv1 = bias[col + 1];
#pragma unroll
            for (int h = 0; h < 2; h++) {
                const int row = r0 + mi * 16 + h * 8;
                const size_t base = (size_t)row * DD + col;
                float v0 = acc[mi][nj][2 * h]     + bv0;
                float v1 = acc[mi][nj][2 * h + 1] + bv1;
                v0 = 0.5f * v0 * (1.f + erff(v0 * 0.70710678118654752f));
                v1 = 0.5f * v1 * (1.f + erff(v1 * 0.70710678118654752f));
                *reinterpret_cast<__half2*>(C + base) = __floats2half2_rn(v0, v1);
            }
        }
    }
}

// ---------------- conversion kernels ----------------
__global__ void k_cvtA2(const float* __restrict__ in, __half* __restrict__ out)
{
    size_t t = (size_t)blockIdx.x * 256 + threadIdx.x;
    float4 v = reinterpret_cast<const float4*>(in)[t];
    __align__(8) __half o[4];
    o[0] = __float2half(v.x); o[1] = __float2half(v.y);
    o[2] = __float2half(v.z); o[3] = __float2half(v.w);
    reinterpret_cast<uint2*>(out)[t] = *reinterpret_cast<const uint2*>(o);
}

__global__ void k_cvtB2(const float* __restrict__ W, __half* __restrict__ out, int K, int N)
{
    __shared__ float ts[32][33];
    const int k0 = blockIdx.y * 32, n0 = blockIdx.x * 32;
    const int tx = threadIdx.x, ty = threadIdx.y;
#pragma unroll
    for (int i = 0; i < 4; i++)
        ts[ty + i * 8][tx] = W[(size_t)(k0 + ty + i * 8) * N + n0 + tx];
    __syncthreads();
#pragma unroll
    for (int i = 0; i < 4; i++) {
        int n = ty + i * 8;
        out[(size_t)(n0 + n) * K + k0 + tx] = __float2half(ts[tx][n]);
    }
}

__global__ void k_cvtB2x3(const float* __restrict__ W0, const float* __restrict__ W1,
                          const float* __restrict__ W2, __half* __restrict__ out)
{
    __shared__ float ts[32][33];
    const float* W = (blockIdx.z == 0) ? W0 : (blockIdx.z == 1) ? W1 : W2;
    __half* o = out + (size_t)blockIdx.z * DD * DD;
    const int k0 = blockIdx.y * 32, n0 = blockIdx.x * 32;
    const int tx = threadIdx.x, ty = threadIdx.y;
#pragma unroll
    for (int i = 0; i < 4; i++)
        ts[ty + i * 8][tx] = W[(size_t)(k0 + ty + i * 8) * DD + n0 + tx];
    __syncthreads();
#pragma unroll
    for (int i = 0; i < 4; i++) {
        int n = ty + i * 8;
        o[(size_t)(n0 + n) * DD + k0 + tx] = __float2half(ts[tx][n]);
    }
}

// ---------------- fused value_gates + blend weights ----------------
__global__ void k_vgbw(const float* __restrict__ Wg2, const float* __restrict__ bg2,
                       const float* __restrict__ Wb2, const float* __restrict__ bb2)
{
    const int warp = threadIdx.x >> 5, lane = threadIdx.x & 31;
    const int bx = blockIdx.x;
    if (bx < MM / 8) {
        const int row = bx * 8 + warp;
        const uint4* g = reinterpret_cast<const uint4*>(g_gh + (size_t)row * DD);
        const float4* w = reinterpret_cast<const float4*>(Wg2);
        float s = 0.f;
#pragma unroll
        for (int i = 0; i < 4; i++) {
            int idx = lane + i * 32;
            uint4 hv = g[idx];
            const __half2* hp = reinterpret_cast<const __half2*>(&hv);
            float4 w0 = w[2 * idx], w1 = w[2 * idx + 1];
            float2 a0 = __half22float2(hp[0]);
            float2 a1 = __half22float2(hp[1]);
            float2 a2 = __half22float2(hp[2]);
            float2 a3 = __half22float2(hp[3]);
            s += a0.x * w0.x + a0.y * w0.y + a1.x * w0.z + a1.y * w0.w;
            s += a2.x * w1.x + a2.y * w1.y + a3.x * w1.z + a3.y * w1.w;
        }
#pragma unroll
        for (int o = 16; o > 0; o >>= 1) s += __shfl_xor_sync(0xFFFFFFFFu, s, o);
        if (lane == 0) g_vg[row] = 1.f / (1.f + expf(-(s + bg2[0])));
    } else {
        const int row = (bx - MM / 8) * 8 + warp;
        const uint4* hv4 = reinterpret_cast<const uint4*>(g_bh + (size_t)row * (DD / 2));
        const float4* wv = reinterpret_cast<const float4*>(Wb2);
        float s0 = 0.f, s1 = 0.f;
#pragma unroll
        for (int i = 0; i < 2; i++) {
            int idx = lane + i * 32;
            uint4 hv = hv4[idx];
            const __half2* hp = reinterpret_cast<const __half2*>(&hv);
#pragma unroll
            for (int j = 0; j < 4; j++) {
                float2 a = __half22float2(hp[j]);
                float4 wA = wv[4 * idx + j];
                s0 += a.x * wA.x + a.y * wA.z;
                s1 += a.x * wA.y + a.y * wA.w;
            }
        }
#pragma unroll
        for (int o = 16; o > 0; o >>= 1) {
            s0 += __shfl_xor_sync(0xFFFFFFFFu, s0, o);
            s1 += __shfl_xor_sync(0xFFFFFFFFu, s1, o);
        }
        if (lane == 0) {
            float a0 = s0 + bb2[0], a1 = s1 + bb2[1];
            float m = fmaxf(a0, a1);
            float e0 = expf(a0 - m), e1 = expf(a1 - m);
            float inv = 1.f / (e0 + e1);
            g_bw[2 * row]     = e0 * inv;
            g_bw[2 * row + 1] = e1 * inv;
        }
    }
}

// ---------------- per-batch gate scan (shuffle-based) ----------------
__global__ void k_gatescan()
{
    const int b = blockIdx.x;
    const int tid = threadIdx.x, lane = tid & 31, warp = tid >> 5;
    __shared__ float shw[33];
    float carry = 0.f;
    for (int t0 = 0; t0 < LL; t0 += 1024) {
        float v = g_vg[b * LL + t0 + tid];
        float sc = v;
#pragma unroll
        for (int o = 1; o < 32; o <<= 1) {
            float t = __shfl_up_sync(0xFFFFFFFFu, sc, o);
            if (lane >= o) sc += t;
        }
        if (lane == 31) shw[warp] = sc;
        __syncthreads();
        if (warp == 0) {
            float w = shw[lane];
            float ws = w;
#pragma unroll
            for (int o = 1; o < 32; o <<= 1) {
                float t = __shfl_up_sync(0xFFFFFFFFu, ws, o);
                if (lane >= o) ws += t;
            }
            shw[lane] = ws - w;
            if (lane == 31) shw[32] = ws;
        }
        __syncthreads();
        float inc = sc + shw[warp] + carry;
        g_gcs[b * LL + t0 + tid] = sqrtf(fmaxf(inc, 1.f));
        carry += shw[32];
        __syncthreads();
    }
}

// ---------------- scan pass T: vectorized (2 d per thread) ----------------
__global__ void k_scanT(const float* __restrict__ pp)
{
    const int d2 = blockIdx.x * 256 + threadIdx.x;   // half2 index, 0..511
    const int d = d2 * 2;
    const int c = blockIdx.y, b = blockIdx.z;
    const int l0 = c * TCHUNK;
    float2 spc = {0.f, 0.f}, sps = {0.f, 0.f}, skc = {0.f, 0.f}, sks = {0.f, 0.f};
    float2 kcp, ksp;
    if (l0 == 0) { kcp = make_float2(0.f, 0.f); ksp = make_float2(0.f, 0.f); }
    else {
        uint2 kk = *reinterpret_cast<const uint2*>(g_kcs + (size_t)(b * LL + l0 - 1) * DD + d);
        float2 k0 = __half22float2(*reinterpret_cast<__half2*>(&kk.x));
        float2 k1 = __half22float2(*reinterpret_cast<__half2*>(&kk.y));
        kcp = make_float2(k0.x, k1.x); ksp = make_float2(k0.y, k1.y);
    }
    for (int t = 0; t < TCHUNK; t++) {
        const int l = l0 + t;
        const int rowi = b * LL + l;
        const size_t idx = (size_t)rowi * DD + d;
        float2 ph = *reinterpret_cast<const float2*>(pp + (size_t)l * DD + d);
        float sn0, cs0, sn1, cs1;
        __sincosf(ph.x, &sn0, &cs0);
        __sincosf(ph.y, &sn1, &cs1);
        float2 pv = __half22float2(*reinterpret_cast<const __half2*>(g_pvh + idx));
        spc.x = fmaf(cs0, pv.x, spc.x); spc.y = fmaf(cs1, pv.y, spc.y);
        sps.x = fmaf(sn0, pv.x, sps.x); sps.y = fmaf(sn1, pv.y, sps.y);
        const float vgv = g_vg[rowi];
        float2 kv = __half22float2(*reinterpret_cast<const __half2*>(g_kvh + idx));
        kv.x *= vgv; kv.y *= vgv;
        skc.x = fmaf(kcp.x, kv.x, skc.x); skc.y = fmaf(kcp.y, kv.y, skc.y);
        sks.x = fmaf(ksp.x, kv.x, sks.x); sks.y = fmaf(ksp.y, kv.y, sks.y);
        uint2 kk = *reinterpret_cast<const uint2*>(g_kcs + idx);
        float2 k0 = __half22float2(*reinterpret_cast<__half2*>(&kk.x));
        float2 k1 = __half22float2(*reinterpret_cast<__half2*>(&kk.y));
        kcp = make_float2(k0.x, k1.x); ksp = make_float2(k0.y, k1.y);
    }
    const size_t tix = (size_t)(b * NCHUNK + c) * DD + d;
    *reinterpret_cast<float2*>(g_tot + tix)            = spc;
    *reinterpret_cast<float2*>(g_tot + TOTN + tix)     = sps;
    *reinterpret_cast<float2*>(g_tot + 2 * TOTN + tix) = skc;
    *reinterpret_cast<float2*>(g_tot + 3 * TOTN + tix) = sks;
}

// ---------------- chunk-total exclusive prefix (in place) ----------------
__global__ void k_totscan()
{
    const int d = blockIdx.x * 256 + threadIdx.x;
    const int b = blockIdx.y;
    float r0 = 0.f, r1 = 0.f, r2 = 0.f, r3 = 0.f;
    for (int c = 0; c < NCHUNK; c++) {
        size_t tix = (size_t)(b * NCHUNK + c) * DD + d;
        float v0 = g_tot[tix];
        float v1 = g_tot[TOTN + tix];
        float v2 = g_tot[2 * TOTN + tix];
        float v3 = g_tot[3 * TOTN + tix];
        g_tot[tix]            = r0;
        g_tot[TOTN + tix]     = r1;
        g_tot[2 * TOTN + tix] = r2;
        g_tot[3 * TOTN + tix] = r3;
        r0 += v0; r1 += v1; r2 += v2; r3 += v3;
    }
}

// ---------------- scan pass C: vectorized, direct offsets, fp16 blend out ----------------
__global__ void k_scanC(const float* __restrict__ pp)
{
    const int d2 = blockIdx.x * 256 + threadIdx.x;
    const int d = d2 * 2;
    const int c = blockIdx.y, b = blockIdx.z;
    const int l0 = c * TCHUNK;
    const size_t otix = (size_t)(b * NCHUNK + c) * DD + d;
    const float2 opc = *reinterpret_cast<const float2*>(g_tot + otix);
    const float2 ops = *reinterpret_cast<const float2*>(g_tot + TOTN + otix);
    const float2 okc = *reinterpret_cast<const float2*>(g_tot + 2 * TOTN + otix);
    const float2 oks = *reinterpret_cast<const float2*>(g_tot + 3 * TOTN + otix);
    const float invSqrtD = 0.03125f;
    float2 spc = {0.f, 0.f}, sps = {0.f, 0.f}, skc = {0.f, 0.f}, sks = {0.f, 0.f};
    float2 kcp, ksp;
    if (l0 == 0) { kcp = make_float2(0.f, 0.f); ksp = make_float2(0.f, 0.f); }
    else {
        uint2 kk = *reinterpret_cast<const uint2*>(g_kcs + (size_t)(b * LL + l0 - 1) * DD + d);
        float2 k0 = __half22float2(*reinterpret_cast<__half2*>(&kk.x));
        float2 k1 = __half22float2(*reinterpret_cast<__half2*>(&kk.y));
        kcp = make_float2(k0.x, k1.x); ksp = make_float2(k0.y, k1.y);
    }
    for (int t = 0; t < TCHUNK; t++) {
        const int l = l0 + t;
        const int rowi = b * LL + l;
        const size_t idx = (size_t)rowi * DD + d;
        float2 ph = *reinterpret_cast<const float2*>(pp + (size_t)l * DD + d);
        float sn0, cs0, sn1, cs1;
        __sincosf(ph.x, &sn0, &cs0);
        __sincosf(ph.y, &sn1, &cs1);
        float2 pv = __half22float2(*reinterpret_cast<const __half2*>(g_pvh + idx));
        spc.x = fmaf(cs0, pv.x, spc.x); spc.y = fmaf(cs1, pv.y, spc.y);
        sps.x = fmaf(sn0, pv.x, sps.x); sps.y = fmaf(sn1, pv.y, sps.y);
        const float vgv = g_vg[rowi];
        float2 kv = __half22float2(*reinterpret_cast<const __half2*>(g_kvh + idx));
        kv.x *= vgv; kv.y *= vgv;
        uint2 kk = *reinterpret_cast<const uint2*>(g_kcs + idx);
        float2 k0 = __half22float2(*reinterpret_cast<__half2*>(&kk.x));
        float2 k1 = __half22float2(*reinterpret_cast<__half2*>(&kk.y));
        skc.x = fmaf(kcp.x, kv.x, skc.x); skc.y = fmaf(kcp.y, kv.y, skc.y);
        sks.x = fmaf(ksp.x, kv.x, sks.x); sks.y = fmaf(ksp.y, kv.y, sks.y);
        kcp = make_float2(k0.x, k1.x); ksp = make_float2(k0.y, k1.y);
        const float rg = 1.f / g_gcs[rowi];
        const float bw0 = g_bw[2 * rowi], bw1 = g_bw[2 * rowi + 1];
        float pr0 = (cs0 * (spc.x + opc.x) + sn0 * (sps.x + ops.x)) * invSqrtD;
        float pr1 = (cs1 * (spc.y + opc.y) + sn1 * (sps.y + ops.y)) * invSqrtD;
        float kr0 = (k0.x * (skc.x + okc.x) + k0.y * (sks.x + oks.x)) * rg * invSqrtD;
        float kr1 = (k1.x * (skc.y + okc.y) + k1.y * (sks.y + oks.y)) * rg * invSqrtD;
        *reinterpret_cast<__half2*>(g_blendh + idx) =
            __floats2half2_rn(bw0 * pr0 + bw1 * kr0, bw0 * pr1 + bw1 * kr1);
    }
}

// ---------------- LayerNorm fused with fp16 cast output (vectorized) ----------------
__global__ void k_ln(const float* __restrict__ lng, const float* __restrict__ lnb,
                     __half* __restrict__ out2)
{
    int row = blockIdx.x, tid = threadIdx.x;
    const __half2* bl = reinterpret_cast<const __half2*>(g_blendh + (size_t)row * DD);
    float2 v[2];
    float s = 0.f, sq = 0.f;
#pragma unroll
    for (int i = 0; i < 2; i++) {
        v[i] = __half22float2(bl[tid + i * 256]);
        s += v[i].x + v[i].y;
        sq += v[i].x * v[i].x + v[i].y * v[i].y;
    }
    __shared__ float shs[256], shq[256];
    shs[tid] = s; shq[tid] = sq; __syncthreads();
    for (int o = 128; o > 0; o >>= 1) {
        if (tid < o) { shs[tid] += shs[tid + o]; shq[tid] += shq[tid + o]; }
        __syncthreads();
    }
    __shared__ float smu, srstd;
    if (tid == 0) {
        float mu  = shs[0] * (1.f / DD);
        float var = shq[0] * (1.f / DD) - mu * mu;
        smu = mu;
        srstd = rsqrtf(var + 1e-5f);
    }
    __syncthreads();
    __half2* o2 = reinterpret_cast<__half2*>(out2 + (size_t)row * DD);
#pragma unroll
    for (int i = 0; i < 2; i++) {
        int dd = 2 * (tid + i * 256);
        float2 gg = *reinterpret_cast<const float2*>(lng + dd);
        float2 bb = *reinterpret_cast<const float2*>(lnb + dd);
        float t0 = (v[i].x - smu) * srstd * gg.x + bb.x;
        float t1 = (v[i].y - smu) * srstd * gg.y + bb.y;
        o2[tid + i * 256] = __floats2half2_rn(t0, t1);
    }
}

// ---------------- launch ----------------
extern "C" void kernel_launch(void* const* d_in, const int* in_sizes, int n_in,
                              void* d_out, int out_size)
{
    const float* x   = (const float*)d_in[0];
    const float* pp  = (const float*)d_in[1];
    const float* Wpv = (const float*)d_in[2];
    const float* bpv = (const float*)d_in[3];
    const float* Wk  = (const float*)d_in[4];
    const float* bk  = (const float*)d_in[5];
    const float* Wkv = (const float*)d_in[6];
    const float* bkv = (const float*)d_in[7];
    const float* Wg1 = (const float*)d_in[8];
    const float* bg1 = (const float*)d_in[9];
    const float* Wg2 = (const float*)d_in[10];
    const float* bg2 = (const float*)d_in[11];
    const float* Wb1 = (const float*)d_in[12];
    const float* bb1 = (const float*)d_in[13];
    const float* Wb2 = (const float*)d_in[14];
    const float* bb2 = (const float*)d_in[15];
    const float* lng = (const float*)d_in[16];
    const float* lnb = (const float*)d_in[17];
    const float* Wo  = (const float*)d_in[18];
    const float* bo  = (const float*)d_in[19];
    float* out = (float*)d_out;

    __half *pvh, *kvh, *gh, *bh, *x2, *ln2, *Wqkv2, *Wg12, *Wb12, *Wo2;
    __half2* kcs;
    cudaGetSymbolAddress((void**)&pvh,   g_pvh);
    cudaGetSymbolAddress((void**)&kvh,   g_kvh);
    cudaGetSymbolAddress((void**)&kcs,   g_kcs);
    cudaGetSymbolAddress((void**)&gh,    g_gh);
    cudaGetSymbolAddress((void**)&bh,    g_bh);
    cudaGetSymbolAddress((void**)&x2,    g_x2);
    cudaGetSymbolAddress((void**)&ln2,   g_ln2);
    cudaGetSymbolAddress((void**)&Wqkv2, g_Wqkv2);
    cudaGetSymbolAddress((void**)&Wg12,  g_Wg12);
    cudaGetSymbolAddress((void**)&Wb12,  g_Wb12);
    cudaGetSymbolAddress((void**)&Wo2,   g_Wo2);

    cudaFuncSetAttribute((const void*)gemm_qkv,          cudaFuncAttributeMaxDynamicSharedMemorySize, GEMM_SMEM);
    cudaFuncSetAttribute((const void*)gemm_mma<EP_GELU>, cudaFuncAttributeMaxDynamicSharedMemorySize, GEMM_SMEM);
    cudaFuncSetAttribute((const void*)gemm_mma<EP_OUT >, cudaFuncAttributeMaxDynamicSharedMemorySize, GEMM_SMEM);
    cudaFuncSetAttribute((const void*)gemm_gate,         cudaFuncAttributeMaxDynamicSharedMemorySize, GEMM_SMEM);

    // 0-1: conversions
    k_cvtA2<<<(MM * DD / 4) / 256, 256>>>(x, x2);
    k_cvtB2x3<<<dim3(DD / 32, DD / 32, 3), dim3(32, 8)>>>(Wpv, Wk, Wkv, Wqkv2);
    // 2: merged QKV GEMM (fp16 in/out, N=3072)
    gemm_qkv<<<dim3(12, MM / 128), 512, GEMM_SMEM>>>(
        (const uint16_t*)x2, (const uint16_t*)Wqkv2, bpv, bk, bkv, pvh, kcs, kvh);
    // 3-4: gate path
    k_cvtB2<<<dim3(DD / 32, 2 * DD / 32), dim3(32, 8)>>>(Wg1, Wg12, 2 * DD, DD);
    gemm_gate<<<dim3(4, MM / 128), 512, GEMM_SMEM>>>((const uint16_t*)x2, (const uint16_t*)Wg12, bg1, gh);
    // 5-6: blend hidden
    k_cvtB2<<<dim3((DD / 2) / 32, DD / 32), dim3(32, 8)>>>(Wb1, Wb12, DD, DD / 2);
    gemm_mma<EP_GELU><<<dim3(2, MM / 128), 512, GEMM_SMEM>>>(
        (const uint16_t*)x2, (const uint16_t*)Wb12, bb1, bh, nullptr, DD / 2, DD);
    // 7-8: fused gates+blend softmax, gate cumsum
    k_vgbw<<<2 * (MM / 8), 256>>>(Wg2, bg2, Wb2, bb2);
    k_gatescan<<<BBATCH, 1024>>>();
    // 9-11: scans (vectorized half2, NCHUNK=128)
    dim3 gscan(DD / 512, NCHUNK, BBATCH);
    k_scanT<<<gscan, 256>>>(pp);
    k_totscan<<<dim3(DD / 256, BBATCH), 256>>>();
    k_scanC<<<gscan, 256>>>(pp);
    // 12: LayerNorm (vectorized fp16)
    k_ln<<<MM, 256>>>(lng, lnb, ln2);
    // 13-14: output path (+residual)
    k_cvtB2<<<dim3(DD / 32, DD / 32), dim3(32, 8)>>>(Wo, Wo2, DD, DD);
    gemm_mma<EP_OUT><<<dim3(4, MM / 128), 512, GEMM_SMEM>>>(
        (const uint16_t*)ln2, (const uint16_t*)Wo2, bo, out, x, DD, DD);
}